// round 10
// baseline (speedup 1.0000x reference)
#include <cuda_runtime.h>
#include <cuda_fp16.h>
#include <math.h>
#include <stdint.h>

#define Lt 256
#define Li 2048
#define LL 2304          // Lt + Li
#define DD 2048
#define HH 16
#define HD 128
#define MLPD 8192
#define EPSF 1e-6f

// ================= helpers =================
__device__ __forceinline__ uint32_t smem_to_u32(const void* p) {
    uint32_t a;
    asm("{ .reg .u64 t; cvta.to.shared.u64 t, %1; cvt.u32.u64 %0, t; }" : "=r"(a) : "l"(p));
    return a;
}
__device__ __forceinline__ void cpa16(uint32_t dst, const void* src) {
    asm volatile("cp.async.cg.shared.global [%0], [%1], 16;" :: "r"(dst), "l"(src));
}
#define CP_COMMIT() asm volatile("cp.async.commit_group;" ::: "memory")
#define CP_WAIT(N)  asm volatile("cp.async.wait_group %0;" :: "n"(N) : "memory")

__device__ __forceinline__ void ldsm_x4(uint32_t addr, uint32_t* r) {
    asm volatile("ldmatrix.sync.aligned.m8n8.x4.shared.b16 {%0,%1,%2,%3}, [%4];"
                 : "=r"(r[0]), "=r"(r[1]), "=r"(r[2]), "=r"(r[3]) : "r"(addr));
}
__device__ __forceinline__ void ldsm_x2(uint32_t addr, uint32_t* r) {
    asm volatile("ldmatrix.sync.aligned.m8n8.x2.shared.b16 {%0,%1}, [%2];"
                 : "=r"(r[0]), "=r"(r[1]) : "r"(addr));
}
__device__ __forceinline__ void mma_fp16(float* d, const uint32_t* a, const uint32_t* b) {
    asm volatile(
        "mma.sync.aligned.m16n8k16.row.col.f32.f16.f16.f32 "
        "{%0,%1,%2,%3}, {%4,%5,%6,%7}, {%8,%9}, {%0,%1,%2,%3};"
        : "+f"(d[0]), "+f"(d[1]), "+f"(d[2]), "+f"(d[3])
        : "r"(a[0]), "r"(a[1]), "r"(a[2]), "r"(a[3]), "r"(b[0]), "r"(b[1]));
}

__device__ __forceinline__ void split2(float x, __half& h, __half& l) {
    h = __float2half_rn(x);
    l = __float2half_rn(x - __half2float(h));
}
__device__ __forceinline__ float gelu_tanh(float x) {
    float x3 = x * x * x;
    return 0.5f * x * (1.0f + tanhf(0.7978845608028654f * (x + 0.044715f * x3)));
}

// ================= scratch (static device globals) =================
__device__ __align__(16) float g_sv[DD];
__device__ __align__(16) float g_mod_img[6 * DD];
__device__ __align__(16) float g_mod_txt[6 * DD];
__device__ __align__(16) __half g_mxi_h[Li * DD];
__device__ __align__(16) __half g_mxi_l[Li * DD];
__device__ __align__(16) __half g_mxt_h[Lt * DD];
__device__ __align__(16) __half g_mxt_l[Lt * DD];
__device__ __align__(16) __half g_wt_h[MLPD * DD];   // transposed rounded weight
__device__ __align__(16) float g_qkv_img[Li * 3 * DD];
__device__ __align__(16) float g_qkv_txt[Lt * 3 * DD];
__device__ __align__(16) __half g_qh[HH * LL * HD];
__device__ __align__(16) __half g_ql[HH * LL * HD];
__device__ __align__(16) __half g_kh[HH * LL * HD];
__device__ __align__(16) __half g_vth[HH * HD * LL]; // V transposed per head [H, HD, LL]
__device__ __align__(16) __half g_vtl[HH * HD * LL];
__device__ __align__(16) __half g_aoh[LL * DD];
__device__ __align__(16) __half g_aol[LL * DD];
__device__ __align__(16) float g_res_i[Li * DD];
__device__ __align__(16) float g_res_t[Lt * DD];
__device__ __align__(16) __half g_hh[Li * DD];
__device__ __align__(16) __half g_hl[Li * DD];
__device__ __align__(16) __half g_mh[(size_t)Li * MLPD];
__device__ __align__(16) __half g_ml[(size_t)Li * MLPD];

// ================= small kernels =================
__global__ void silu_k(const float* __restrict__ vec, float* __restrict__ sv) {
    int i = blockIdx.x * blockDim.x + threadIdx.x;
    if (i < DD) { float x = vec[i]; sv[i] = x / (1.0f + __expf(-x)); }
}

__global__ void modmul_k(const float* __restrict__ sv, const float* __restrict__ W,
                         const float* __restrict__ b, float* __restrict__ out) {
    __shared__ float s[DD];
    for (int i = threadIdx.x; i < DD; i += 128) s[i] = sv[i];
    __syncthreads();
    int j = blockIdx.x * 128 + threadIdx.x;
    float acc = 0.0f;
    const float* wp = W + j;
    for (int d = 0; d < DD; d++) acc += s[d] * wp[(size_t)d * (6 * DD)];
    out[j] = acc + b[j];
}

// y_hi/y_lo = split((1+sc)*LN(x) + sh)
__global__ void ln_mod_split_k(const float* __restrict__ x,
                               __half* __restrict__ yh, __half* __restrict__ yl,
                               const float* __restrict__ sh, const float* __restrict__ sc) {
    int row = blockIdx.x;
    const float* px = x + (size_t)row * DD;
    __shared__ float red[256];
    int tid = threadIdx.x;
    float v[8];
    float s = 0.0f;
#pragma unroll
    for (int i = 0; i < 8; i++) { v[i] = px[tid + i * 256]; s += v[i]; }
    red[tid] = s; __syncthreads();
    for (int o = 128; o > 0; o >>= 1) { if (tid < o) red[tid] += red[tid + o]; __syncthreads(); }
    float mu = red[0] * (1.0f / DD);
    __syncthreads();
    float ss = 0.0f;
#pragma unroll
    for (int i = 0; i < 8; i++) { float d = v[i] - mu; ss += d * d; }
    red[tid] = ss; __syncthreads();
    for (int o = 128; o > 0; o >>= 1) { if (tid < o) red[tid] += red[tid + o]; __syncthreads(); }
    float r = rsqrtf(red[0] * (1.0f / DD) + EPSF);
#pragma unroll
    for (int i = 0; i < 8; i++) {
        int c = tid + i * 256;
        float y = (1.0f + sc[c]) * ((v[i] - mu) * r) + sh[c];
        __half h, l; split2(y, h, l);
        yh[(size_t)row * DD + c] = h;
        yl[(size_t)row * DD + c] = l;
    }
}

// transpose + round: W[K,N] fp32 -> Wt [N,K] fp16
__global__ void wconv_k(const float* __restrict__ W,
                        __half* __restrict__ Wh, int Kd, int Nd) {
    __shared__ float t[32][33];
    int n = blockIdx.x * 32 + threadIdx.x;
#pragma unroll
    for (int i = 0; i < 4; i++) {
        int k = blockIdx.y * 32 + threadIdx.y + i * 8;
        t[threadIdx.y + i * 8][threadIdx.x] = W[(size_t)k * Nd + n];
    }
    __syncthreads();
    int k2 = blockIdx.y * 32 + threadIdx.x;
#pragma unroll
    for (int i = 0; i < 4; i++) {
        int n2 = blockIdx.x * 32 + threadIdx.y + i * 8;
        Wh[(size_t)n2 * Kd + k2] = __float2half_rn(t[threadIdx.x][threadIdx.y + i * 8]);
    }
}

// split qkv, rmsnorm(q,k)*scale, rope(q,k); q split hi/lo, k rounded, v split (transposed)
__global__ void qkv_prep_k(const float* __restrict__ qkv_txt, const float* __restrict__ qkv_img,
                           const float* __restrict__ tq_s, const float* __restrict__ tk_s,
                           const float* __restrict__ iq_s, const float* __restrict__ ik_s,
                           const float* __restrict__ pe,
                           __half* __restrict__ qh, __half* __restrict__ ql,
                           __half* __restrict__ kh,
                           __half* __restrict__ vth, __half* __restrict__ vtl) {
    int h = blockIdx.x;
    int pos = blockIdx.y;
    int d = threadIdx.x;
    const float* src; int l; const float* qs; const float* ks;
    if (pos < Lt) { src = qkv_txt; l = pos;      qs = tq_s; ks = tk_s; }
    else          { src = qkv_img; l = pos - Lt; qs = iq_s; ks = ik_s; }
    const float* base = src + (size_t)l * (3 * DD) + h * HD;
    float qv = base[d];
    float kv = base[DD + d];
    float vv = base[2 * DD + d];

    __shared__ float sq[HD], sk[HD], red[8];
    float q2 = qv * qv, k2 = kv * kv;
#pragma unroll
    for (int o = 16; o > 0; o >>= 1) {
        q2 += __shfl_xor_sync(0xFFFFFFFFu, q2, o);
        k2 += __shfl_xor_sync(0xFFFFFFFFu, k2, o);
    }
    int w = d >> 5;
    if ((d & 31) == 0) { red[w] = q2; red[4 + w] = k2; }
    __syncthreads();
    float qss = red[0] + red[1] + red[2] + red[3];
    float kss = red[4] + red[5] + red[6] + red[7];
    float qn = qv * rsqrtf(qss * (1.0f / HD) + EPSF) * qs[d];
    float kn = kv * rsqrtf(kss * (1.0f / HD) + EPSF) * ks[d];
    sq[d] = qn; sk[d] = kn;
    __syncthreads();
    int i = d >> 1, j = d & 1;
    const float* pp = pe + (((size_t)pos * 64 + i) * 4 + j * 2);
    float p0 = pp[0], p1 = pp[1];
    float rq = p0 * sq[2 * i] + p1 * sq[2 * i + 1];
    float rk = p0 * sk[2 * i] + p1 * sk[2 * i + 1];
    size_t o = ((size_t)h * LL + pos) * HD + d;
    __half a, b;
    split2(rq, a, b); qh[o] = a; ql[o] = b;
    kh[o] = __float2half_rn(rk);
    size_t ov = ((size_t)h * HD + d) * LL + pos;
    split2(vv, a, b); vth[ov] = a; vtl[ov] = b;
}

// ================= fused flash attention =================
// Per CTA: one head, 128 Q rows. KV chunks of 64, double-buffered cp.async.
// S = (qh+ql)·kh (2 mma), P rounded fp16, O += pH·(vh+vl) (2 mma).
// MMA streams are issued as independent passes (hi pass, lo pass) so dependent
// accumulator reuse distance >= 8 — hides HMMA latency.
#define FCHUNK 64
#define NCHUNK (LL / FCHUNK)       // 36
#define F_QROW 272                 // 128 cols fp16 + 16B pad
#define F_QSZ  (128 * F_QROW)      // 34816 per array
#define F_KROW 272
#define F_KSZ  (64 * F_KROW)       // 17408
#define F_VROW 144                 // 64 cols fp16 + 16B pad
#define F_VSZ  (128 * F_VROW)      // 18432 per array
#define F_STG0 (2 * F_QSZ)         // 69632
#define F_STGSZ (F_KSZ + 2 * F_VSZ)      // 54272
#define FLASH_SMEM (F_STG0 + 2 * F_STGSZ) // 178176

__global__ __launch_bounds__(256, 1) void flash_k(
    const __half* __restrict__ qhg, const __half* __restrict__ qlg,
    const __half* __restrict__ khg,
    const __half* __restrict__ vthg, const __half* __restrict__ vtlg,
    __half* __restrict__ aoh, __half* __restrict__ aol) {
    extern __shared__ char smem[];
    uint32_t sb = smem_to_u32(smem);
    int tid = threadIdx.x, wid = tid >> 5, lane = tid & 31;
    int h = blockIdx.y, qt = blockIdx.x;
    const float iscale = 0.08838834764831845f; // 1/sqrt(128)

    // ---- load Q tile (once) ----
#pragma unroll
    for (int i = 0; i < 8; i++) {
        int u = tid + i * 256;          // 0..2047
        int row = u >> 4, cu = u & 15;
        size_t go = ((size_t)h * LL + qt * 128 + row) * HD + cu * 8;
        cpa16(sb + row * F_QROW + cu * 16, qhg + go);
        cpa16(sb + F_QSZ + row * F_QROW + cu * 16, qlg + go);
    }
    CP_COMMIT();

    // ---- prefetch chunk 0 ----
    {
        uint32_t st = sb + F_STG0;
#pragma unroll
        for (int i = 0; i < 4; i++) {
            int u = tid + i * 256;      // 0..1023
            int row = u >> 4, cu = u & 15;
            size_t go = ((size_t)h * LL + row) * HD + cu * 8;
            cpa16(st + row * F_KROW + cu * 16, khg + go);
            int vr = u >> 3, vc = u & 7;
            size_t gv = ((size_t)h * HD + vr) * LL + vc * 8;
            cpa16(st + F_KSZ + vr * F_VROW + vc * 16, vthg + gv);
            cpa16(st + F_KSZ + F_VSZ + vr * F_VROW + vc * 16, vtlg + gv);
        }
        CP_COMMIT();
    }

    float o[16][4];
#pragma unroll
    for (int i = 0; i < 16; i++)
#pragma unroll
        for (int f = 0; f < 4; f++) o[i][f] = 0.0f;
    float m0 = -1e30f, m1 = -1e30f, l0 = 0.0f, l1 = 0.0f;

    uint32_t qa_base = sb + (wid * 16 + (lane & 15)) * F_QROW + ((lane >> 4) * 16);

    for (int j = 0; j < NCHUNK; j++) {
        CP_WAIT(0);
        __syncthreads();
        if (j + 1 < NCHUNK) {
            int ln = (j + 1) * FCHUNK;
            uint32_t st = sb + F_STG0 + ((j + 1) & 1) * F_STGSZ;
#pragma unroll
            for (int i = 0; i < 4; i++) {
                int u = tid + i * 256;
                int row = u >> 4, cu = u & 15;
                size_t go = ((size_t)h * LL + ln + row) * HD + cu * 8;
                cpa16(st + row * F_KROW + cu * 16, khg + go);
                int vr = u >> 3, vc = u & 7;
                size_t gv = ((size_t)h * HD + vr) * LL + ln + vc * 8;
                cpa16(st + F_KSZ + vr * F_VROW + vc * 16, vthg + gv);
                cpa16(st + F_KSZ + F_VSZ + vr * F_VROW + vc * 16, vtlg + gv);
            }
            CP_COMMIT();
        }

        uint32_t st = sb + F_STG0 + (j & 1) * F_STGSZ;

        // ---- S = Q @ K^T (hi pass then lo pass; acc reuse distance 8) ----
        float S[8][4];
#pragma unroll
        for (int i = 0; i < 8; i++)
#pragma unroll
            for (int f = 0; f < 4; f++) S[i][f] = 0.0f;
#pragma unroll
        for (int kk = 0; kk < 8; kk++) {
            uint32_t aH[4], aL[4], bArr[8][2];
            uint32_t qa = qa_base + kk * 32;
            ldsm_x4(qa, aH);
            ldsm_x4(qa + F_QSZ, aL);
#pragma unroll
            for (int ni = 0; ni < 8; ni++) {
                uint32_t ka = st + (ni * 8 + (lane & 7)) * F_KROW + ((lane >> 3) & 1) * 16 + kk * 32;
                ldsm_x2(ka, bArr[ni]);
            }
#pragma unroll
            for (int ni = 0; ni < 8; ni++) mma_fp16(S[ni], aH, bArr[ni]);
#pragma unroll
            for (int ni = 0; ni < 8; ni++) mma_fp16(S[ni], aL, bArr[ni]);
        }

        // ---- online softmax ----
        float rm0 = -1e30f, rm1 = -1e30f;
#pragma unroll
        for (int ni = 0; ni < 8; ni++) {
            rm0 = fmaxf(rm0, fmaxf(S[ni][0], S[ni][1]));
            rm1 = fmaxf(rm1, fmaxf(S[ni][2], S[ni][3]));
        }
        rm0 = fmaxf(rm0, __shfl_xor_sync(0xFFFFFFFFu, rm0, 1));
        rm0 = fmaxf(rm0, __shfl_xor_sync(0xFFFFFFFFu, rm0, 2));
        rm1 = fmaxf(rm1, __shfl_xor_sync(0xFFFFFFFFu, rm1, 1));
        rm1 = fmaxf(rm1, __shfl_xor_sync(0xFFFFFFFFu, rm1, 2));
        float mn0 = fmaxf(m0, rm0), mn1 = fmaxf(m1, rm1);
        float f0 = __expf((m0 - mn0) * iscale);
        float f1 = __expf((m1 - mn1) * iscale);
        m0 = mn0; m1 = mn1;
        float rs0 = 0.0f, rs1 = 0.0f;
#pragma unroll
        for (int ni = 0; ni < 8; ni++) {
            S[ni][0] = __expf((S[ni][0] - mn0) * iscale);
            S[ni][1] = __expf((S[ni][1] - mn0) * iscale);
            S[ni][2] = __expf((S[ni][2] - mn1) * iscale);
            S[ni][3] = __expf((S[ni][3] - mn1) * iscale);
            rs0 += S[ni][0] + S[ni][1];
            rs1 += S[ni][2] + S[ni][3];
        }
        rs0 += __shfl_xor_sync(0xFFFFFFFFu, rs0, 1);
        rs0 += __shfl_xor_sync(0xFFFFFFFFu, rs0, 2);
        rs1 += __shfl_xor_sync(0xFFFFFFFFu, rs1, 1);
        rs1 += __shfl_xor_sync(0xFFFFFFFFu, rs1, 2);
        l0 = l0 * f0 + rs0;
        l1 = l1 * f1 + rs1;
#pragma unroll
        for (int ni = 0; ni < 16; ni++) {
            o[ni][0] *= f0; o[ni][1] *= f0;
            o[ni][2] *= f1; o[ni][3] *= f1;
        }

        // ---- O += P @ V (bH ni-sweep then bL ni-sweep; acc reuse distance 16) ----
#pragma unroll
        for (int kf = 0; kf < 4; kf++) {
            uint32_t pH[4];
            {
                float* c0 = S[2 * kf];
                float* c1 = S[2 * kf + 1];
                __half2 t;
                t = __floats2half2_rn(c0[0], c0[1]); pH[0] = *(uint32_t*)&t;
                t = __floats2half2_rn(c0[2], c0[3]); pH[1] = *(uint32_t*)&t;
                t = __floats2half2_rn(c1[0], c1[1]); pH[2] = *(uint32_t*)&t;
                t = __floats2half2_rn(c1[2], c1[3]); pH[3] = *(uint32_t*)&t;
            }
#pragma unroll
            for (int ni = 0; ni < 16; ni++) {
                uint32_t bH[2];
                uint32_t va = st + F_KSZ + (ni * 8 + (lane & 7)) * F_VROW +
                              ((lane >> 3) & 1) * 16 + kf * 32;
                ldsm_x2(va, bH);
                mma_fp16(o[ni], pH, bH);
            }
#pragma unroll
            for (int ni = 0; ni < 16; ni++) {
                uint32_t bL[2];
                uint32_t va = st + F_KSZ + F_VSZ + (ni * 8 + (lane & 7)) * F_VROW +
                              ((lane >> 3) & 1) * 16 + kf * 32;
                ldsm_x2(va, bL);
                mma_fp16(o[ni], pH, bL);
            }
        }
        __syncthreads();
    }

    // ---- normalize + write out split hi/lo ----
    float inv0 = 1.0f / l0, inv1 = 1.0f / l1;
    int row0 = qt * 128 + wid * 16 + (lane >> 2);
    int row1 = row0 + 8;
#pragma unroll
    for (int ni = 0; ni < 16; ni++) {
        int col = h * HD + ni * 8 + (lane & 3) * 2;
        float a0 = o[ni][0] * inv0, a1 = o[ni][1] * inv0;
        float b0 = o[ni][2] * inv1, b1 = o[ni][3] * inv1;
        __half2 h0 = __floats2half2_rn(a0, a1);
        __half2 l0v; { float x = a0 - __low2float(h0), y = a1 - __high2float(h0); l0v = __floats2half2_rn(x, y); }
        __half2 h1 = __floats2half2_rn(b0, b1);
        __half2 l1v; { float x = b0 - __low2float(h1), y = b1 - __high2float(h1); l1v = __floats2half2_rn(x, y); }
        *(__half2*)&aoh[(size_t)row0 * DD + col] = h0;
        *(__half2*)&aol[(size_t)row0 * DD + col] = l0v;
        *(__half2*)&aoh[(size_t)row1 * DD + col] = h1;
        *(__half2*)&aol[(size_t)row1 * DD + col] = l1v;
    }
}

// ================= HMMA (mma.sync fp16) GEMM =================
// C[M,N] = epi( (Ah+Al)[M,K] @ Bh[N,K]^T ), 2-product split (A exact, B rounded), fp32 accum.
// CTA tile 128x128, BK=32. 8 warps (2x4), warp tile 64x32.
// Hi-product pass over all 16 accumulators, then lo-product pass: acc reuse
// distance 16 MMAs — hides HMMA latency.
#define SROW 80
#define ARRB (128 * SROW)
#define STAGEB (3 * ARRB)
#define TGEMM_SMEM (2 * STAGEB)    // 61440

template <int EPI>
__global__ __launch_bounds__(256, 1) void tgemm(
    const __half* __restrict__ Ah, const __half* __restrict__ Al, long long sAz,
    const __half* __restrict__ Bh, long long sBz,
    float* __restrict__ C, long long sCz,
    __half* __restrict__ Chi, __half* __restrict__ Clo,
    int K, int lda, int ldb, int ldc, float alpha,
    const float* __restrict__ bias, const float* __restrict__ gate,
    const float* __restrict__ res, int ldres) {
    extern __shared__ char smem[];
    uint32_t sb = smem_to_u32(smem);
    int tid = threadIdx.x, wid = tid >> 5, lane = tid & 31;
    int warpM = wid >> 2, warpN = wid & 3;
    int m0 = blockIdx.y * 128, n0 = blockIdx.x * 128;
    int z = blockIdx.z;
    Ah += (size_t)z * sAz; Al += (size_t)z * sAz;
    Bh += (size_t)z * sBz;
    if (C)   C   += (size_t)z * sCz;
    if (Chi) { Chi += (size_t)z * sCz; Clo += (size_t)z * sCz; }

    const __half* g0 = Ah + (size_t)m0 * lda;
    const __half* g1 = Al + (size_t)m0 * lda;
    const __half* g2 = Bh + (size_t)n0 * ldb;

    int r0 = tid >> 2, q0 = tid & 3;
    int r1 = (tid + 256) >> 2, q1 = q0;
    uint32_t d00 = sb + r0 * SROW + q0 * 16;
    uint32_t d01 = sb + r1 * SROW + q1 * 16;

    float acc[4][4][4];
#pragma unroll
    for (int i = 0; i < 4; i++)
#pragma unroll
        for (int j = 0; j < 4; j++)
#pragma unroll
            for (int f = 0; f < 4; f++) acc[i][j][f] = 0.0f;

    int nit = K / 32;

    {
        cpa16(d00 + 0 * ARRB, g0 + (size_t)r0 * lda + q0 * 8);
        cpa16(d01 + 0 * ARRB, g0 + (size_t)r1 * lda + q1 * 8);
        cpa16(d00 + 1 * ARRB, g1 + (size_t)r0 * lda + q0 * 8);
        cpa16(d01 + 1 * ARRB, g1 + (size_t)r1 * lda + q1 * 8);
        cpa16(d00 + 2 * ARRB, g2 + (size_t)r0 * ldb + q0 * 8);
        cpa16(d01 + 2 * ARRB, g2 + (size_t)r1 * ldb + q1 * 8);
        CP_COMMIT();
    }

    uint32_t a_base = sb + (warpM * 64 + (lane & 15)) * SROW + ((lane >> 4) * 16);
    uint32_t b_base = sb + 2 * ARRB + (warpN * 32 + (lane & 7)) * SROW + (((lane >> 3) & 1) * 16);

    for (int it = 0; it < nit; it++) {
        bool pf = (it + 1) < nit;
        if (pf) {
            int k0 = (it + 1) * 32;
            uint32_t st = ((it + 1) & 1) * STAGEB;
            cpa16(d00 + st + 0 * ARRB, g0 + (size_t)r0 * lda + k0 + q0 * 8);
            cpa16(d01 + st + 0 * ARRB, g0 + (size_t)r1 * lda + k0 + q1 * 8);
            cpa16(d00 + st + 1 * ARRB, g1 + (size_t)r0 * lda + k0 + q0 * 8);
            cpa16(d01 + st + 1 * ARRB, g1 + (size_t)r1 * lda + k0 + q1 * 8);
            cpa16(d00 + st + 2 * ARRB, g2 + (size_t)r0 * ldb + k0 + q0 * 8);
            cpa16(d01 + st + 2 * ARRB, g2 + (size_t)r1 * ldb + k0 + q1 * 8);
            CP_COMMIT();
            CP_WAIT(1);
        } else {
            CP_WAIT(0);
        }
        __syncthreads();

        uint32_t st = (it & 1) * STAGEB;
        uint32_t ab = a_base + st;
        uint32_t bb = b_base + st;
#pragma unroll
        for (int kk = 0; kk < 2; kk++) {
            int kb = kk * 32;
            uint32_t ah[4][4], al[4][4], bh[4][2];
#pragma unroll
            for (int mi = 0; mi < 4; mi++) {
                ldsm_x4(ab + mi * (16 * SROW) + kb, ah[mi]);
                ldsm_x4(ab + ARRB + mi * (16 * SROW) + kb, al[mi]);
            }
#pragma unroll
            for (int ni = 0; ni < 4; ni++)
                ldsm_x2(bb + ni * (8 * SROW) + kb, bh[ni]);
#pragma unroll
            for (int ni = 0; ni < 4; ni++)
#pragma unroll
                for (int mi = 0; mi < 4; mi++)
                    mma_fp16(acc[mi][ni], ah[mi], bh[ni]);
#pragma unroll
            for (int ni = 0; ni < 4; ni++)
#pragma unroll
                for (int mi = 0; mi < 4; mi++)
                    mma_fp16(acc[mi][ni], al[mi], bh[ni]);
        }
        __syncthreads();
    }

    int rbase = m0 + warpM * 64 + (lane >> 2);
    int cbase = n0 + warpN * 32 + (lane & 3) * 2;
#pragma unroll
    for (int mi = 0; mi < 4; mi++) {
#pragma unroll
        for (int ni = 0; ni < 4; ni++) {
            int col = cbase + ni * 8;
#pragma unroll
            for (int hf = 0; hf < 2; hf++) {
                int row = rbase + mi * 16 + hf * 8;
                float v0 = acc[mi][ni][hf * 2 + 0];
                float v1 = acc[mi][ni][hf * 2 + 1];
                if (EPI == 0) {
                    float2 oo; oo.x = alpha * v0; oo.y = alpha * v1;
                    *(float2*)&C[(size_t)row * ldc + col] = oo;
                } else if (EPI == 2) {
                    float2 oo;
                    oo.x = res[(size_t)row * ldres + col + 0] + gate[col + 0] * (v0 + bias[col + 0]);
                    oo.y = res[(size_t)row * ldres + col + 1] + gate[col + 1] * (v1 + bias[col + 1]);
                    *(float2*)&C[(size_t)row * ldc + col] = oo;
                } else { // EPI 3
                    float gg0 = gelu_tanh(v0 + bias[col]);
                    float gg1 = gelu_tanh(v1 + bias[col + 1]);
                    __half2 hp = __floats2half2_rn(gg0, gg1);
                    float rr0 = gg0 - __low2float(hp), rr1 = gg1 - __high2float(hp);
                    __half2 lp = __floats2half2_rn(rr0, rr1);
                    *(__half2*)&Chi[(size_t)row * ldc + col] = hp;
                    *(__half2*)&Clo[(size_t)row * ldc + col] = lp;
                }
            }
        }
    }
}

// ================= host side =================
#define SYMF(p, s) do { void* _t = nullptr; cudaGetSymbolAddress(&_t, s); (p) = (float*)_t; } while (0)
#define SYMH(p, s) do { void* _t = nullptr; cudaGetSymbolAddress(&_t, s); (p) = (__half*)_t; } while (0)

extern "C" void kernel_launch(void* const* d_in, const int* in_sizes, int n_in,
                              void* d_out, int out_size) {
    const float* img     = (const float*)d_in[0];
    const float* txt     = (const float*)d_in[1];
    const float* vec     = (const float*)d_in[2];
    const float* pe      = (const float*)d_in[3];
    const float* i_mod_w = (const float*)d_in[4];
    const float* i_mod_b = (const float*)d_in[5];
    const float* i_qkv_w = (const float*)d_in[6];
    const float* i_q_s   = (const float*)d_in[7];
    const float* i_k_s   = (const float*)d_in[8];
    const float* i_pw    = (const float*)d_in[9];
    const float* i_pb    = (const float*)d_in[10];
    const float* i_w1    = (const float*)d_in[11];
    const float* i_b1    = (const float*)d_in[12];
    const float* i_w2    = (const float*)d_in[13];
    const float* i_b2    = (const float*)d_in[14];
    const float* t_mod_w = (const float*)d_in[15];
    const float* t_mod_b = (const float*)d_in[16];
    const float* t_qkv_w = (const float*)d_in[17];
    const float* t_q_s   = (const float*)d_in[18];
    const float* t_k_s   = (const float*)d_in[19];
    const float* t_pw    = (const float*)d_in[20];
    const float* t_pb    = (const float*)d_in[21];
    const float* t_w1    = (const float*)d_in[22];
    const float* t_b1    = (const float*)d_in[23];
    const float* t_w2    = (const float*)d_in[24];
    const float* t_b2    = (const float*)d_in[25];

    float* out_img = (float*)d_out;
    float* out_txt = out_img + (size_t)Li * DD;

    float *sv, *mod_i, *mod_t, *qkv_i, *qkv_t, *res_i, *res_t;
    __half *mxi_h, *mxi_l, *mxt_h, *mxt_l, *wt_h;
    __half *qh, *ql, *kh, *vth, *vtl, *aoh, *aol, *hh, *hl, *mh, *ml;
    SYMF(sv, g_sv); SYMF(mod_i, g_mod_img); SYMF(mod_t, g_mod_txt);
    SYMF(qkv_i, g_qkv_img); SYMF(qkv_t, g_qkv_txt);
    SYMF(res_i, g_res_i); SYMF(res_t, g_res_t);
    SYMH(mxi_h, g_mxi_h); SYMH(mxi_l, g_mxi_l); SYMH(mxt_h, g_mxt_h); SYMH(mxt_l, g_mxt_l);
    SYMH(wt_h, g_wt_h);
    SYMH(qh, g_qh); SYMH(ql, g_ql); SYMH(kh, g_kh);
    SYMH(vth, g_vth); SYMH(vtl, g_vtl);
    SYMH(aoh, g_aoh); SYMH(aol, g_aol);
    SYMH(hh, g_hh); SYMH(hl, g_hl); SYMH(mh, g_mh); SYMH(ml, g_ml);

    cudaFuncSetAttribute(tgemm<0>, cudaFuncAttributeMaxDynamicSharedMemorySize, TGEMM_SMEM);
    cudaFuncSetAttribute(tgemm<2>, cudaFuncAttributeMaxDynamicSharedMemorySize, TGEMM_SMEM);
    cudaFuncSetAttribute(tgemm<3>, cudaFuncAttributeMaxDynamicSharedMemorySize, TGEMM_SMEM);
    cudaFuncSetAttribute(flash_k, cudaFuncAttributeMaxDynamicSharedMemorySize, FLASH_SMEM);

    dim3 wcb(32, 8);

    // 1. modulation
    silu_k<<<(DD + 255) / 256, 256>>>(vec, sv);
    modmul_k<<<6 * DD / 128, 128>>>(sv, i_mod_w, i_mod_b, mod_i);
    modmul_k<<<6 * DD / 128, 128>>>(sv, t_mod_w, t_mod_b, mod_t);

    // 2. LN1 + modulate -> fp16 hi/lo
    ln_mod_split_k<<<Li, 256>>>(img, mxi_h, mxi_l, mod_i + 0 * DD, mod_i + 1 * DD);
    ln_mod_split_k<<<Lt, 256>>>(txt, mxt_h, mxt_l, mod_t + 0 * DD, mod_t + 1 * DD);

    // 3. QKV GEMMs
    wconv_k<<<dim3(3 * DD / 32, DD / 32), wcb>>>(i_qkv_w, wt_h, DD, 3 * DD);
    tgemm<0><<<dim3(3 * DD / 128, Li / 128, 1), 256, TGEMM_SMEM>>>(
        mxi_h, mxi_l, 0, wt_h, 0, qkv_i, 0, nullptr, nullptr,
        DD, DD, DD, 3 * DD, 1.0f, nullptr, nullptr, nullptr, 0);
    wconv_k<<<dim3(3 * DD / 32, DD / 32), wcb>>>(t_qkv_w, wt_h, DD, 3 * DD);
    tgemm<0><<<dim3(3 * DD / 128, Lt / 128, 1), 256, TGEMM_SMEM>>>(
        mxt_h, mxt_l, 0, wt_h, 0, qkv_t, 0, nullptr, nullptr,
        DD, DD, DD, 3 * DD, 1.0f, nullptr, nullptr, nullptr, 0);

    // 4. split + rmsnorm + rope
    qkv_prep_k<<<dim3(HH, LL), HD>>>(qkv_t, qkv_i, t_q_s, t_k_s, i_q_s, i_k_s, pe,
                                     qh, ql, kh, vth, vtl);

    // 5. fused flash attention -> aoh/aol
    flash_k<<<dim3(LL / 128, HH), 256, FLASH_SMEM>>>(qh, ql, kh, vth, vtl, aoh, aol);

    // 6. proj + gated residual
    wconv_k<<<dim3(DD / 32, DD / 32), wcb>>>(i_pw, wt_h, DD, DD);
    tgemm<2><<<dim3(DD / 128, Li / 128, 1), 256, TGEMM_SMEM>>>(
        aoh + (size_t)Lt * DD, aol + (size_t)Lt * DD, 0, wt_h, 0,
        res_i, 0, nullptr, nullptr,
        DD, DD, DD, DD, 1.0f, i_pb, mod_i + 2 * DD, img, DD);
    wconv_k<<<dim3(DD / 32, DD / 32), wcb>>>(t_pw, wt_h, DD, DD);
    tgemm<2><<<dim3(DD / 128, Lt / 128, 1), 256, TGEMM_SMEM>>>(
        aoh, aol, 0, wt_h, 0, res_t, 0, nullptr, nullptr,
        DD, DD, DD, DD, 1.0f, t_pb, mod_t + 2 * DD, txt, DD);

    // 7. img MLP
    ln_mod_split_k<<<Li, 256>>>(res_i, hh, hl, mod_i + 3 * DD, mod_i + 4 * DD);
    wconv_k<<<dim3(MLPD / 32, DD / 32), wcb>>>(i_w1, wt_h, DD, MLPD);
    tgemm<3><<<dim3(MLPD / 128, Li / 128, 1), 256, TGEMM_SMEM>>>(
        hh, hl, 0, wt_h, 0, nullptr, 0, mh, ml,
        DD, DD, DD, MLPD, 1.0f, i_b1, nullptr, nullptr, 0);
    wconv_k<<<dim3(DD / 32, MLPD / 32), wcb>>>(i_w2, wt_h, MLPD, DD);
    tgemm<2><<<dim3(DD / 128, Li / 128, 1), 256, TGEMM_SMEM>>>(
        mh, ml, 0, wt_h, 0, out_img, 0, nullptr, nullptr,
        MLPD, MLPD, MLPD, DD, 1.0f, i_b2, mod_i + 5 * DD, res_i, DD);

    // 8. txt MLP
    ln_mod_split_k<<<Lt, 256>>>(res_t, hh, hl, mod_t + 3 * DD, mod_t + 4 * DD);
    wconv_k<<<dim3(MLPD / 32, DD / 32), wcb>>>(t_w1, wt_h, DD, MLPD);
    tgemm<3><<<dim3(MLPD / 128, Lt / 128, 1), 256, TGEMM_SMEM>>>(
        hh, hl, 0, wt_h, 0, nullptr, 0, mh, ml,
        DD, DD, DD, MLPD, 1.0f, t_b1, nullptr, nullptr, 0);
    wconv_k<<<dim3(DD / 32, MLPD / 32), wcb>>>(t_w2, wt_h, MLPD, DD);
    tgemm<2><<<dim3(DD / 128, Lt / 128, 1), 256, TGEMM_SMEM>>>(
        mh, ml, 0, wt_h, 0, out_txt, 0, nullptr, nullptr,
        MLPD, MLPD, MLPD, DD, 1.0f, t_b2, mod_t + 5 * DD, res_t, DD);

    (void)in_sizes; (void)n_in; (void)out_size;
}

// round 11
// speedup vs baseline: 1.3584x; 1.3584x over previous
#include <cuda_runtime.h>
#include <cuda_fp16.h>
#include <math.h>
#include <stdint.h>

#define Lt 256
#define Li 2048
#define LL 2304          // Lt + Li
#define DD 2048
#define HH 16
#define HD 128
#define MLPD 8192
#define EPSF 1e-6f

// ================= helpers =================
__device__ __forceinline__ uint32_t smem_to_u32(const void* p) {
    uint32_t a;
    asm("{ .reg .u64 t; cvta.to.shared.u64 t, %1; cvt.u32.u64 %0, t; }" : "=r"(a) : "l"(p));
    return a;
}
__device__ __forceinline__ void cpa16(uint32_t dst, const void* src) {
    asm volatile("cp.async.cg.shared.global [%0], [%1], 16;" :: "r"(dst), "l"(src));
}
#define CP_COMMIT() asm volatile("cp.async.commit_group;" ::: "memory")
#define CP_WAIT(N)  asm volatile("cp.async.wait_group %0;" :: "n"(N) : "memory")

__device__ __forceinline__ void ldsm_x4(uint32_t addr, uint32_t* r) {
    asm volatile("ldmatrix.sync.aligned.m8n8.x4.shared.b16 {%0,%1,%2,%3}, [%4];"
                 : "=r"(r[0]), "=r"(r[1]), "=r"(r[2]), "=r"(r[3]) : "r"(addr));
}
__device__ __forceinline__ void ldsm_x2(uint32_t addr, uint32_t* r) {
    asm volatile("ldmatrix.sync.aligned.m8n8.x2.shared.b16 {%0,%1}, [%2];"
                 : "=r"(r[0]), "=r"(r[1]) : "r"(addr));
}
__device__ __forceinline__ void mma_fp16(float* d, const uint32_t* a, const uint32_t* b) {
    asm volatile(
        "mma.sync.aligned.m16n8k16.row.col.f32.f16.f16.f32 "
        "{%0,%1,%2,%3}, {%4,%5,%6,%7}, {%8,%9}, {%0,%1,%2,%3};"
        : "+f"(d[0]), "+f"(d[1]), "+f"(d[2]), "+f"(d[3])
        : "r"(a[0]), "r"(a[1]), "r"(a[2]), "r"(a[3]), "r"(b[0]), "r"(b[1]));
}

__device__ __forceinline__ void split2(float x, __half& h, __half& l) {
    h = __float2half_rn(x);
    l = __float2half_rn(x - __half2float(h));
}
__device__ __forceinline__ float gelu_tanh(float x) {
    float x3 = x * x * x;
    return 0.5f * x * (1.0f + tanhf(0.7978845608028654f * (x + 0.044715f * x3)));
}

// ================= scratch (static device globals) =================
__device__ __align__(16) float g_sv[DD];
__device__ __align__(16) float g_mod_img[6 * DD];
__device__ __align__(16) float g_mod_txt[6 * DD];
__device__ __align__(16) __half g_mxi_h[Li * DD];
__device__ __align__(16) __half g_mxt_h[Lt * DD];
__device__ __align__(16) __half g_wt_h[MLPD * DD];   // transposed rounded weight
__device__ __align__(16) float g_qkv_img[Li * 3 * DD];
__device__ __align__(16) float g_qkv_txt[Lt * 3 * DD];
__device__ __align__(16) __half g_qh[HH * LL * HD];
__device__ __align__(16) __half g_ql[HH * LL * HD];
__device__ __align__(16) __half g_kh[HH * LL * HD];
__device__ __align__(16) __half g_vth[HH * HD * LL]; // V transposed per head [H, HD, LL]
__device__ __align__(16) __half g_vtl[HH * HD * LL];
__device__ __align__(16) __half g_aoh[LL * DD];
__device__ __align__(16) float g_res_i[Li * DD];
__device__ __align__(16) float g_res_t[Lt * DD];
__device__ __align__(16) __half g_hh[Li * DD];
__device__ __align__(16) __half g_mh[(size_t)Li * MLPD];

// ================= small kernels =================
__global__ void silu_k(const float* __restrict__ vec, float* __restrict__ sv) {
    int i = blockIdx.x * blockDim.x + threadIdx.x;
    if (i < DD) { float x = vec[i]; sv[i] = x / (1.0f + __expf(-x)); }
}

__global__ void modmul_k(const float* __restrict__ sv, const float* __restrict__ W,
                         const float* __restrict__ b, float* __restrict__ out) {
    __shared__ float s[DD];
    for (int i = threadIdx.x; i < DD; i += 128) s[i] = sv[i];
    __syncthreads();
    int j = blockIdx.x * 128 + threadIdx.x;
    float acc = 0.0f;
    const float* wp = W + j;
    for (int d = 0; d < DD; d++) acc += s[d] * wp[(size_t)d * (6 * DD)];
    out[j] = acc + b[j];
}

// y = round_fp16((1+sc)*LN(x) + sh)
__global__ void ln_mod_h_k(const float* __restrict__ x,
                           __half* __restrict__ yh,
                           const float* __restrict__ sh, const float* __restrict__ sc) {
    int row = blockIdx.x;
    const float* px = x + (size_t)row * DD;
    __shared__ float red[256];
    int tid = threadIdx.x;
    float v[8];
    float s = 0.0f;
#pragma unroll
    for (int i = 0; i < 8; i++) { v[i] = px[tid + i * 256]; s += v[i]; }
    red[tid] = s; __syncthreads();
    for (int o = 128; o > 0; o >>= 1) { if (tid < o) red[tid] += red[tid + o]; __syncthreads(); }
    float mu = red[0] * (1.0f / DD);
    __syncthreads();
    float ss = 0.0f;
#pragma unroll
    for (int i = 0; i < 8; i++) { float d = v[i] - mu; ss += d * d; }
    red[tid] = ss; __syncthreads();
    for (int o = 128; o > 0; o >>= 1) { if (tid < o) red[tid] += red[tid + o]; __syncthreads(); }
    float r = rsqrtf(red[0] * (1.0f / DD) + EPSF);
#pragma unroll
    for (int i = 0; i < 8; i++) {
        int c = tid + i * 256;
        float y = (1.0f + sc[c]) * ((v[i] - mu) * r) + sh[c];
        yh[(size_t)row * DD + c] = __float2half_rn(y);
    }
}

// transpose + round: W[K,N] fp32 -> Wt [N,K] fp16
__global__ void wconv_k(const float* __restrict__ W,
                        __half* __restrict__ Wh, int Kd, int Nd) {
    __shared__ float t[32][33];
    int n = blockIdx.x * 32 + threadIdx.x;
#pragma unroll
    for (int i = 0; i < 4; i++) {
        int k = blockIdx.y * 32 + threadIdx.y + i * 8;
        t[threadIdx.y + i * 8][threadIdx.x] = W[(size_t)k * Nd + n];
    }
    __syncthreads();
    int k2 = blockIdx.y * 32 + threadIdx.x;
#pragma unroll
    for (int i = 0; i < 4; i++) {
        int n2 = blockIdx.x * 32 + threadIdx.y + i * 8;
        Wh[(size_t)n2 * Kd + k2] = __float2half_rn(t[threadIdx.x][threadIdx.y + i * 8]);
    }
}

// split qkv, rmsnorm(q,k)*scale, rope(q,k); q split hi/lo, k rounded, v split (transposed)
__global__ void qkv_prep_k(const float* __restrict__ qkv_txt, const float* __restrict__ qkv_img,
                           const float* __restrict__ tq_s, const float* __restrict__ tk_s,
                           const float* __restrict__ iq_s, const float* __restrict__ ik_s,
                           const float* __restrict__ pe,
                           __half* __restrict__ qh, __half* __restrict__ ql,
                           __half* __restrict__ kh,
                           __half* __restrict__ vth, __half* __restrict__ vtl) {
    int h = blockIdx.x;
    int pos = blockIdx.y;
    int d = threadIdx.x;
    const float* src; int l; const float* qs; const float* ks;
    if (pos < Lt) { src = qkv_txt; l = pos;      qs = tq_s; ks = tk_s; }
    else          { src = qkv_img; l = pos - Lt; qs = iq_s; ks = ik_s; }
    const float* base = src + (size_t)l * (3 * DD) + h * HD;
    float qv = base[d];
    float kv = base[DD + d];
    float vv = base[2 * DD + d];

    __shared__ float sq[HD], sk[HD], red[8];
    float q2 = qv * qv, k2 = kv * kv;
#pragma unroll
    for (int o = 16; o > 0; o >>= 1) {
        q2 += __shfl_xor_sync(0xFFFFFFFFu, q2, o);
        k2 += __shfl_xor_sync(0xFFFFFFFFu, k2, o);
    }
    int w = d >> 5;
    if ((d & 31) == 0) { red[w] = q2; red[4 + w] = k2; }
    __syncthreads();
    float qss = red[0] + red[1] + red[2] + red[3];
    float kss = red[4] + red[5] + red[6] + red[7];
    float qn = qv * rsqrtf(qss * (1.0f / HD) + EPSF) * qs[d];
    float kn = kv * rsqrtf(kss * (1.0f / HD) + EPSF) * ks[d];
    sq[d] = qn; sk[d] = kn;
    __syncthreads();
    int i = d >> 1, j = d & 1;
    const float* pp = pe + (((size_t)pos * 64 + i) * 4 + j * 2);
    float p0 = pp[0], p1 = pp[1];
    float rq = p0 * sq[2 * i] + p1 * sq[2 * i + 1];
    float rk = p0 * sk[2 * i] + p1 * sk[2 * i + 1];
    size_t o = ((size_t)h * LL + pos) * HD + d;
    __half a, b;
    split2(rq, a, b); qh[o] = a; ql[o] = b;
    kh[o] = __float2half_rn(rk);
    size_t ov = ((size_t)h * HD + d) * LL + pos;
    split2(vv, a, b); vth[ov] = a; vtl[ov] = b;
}

// ================= fused flash attention =================
// Per CTA: one head, 128 Q rows. KV chunks of 64, double-buffered cp.async.
// S = (qh+ql)·kh (2 mma), P rounded fp16, O += pH·(vh+vl) (2 mma).
#define FCHUNK 64
#define NCHUNK (LL / FCHUNK)       // 36
#define F_QROW 272                 // 128 cols fp16 + 16B pad
#define F_QSZ  (128 * F_QROW)      // 34816 per array
#define F_KROW 272
#define F_KSZ  (64 * F_KROW)       // 17408
#define F_VROW 144                 // 64 cols fp16 + 16B pad
#define F_VSZ  (128 * F_VROW)      // 18432 per array
#define F_STG0 (2 * F_QSZ)         // 69632
#define F_STGSZ (F_KSZ + 2 * F_VSZ)      // 54272
#define FLASH_SMEM (F_STG0 + 2 * F_STGSZ) // 178176

__global__ __launch_bounds__(256, 1) void flash_k(
    const __half* __restrict__ qhg, const __half* __restrict__ qlg,
    const __half* __restrict__ khg,
    const __half* __restrict__ vthg, const __half* __restrict__ vtlg,
    __half* __restrict__ aoh) {
    extern __shared__ char smem[];
    uint32_t sb = smem_to_u32(smem);
    int tid = threadIdx.x, wid = tid >> 5, lane = tid & 31;
    int h = blockIdx.y, qt = blockIdx.x;
    const float iscale = 0.08838834764831845f; // 1/sqrt(128)

    // ---- load Q tile (once) ----
#pragma unroll
    for (int i = 0; i < 8; i++) {
        int u = tid + i * 256;          // 0..2047
        int row = u >> 4, cu = u & 15;
        size_t go = ((size_t)h * LL + qt * 128 + row) * HD + cu * 8;
        cpa16(sb + row * F_QROW + cu * 16, qhg + go);
        cpa16(sb + F_QSZ + row * F_QROW + cu * 16, qlg + go);
    }
    CP_COMMIT();

    // ---- prefetch chunk 0 ----
    {
        uint32_t st = sb + F_STG0;
#pragma unroll
        for (int i = 0; i < 4; i++) {
            int u = tid + i * 256;      // 0..1023
            int row = u >> 4, cu = u & 15;
            size_t go = ((size_t)h * LL + row) * HD + cu * 8;
            cpa16(st + row * F_KROW + cu * 16, khg + go);
            int vr = u >> 3, vc = u & 7;
            size_t gv = ((size_t)h * HD + vr) * LL + vc * 8;
            cpa16(st + F_KSZ + vr * F_VROW + vc * 16, vthg + gv);
            cpa16(st + F_KSZ + F_VSZ + vr * F_VROW + vc * 16, vtlg + gv);
        }
        CP_COMMIT();
    }

    float o[16][4];
#pragma unroll
    for (int i = 0; i < 16; i++)
#pragma unroll
        for (int f = 0; f < 4; f++) o[i][f] = 0.0f;
    float m0 = -1e30f, m1 = -1e30f, l0 = 0.0f, l1 = 0.0f;

    uint32_t qa_base = sb + (wid * 16 + (lane & 15)) * F_QROW + ((lane >> 4) * 16);

    for (int j = 0; j < NCHUNK; j++) {
        CP_WAIT(0);
        __syncthreads();
        if (j + 1 < NCHUNK) {
            int ln = (j + 1) * FCHUNK;
            uint32_t st = sb + F_STG0 + ((j + 1) & 1) * F_STGSZ;
#pragma unroll
            for (int i = 0; i < 4; i++) {
                int u = tid + i * 256;
                int row = u >> 4, cu = u & 15;
                size_t go = ((size_t)h * LL + ln + row) * HD + cu * 8;
                cpa16(st + row * F_KROW + cu * 16, khg + go);
                int vr = u >> 3, vc = u & 7;
                size_t gv = ((size_t)h * HD + vr) * LL + ln + vc * 8;
                cpa16(st + F_KSZ + vr * F_VROW + vc * 16, vthg + gv);
                cpa16(st + F_KSZ + F_VSZ + vr * F_VROW + vc * 16, vtlg + gv);
            }
            CP_COMMIT();
        }

        uint32_t st = sb + F_STG0 + (j & 1) * F_STGSZ;

        // ---- S = Q @ K^T ----
        float S[8][4];
#pragma unroll
        for (int i = 0; i < 8; i++)
#pragma unroll
            for (int f = 0; f < 4; f++) S[i][f] = 0.0f;
#pragma unroll
        for (int kk = 0; kk < 8; kk++) {
            uint32_t aH[4], aL[4], bArr[8][2];
            uint32_t qa = qa_base + kk * 32;
            ldsm_x4(qa, aH);
            ldsm_x4(qa + F_QSZ, aL);
#pragma unroll
            for (int ni = 0; ni < 8; ni++) {
                uint32_t ka = st + (ni * 8 + (lane & 7)) * F_KROW + ((lane >> 3) & 1) * 16 + kk * 32;
                ldsm_x2(ka, bArr[ni]);
            }
#pragma unroll
            for (int ni = 0; ni < 8; ni++) mma_fp16(S[ni], aH, bArr[ni]);
#pragma unroll
            for (int ni = 0; ni < 8; ni++) mma_fp16(S[ni], aL, bArr[ni]);
        }

        // ---- online softmax ----
        float rm0 = -1e30f, rm1 = -1e30f;
#pragma unroll
        for (int ni = 0; ni < 8; ni++) {
            rm0 = fmaxf(rm0, fmaxf(S[ni][0], S[ni][1]));
            rm1 = fmaxf(rm1, fmaxf(S[ni][2], S[ni][3]));
        }
        rm0 = fmaxf(rm0, __shfl_xor_sync(0xFFFFFFFFu, rm0, 1));
        rm0 = fmaxf(rm0, __shfl_xor_sync(0xFFFFFFFFu, rm0, 2));
        rm1 = fmaxf(rm1, __shfl_xor_sync(0xFFFFFFFFu, rm1, 1));
        rm1 = fmaxf(rm1, __shfl_xor_sync(0xFFFFFFFFu, rm1, 2));
        float mn0 = fmaxf(m0, rm0), mn1 = fmaxf(m1, rm1);
        float f0 = __expf((m0 - mn0) * iscale);
        float f1 = __expf((m1 - mn1) * iscale);
        m0 = mn0; m1 = mn1;
        float rs0 = 0.0f, rs1 = 0.0f;
#pragma unroll
        for (int ni = 0; ni < 8; ni++) {
            S[ni][0] = __expf((S[ni][0] - mn0) * iscale);
            S[ni][1] = __expf((S[ni][1] - mn0) * iscale);
            S[ni][2] = __expf((S[ni][2] - mn1) * iscale);
            S[ni][3] = __expf((S[ni][3] - mn1) * iscale);
            rs0 += S[ni][0] + S[ni][1];
            rs1 += S[ni][2] + S[ni][3];
        }
        rs0 += __shfl_xor_sync(0xFFFFFFFFu, rs0, 1);
        rs0 += __shfl_xor_sync(0xFFFFFFFFu, rs0, 2);
        rs1 += __shfl_xor_sync(0xFFFFFFFFu, rs1, 1);
        rs1 += __shfl_xor_sync(0xFFFFFFFFu, rs1, 2);
        l0 = l0 * f0 + rs0;
        l1 = l1 * f1 + rs1;
#pragma unroll
        for (int ni = 0; ni < 16; ni++) {
            o[ni][0] *= f0; o[ni][1] *= f0;
            o[ni][2] *= f1; o[ni][3] *= f1;
        }

        // ---- O += P @ V ----
#pragma unroll
        for (int kf = 0; kf < 4; kf++) {
            uint32_t pH[4];
            {
                float* c0 = S[2 * kf];
                float* c1 = S[2 * kf + 1];
                __half2 t;
                t = __floats2half2_rn(c0[0], c0[1]); pH[0] = *(uint32_t*)&t;
                t = __floats2half2_rn(c0[2], c0[3]); pH[1] = *(uint32_t*)&t;
                t = __floats2half2_rn(c1[0], c1[1]); pH[2] = *(uint32_t*)&t;
                t = __floats2half2_rn(c1[2], c1[3]); pH[3] = *(uint32_t*)&t;
            }
#pragma unroll
            for (int ni = 0; ni < 16; ni++) {
                uint32_t bH[2];
                uint32_t va = st + F_KSZ + (ni * 8 + (lane & 7)) * F_VROW +
                              ((lane >> 3) & 1) * 16 + kf * 32;
                ldsm_x2(va, bH);
                mma_fp16(o[ni], pH, bH);
            }
#pragma unroll
            for (int ni = 0; ni < 16; ni++) {
                uint32_t bL[2];
                uint32_t va = st + F_KSZ + F_VSZ + (ni * 8 + (lane & 7)) * F_VROW +
                              ((lane >> 3) & 1) * 16 + kf * 32;
                ldsm_x2(va, bL);
                mma_fp16(o[ni], pH, bL);
            }
        }
        __syncthreads();
    }

    // ---- normalize + write out (fp16 rounded) ----
    float inv0 = 1.0f / l0, inv1 = 1.0f / l1;
    int row0 = qt * 128 + wid * 16 + (lane >> 2);
    int row1 = row0 + 8;
#pragma unroll
    for (int ni = 0; ni < 16; ni++) {
        int col = h * HD + ni * 8 + (lane & 3) * 2;
        __half2 h0 = __floats2half2_rn(o[ni][0] * inv0, o[ni][1] * inv0);
        __half2 h1 = __floats2half2_rn(o[ni][2] * inv1, o[ni][3] * inv1);
        *(__half2*)&aoh[(size_t)row0 * DD + col] = h0;
        *(__half2*)&aoh[(size_t)row1 * DD + col] = h1;
    }
}

// ================= HMMA (mma.sync fp16) GEMM =================
// C[M,N] = epi( Ah[M,K] @ Bh[N,K]^T ), single-product (both operands fp16-rounded),
// fp32 accum. CTA tile 128x128, BK=32. 8 warps (2x4), warp tile 64x32.
#define SROW 80
#define ARRB (128 * SROW)
#define STAGEB (2 * ARRB)
#define TGEMM_SMEM (2 * STAGEB)    // 40960

template <int EPI>
__global__ __launch_bounds__(256, 1) void tgemm(
    const __half* __restrict__ Ah, long long sAz,
    const __half* __restrict__ Bh, long long sBz,
    float* __restrict__ C, long long sCz,
    __half* __restrict__ Chi,
    int K, int lda, int ldb, int ldc, float alpha,
    const float* __restrict__ bias, const float* __restrict__ gate,
    const float* __restrict__ res, int ldres) {
    extern __shared__ char smem[];
    uint32_t sb = smem_to_u32(smem);
    int tid = threadIdx.x, wid = tid >> 5, lane = tid & 31;
    int warpM = wid >> 2, warpN = wid & 3;
    int m0 = blockIdx.y * 128, n0 = blockIdx.x * 128;
    int z = blockIdx.z;
    Ah += (size_t)z * sAz;
    Bh += (size_t)z * sBz;
    if (C)   C   += (size_t)z * sCz;
    if (Chi) Chi += (size_t)z * sCz;

    const __half* g0 = Ah + (size_t)m0 * lda;
    const __half* g2 = Bh + (size_t)n0 * ldb;

    int r0 = tid >> 2, q0 = tid & 3;
    int r1 = (tid + 256) >> 2, q1 = q0;
    uint32_t d00 = sb + r0 * SROW + q0 * 16;
    uint32_t d01 = sb + r1 * SROW + q1 * 16;

    float acc[4][4][4];
#pragma unroll
    for (int i = 0; i < 4; i++)
#pragma unroll
        for (int j = 0; j < 4; j++)
#pragma unroll
            for (int f = 0; f < 4; f++) acc[i][j][f] = 0.0f;

    int nit = K / 32;

    {
        cpa16(d00 + 0 * ARRB, g0 + (size_t)r0 * lda + q0 * 8);
        cpa16(d01 + 0 * ARRB, g0 + (size_t)r1 * lda + q1 * 8);
        cpa16(d00 + 1 * ARRB, g2 + (size_t)r0 * ldb + q0 * 8);
        cpa16(d01 + 1 * ARRB, g2 + (size_t)r1 * ldb + q1 * 8);
        CP_COMMIT();
    }

    uint32_t a_base = sb + (warpM * 64 + (lane & 15)) * SROW + ((lane >> 4) * 16);
    uint32_t b_base = sb + 1 * ARRB + (warpN * 32 + (lane & 7)) * SROW + (((lane >> 3) & 1) * 16);

    for (int it = 0; it < nit; it++) {
        bool pf = (it + 1) < nit;
        if (pf) {
            int k0 = (it + 1) * 32;
            uint32_t st = ((it + 1) & 1) * STAGEB;
            cpa16(d00 + st + 0 * ARRB, g0 + (size_t)r0 * lda + k0 + q0 * 8);
            cpa16(d01 + st + 0 * ARRB, g0 + (size_t)r1 * lda + k0 + q1 * 8);
            cpa16(d00 + st + 1 * ARRB, g2 + (size_t)r0 * ldb + k0 + q0 * 8);
            cpa16(d01 + st + 1 * ARRB, g2 + (size_t)r1 * ldb + k0 + q1 * 8);
            CP_COMMIT();
            CP_WAIT(1);
        } else {
            CP_WAIT(0);
        }
        __syncthreads();

        uint32_t st = (it & 1) * STAGEB;
        uint32_t ab = a_base + st;
        uint32_t bb = b_base + st;
#pragma unroll
        for (int kk = 0; kk < 2; kk++) {
            int kb = kk * 32;
            uint32_t ah[4][4], bh[4][2];
#pragma unroll
            for (int mi = 0; mi < 4; mi++)
                ldsm_x4(ab + mi * (16 * SROW) + kb, ah[mi]);
#pragma unroll
            for (int ni = 0; ni < 4; ni++)
                ldsm_x2(bb + ni * (8 * SROW) + kb, bh[ni]);
#pragma unroll
            for (int ni = 0; ni < 4; ni++)
#pragma unroll
                for (int mi = 0; mi < 4; mi++)
                    mma_fp16(acc[mi][ni], ah[mi], bh[ni]);
        }
        __syncthreads();
    }

    int rbase = m0 + warpM * 64 + (lane >> 2);
    int cbase = n0 + warpN * 32 + (lane & 3) * 2;
#pragma unroll
    for (int mi = 0; mi < 4; mi++) {
#pragma unroll
        for (int ni = 0; ni < 4; ni++) {
            int col = cbase + ni * 8;
#pragma unroll
            for (int hf = 0; hf < 2; hf++) {
                int row = rbase + mi * 16 + hf * 8;
                float v0 = acc[mi][ni][hf * 2 + 0];
                float v1 = acc[mi][ni][hf * 2 + 1];
                if (EPI == 0) {
                    float2 oo; oo.x = alpha * v0; oo.y = alpha * v1;
                    *(float2*)&C[(size_t)row * ldc + col] = oo;
                } else if (EPI == 2) {
                    float2 oo;
                    oo.x = res[(size_t)row * ldres + col + 0] + gate[col + 0] * (v0 + bias[col + 0]);
                    oo.y = res[(size_t)row * ldres + col + 1] + gate[col + 1] * (v1 + bias[col + 1]);
                    *(float2*)&C[(size_t)row * ldc + col] = oo;
                } else { // EPI 3: gelu -> fp16
                    float gg0 = gelu_tanh(v0 + bias[col]);
                    float gg1 = gelu_tanh(v1 + bias[col + 1]);
                    __half2 hp = __floats2half2_rn(gg0, gg1);
                    *(__half2*)&Chi[(size_t)row * ldc + col] = hp;
                }
            }
        }
    }
}

// ================= host side =================
#define SYMF(p, s) do { void* _t = nullptr; cudaGetSymbolAddress(&_t, s); (p) = (float*)_t; } while (0)
#define SYMH(p, s) do { void* _t = nullptr; cudaGetSymbolAddress(&_t, s); (p) = (__half*)_t; } while (0)

extern "C" void kernel_launch(void* const* d_in, const int* in_sizes, int n_in,
                              void* d_out, int out_size) {
    const float* img     = (const float*)d_in[0];
    const float* txt     = (const float*)d_in[1];
    const float* vec     = (const float*)d_in[2];
    const float* pe      = (const float*)d_in[3];
    const float* i_mod_w = (const float*)d_in[4];
    const float* i_mod_b = (const float*)d_in[5];
    const float* i_qkv_w = (const float*)d_in[6];
    const float* i_q_s   = (const float*)d_in[7];
    const float* i_k_s   = (const float*)d_in[8];
    const float* i_pw    = (const float*)d_in[9];
    const float* i_pb    = (const float*)d_in[10];
    const float* i_w1    = (const float*)d_in[11];
    const float* i_b1    = (const float*)d_in[12];
    const float* i_w2    = (const float*)d_in[13];
    const float* i_b2    = (const float*)d_in[14];
    const float* t_mod_w = (const float*)d_in[15];
    const float* t_mod_b = (const float*)d_in[16];
    const float* t_qkv_w = (const float*)d_in[17];
    const float* t_q_s   = (const float*)d_in[18];
    const float* t_k_s   = (const float*)d_in[19];
    const float* t_pw    = (const float*)d_in[20];
    const float* t_pb    = (const float*)d_in[21];
    const float* t_w1    = (const float*)d_in[22];
    const float* t_b1    = (const float*)d_in[23];
    const float* t_w2    = (const float*)d_in[24];
    const float* t_b2    = (const float*)d_in[25];

    float* out_img = (float*)d_out;
    float* out_txt = out_img + (size_t)Li * DD;

    float *sv, *mod_i, *mod_t, *qkv_i, *qkv_t, *res_i, *res_t;
    __half *mxi_h, *mxt_h, *wt_h;
    __half *qh, *ql, *kh, *vth, *vtl, *aoh, *hh, *mh;
    SYMF(sv, g_sv); SYMF(mod_i, g_mod_img); SYMF(mod_t, g_mod_txt);
    SYMF(qkv_i, g_qkv_img); SYMF(qkv_t, g_qkv_txt);
    SYMF(res_i, g_res_i); SYMF(res_t, g_res_t);
    SYMH(mxi_h, g_mxi_h); SYMH(mxt_h, g_mxt_h);
    SYMH(wt_h, g_wt_h);
    SYMH(qh, g_qh); SYMH(ql, g_ql); SYMH(kh, g_kh);
    SYMH(vth, g_vth); SYMH(vtl, g_vtl);
    SYMH(aoh, g_aoh);
    SYMH(hh, g_hh); SYMH(mh, g_mh);

    cudaFuncSetAttribute(tgemm<0>, cudaFuncAttributeMaxDynamicSharedMemorySize, TGEMM_SMEM);
    cudaFuncSetAttribute(tgemm<2>, cudaFuncAttributeMaxDynamicSharedMemorySize, TGEMM_SMEM);
    cudaFuncSetAttribute(tgemm<3>, cudaFuncAttributeMaxDynamicSharedMemorySize, TGEMM_SMEM);
    cudaFuncSetAttribute(flash_k, cudaFuncAttributeMaxDynamicSharedMemorySize, FLASH_SMEM);

    dim3 wcb(32, 8);

    // 1. modulation
    silu_k<<<(DD + 255) / 256, 256>>>(vec, sv);
    modmul_k<<<6 * DD / 128, 128>>>(sv, i_mod_w, i_mod_b, mod_i);
    modmul_k<<<6 * DD / 128, 128>>>(sv, t_mod_w, t_mod_b, mod_t);

    // 2. LN1 + modulate -> fp16
    ln_mod_h_k<<<Li, 256>>>(img, mxi_h, mod_i + 0 * DD, mod_i + 1 * DD);
    ln_mod_h_k<<<Lt, 256>>>(txt, mxt_h, mod_t + 0 * DD, mod_t + 1 * DD);

    // 3. QKV GEMMs
    wconv_k<<<dim3(3 * DD / 32, DD / 32), wcb>>>(i_qkv_w, wt_h, DD, 3 * DD);
    tgemm<0><<<dim3(3 * DD / 128, Li / 128, 1), 256, TGEMM_SMEM>>>(
        mxi_h, 0, wt_h, 0, qkv_i, 0, nullptr,
        DD, DD, DD, 3 * DD, 1.0f, nullptr, nullptr, nullptr, 0);
    wconv_k<<<dim3(3 * DD / 32, DD / 32), wcb>>>(t_qkv_w, wt_h, DD, 3 * DD);
    tgemm<0><<<dim3(3 * DD / 128, Lt / 128, 1), 256, TGEMM_SMEM>>>(
        mxt_h, 0, wt_h, 0, qkv_t, 0, nullptr,
        DD, DD, DD, 3 * DD, 1.0f, nullptr, nullptr, nullptr, 0);

    // 4. split + rmsnorm + rope
    qkv_prep_k<<<dim3(HH, LL), HD>>>(qkv_t, qkv_i, t_q_s, t_k_s, i_q_s, i_k_s, pe,
                                     qh, ql, kh, vth, vtl);

    // 5. fused flash attention -> aoh
    flash_k<<<dim3(LL / 128, HH), 256, FLASH_SMEM>>>(qh, ql, kh, vth, vtl, aoh);

    // 6. proj + gated residual
    wconv_k<<<dim3(DD / 32, DD / 32), wcb>>>(i_pw, wt_h, DD, DD);
    tgemm<2><<<dim3(DD / 128, Li / 128, 1), 256, TGEMM_SMEM>>>(
        aoh + (size_t)Lt * DD, 0, wt_h, 0, res_i, 0, nullptr,
        DD, DD, DD, DD, 1.0f, i_pb, mod_i + 2 * DD, img, DD);
    wconv_k<<<dim3(DD / 32, DD / 32), wcb>>>(t_pw, wt_h, DD, DD);
    tgemm<2><<<dim3(DD / 128, Lt / 128, 1), 256, TGEMM_SMEM>>>(
        aoh, 0, wt_h, 0, res_t, 0, nullptr,
        DD, DD, DD, DD, 1.0f, t_pb, mod_t + 2 * DD, txt, DD);

    // 7. img MLP
    ln_mod_h_k<<<Li, 256>>>(res_i, hh, mod_i + 3 * DD, mod_i + 4 * DD);
    wconv_k<<<dim3(MLPD / 32, DD / 32), wcb>>>(i_w1, wt_h, DD, MLPD);
    tgemm<3><<<dim3(MLPD / 128, Li / 128, 1), 256, TGEMM_SMEM>>>(
        hh, 0, wt_h, 0, nullptr, 0, mh,
        DD, DD, DD, MLPD, 1.0f, i_b1, nullptr, nullptr, 0);
    wconv_k<<<dim3(DD / 32, MLPD / 32), wcb>>>(i_w2, wt_h, MLPD, DD);
    tgemm<2><<<dim3(DD / 128, Li / 128, 1), 256, TGEMM_SMEM>>>(
        mh, 0, wt_h, 0, out_img, 0, nullptr,
        MLPD, MLPD, MLPD, DD, 1.0f, i_b2, mod_i + 5 * DD, res_i, DD);

    // 8. txt MLP
    ln_mod_h_k<<<Lt, 256>>>(res_t, hh, mod_t + 3 * DD, mod_t + 4 * DD);
    wconv_k<<<dim3(MLPD / 32, DD / 32), wcb>>>(t_w1, wt_h, DD, MLPD);
    tgemm<3><<<dim3(MLPD / 128, Lt / 128, 1), 256, TGEMM_SMEM>>>(
        hh, 0, wt_h, 0, nullptr, 0, mh,
        DD, DD, DD, MLPD, 1.0f, t_b1, nullptr, nullptr, 0);
    wconv_k<<<dim3(DD / 32, MLPD / 32), wcb>>>(t_w2, wt_h, MLPD, DD);
    tgemm<2><<<dim3(DD / 128, Lt / 128, 1), 256, TGEMM_SMEM>>>(
        mh, 0, wt_h, 0, out_txt, 0, nullptr,
        MLPD, MLPD, MLPD, DD, 1.0f, t_b2, mod_t + 5 * DD, res_t, DD);

    (void)in_sizes; (void)n_in; (void)out_size;
}

// round 13
// speedup vs baseline: 1.6659x; 1.2263x over previous
#include <cuda_runtime.h>
#include <cuda_fp16.h>
#include <math.h>
#include <stdint.h>

#define Lt 256
#define Li 2048
#define LL 2304          // Lt + Li
#define DD 2048
#define HH 16
#define HD 128
#define MLPD 8192
#define EPSF 1e-6f

// ================= helpers =================
__device__ __forceinline__ uint32_t smem_to_u32(const void* p) {
    uint32_t a;
    asm("{ .reg .u64 t; cvta.to.shared.u64 t, %1; cvt.u32.u64 %0, t; }" : "=r"(a) : "l"(p));
    return a;
}
__device__ __forceinline__ void cpa16(uint32_t dst, const void* src) {
    asm volatile("cp.async.cg.shared.global [%0], [%1], 16;" :: "r"(dst), "l"(src));
}
#define CP_COMMIT() asm volatile("cp.async.commit_group;" ::: "memory")
#define CP_WAIT(N)  asm volatile("cp.async.wait_group %0;" :: "n"(N) : "memory")

__device__ __forceinline__ void ldsm_x4(uint32_t addr, uint32_t* r) {
    asm volatile("ldmatrix.sync.aligned.m8n8.x4.shared.b16 {%0,%1,%2,%3}, [%4];"
                 : "=r"(r[0]), "=r"(r[1]), "=r"(r[2]), "=r"(r[3]) : "r"(addr));
}
__device__ __forceinline__ void ldsm_x2(uint32_t addr, uint32_t* r) {
    asm volatile("ldmatrix.sync.aligned.m8n8.x2.shared.b16 {%0,%1}, [%2];"
                 : "=r"(r[0]), "=r"(r[1]) : "r"(addr));
}
__device__ __forceinline__ void mma_fp16(float* d, const uint32_t* a, const uint32_t* b) {
    asm volatile(
        "mma.sync.aligned.m16n8k16.row.col.f32.f16.f16.f32 "
        "{%0,%1,%2,%3}, {%4,%5,%6,%7}, {%8,%9}, {%0,%1,%2,%3};"
        : "+f"(d[0]), "+f"(d[1]), "+f"(d[2]), "+f"(d[3])
        : "r"(a[0]), "r"(a[1]), "r"(a[2]), "r"(a[3]), "r"(b[0]), "r"(b[1]));
}

__device__ __forceinline__ float gelu_tanh(float x) {
    float x3 = x * x * x;
    return 0.5f * x * (1.0f + tanhf(0.7978845608028654f * (x + 0.044715f * x3)));
}

// ================= scratch (static device globals) =================
__device__ __align__(16) float g_sv[DD];
__device__ __align__(16) float g_mod_img[6 * DD];
__device__ __align__(16) float g_mod_txt[6 * DD];
__device__ __align__(16) __half g_mxi_h[Li * DD];
__device__ __align__(16) __half g_mxt_h[Lt * DD];
__device__ __align__(16) __half g_wta[MLPD * DD];    // img weight (transposed fp16)
__device__ __align__(16) __half g_wtb[MLPD * DD];    // txt weight (transposed fp16)
__device__ __align__(16) float g_qkv_img[Li * 3 * DD];
__device__ __align__(16) float g_qkv_txt[Lt * 3 * DD];
__device__ __align__(16) __half g_qh[HH * LL * HD];
__device__ __align__(16) __half g_kh[HH * LL * HD];
__device__ __align__(16) __half g_vth[HH * HD * LL]; // V transposed per head [H, HD, LL]
__device__ __align__(16) __half g_aoh[LL * DD];
__device__ __align__(16) float g_res_i[Li * DD];
__device__ __align__(16) float g_res_t[Lt * DD];
__device__ __align__(16) __half g_hh[Li * DD];
__device__ __align__(16) __half g_ht[Lt * DD];
__device__ __align__(16) __half g_mh[(size_t)Li * MLPD];
__device__ __align__(16) __half g_mt[(size_t)Lt * MLPD];

// ================= small kernels =================
__global__ void silu_k(const float* __restrict__ vec, float* __restrict__ sv) {
    int i = blockIdx.x * blockDim.x + threadIdx.x;
    if (i < DD) { float x = vec[i]; sv[i] = x / (1.0f + __expf(-x)); }
}

__global__ void modmul_k(const float* __restrict__ sv, const float* __restrict__ W,
                         const float* __restrict__ b, float* __restrict__ out) {
    __shared__ float s[DD];
    for (int i = threadIdx.x; i < DD; i += 128) s[i] = sv[i];
    __syncthreads();
    int j = blockIdx.x * 128 + threadIdx.x;
    float acc = 0.0f;
    const float* wp = W + j;
    for (int d = 0; d < DD; d++) acc += s[d] * wp[(size_t)d * (6 * DD)];
    out[j] = acc + b[j];
}

// y = round_fp16((1+sc)*LN(x) + sh)
__global__ void ln_mod_h_k(const float* __restrict__ x,
                           __half* __restrict__ yh,
                           const float* __restrict__ sh, const float* __restrict__ sc) {
    int row = blockIdx.x;
    const float* px = x + (size_t)row * DD;
    __shared__ float red[256];
    int tid = threadIdx.x;
    float v[8];
    float s = 0.0f;
#pragma unroll
    for (int i = 0; i < 8; i++) { v[i] = px[tid + i * 256]; s += v[i]; }
    red[tid] = s; __syncthreads();
    for (int o = 128; o > 0; o >>= 1) { if (tid < o) red[tid] += red[tid + o]; __syncthreads(); }
    float mu = red[0] * (1.0f / DD);
    __syncthreads();
    float ss = 0.0f;
#pragma unroll
    for (int i = 0; i < 8; i++) { float d = v[i] - mu; ss += d * d; }
    red[tid] = ss; __syncthreads();
    for (int o = 128; o > 0; o >>= 1) { if (tid < o) red[tid] += red[tid + o]; __syncthreads(); }
    float r = rsqrtf(red[0] * (1.0f / DD) + EPSF);
#pragma unroll
    for (int i = 0; i < 8; i++) {
        int c = tid + i * 256;
        float y = (1.0f + sc[c]) * ((v[i] - mu) * r) + sh[c];
        yh[(size_t)row * DD + c] = __float2half_rn(y);
    }
}

// transpose + round: W[K,N] fp32 -> Wt [N,K] fp16
__global__ void wconv_k(const float* __restrict__ W,
                        __half* __restrict__ Wh, int Kd, int Nd) {
    __shared__ float t[32][33];
    int n = blockIdx.x * 32 + threadIdx.x;
#pragma unroll
    for (int i = 0; i < 4; i++) {
        int k = blockIdx.y * 32 + threadIdx.y + i * 8;
        t[threadIdx.y + i * 8][threadIdx.x] = W[(size_t)k * Nd + n];
    }
    __syncthreads();
    int k2 = blockIdx.y * 32 + threadIdx.x;
#pragma unroll
    for (int i = 0; i < 4; i++) {
        int n2 = blockIdx.x * 32 + threadIdx.y + i * 8;
        Wh[(size_t)n2 * Kd + k2] = __float2half_rn(t[threadIdx.x][threadIdx.y + i * 8]);
    }
}

// split qkv, rmsnorm(q,k)*scale, rope(q,k); q,k rounded fp16, v rounded (transposed)
__global__ void qkv_prep_k(const float* __restrict__ qkv_txt, const float* __restrict__ qkv_img,
                           const float* __restrict__ tq_s, const float* __restrict__ tk_s,
                           const float* __restrict__ iq_s, const float* __restrict__ ik_s,
                           const float* __restrict__ pe,
                           __half* __restrict__ qh, __half* __restrict__ kh,
                           __half* __restrict__ vth) {
    int h = blockIdx.x;
    int pos = blockIdx.y;
    int d = threadIdx.x;
    const float* src; int l; const float* qs; const float* ks;
    if (pos < Lt) { src = qkv_txt; l = pos;      qs = tq_s; ks = tk_s; }
    else          { src = qkv_img; l = pos - Lt; qs = iq_s; ks = ik_s; }
    const float* base = src + (size_t)l * (3 * DD) + h * HD;
    float qv = base[d];
    float kv = base[DD + d];
    float vv = base[2 * DD + d];

    __shared__ float sq[HD], sk[HD], red[8];
    float q2 = qv * qv, k2 = kv * kv;
#pragma unroll
    for (int o = 16; o > 0; o >>= 1) {
        q2 += __shfl_xor_sync(0xFFFFFFFFu, q2, o);
        k2 += __shfl_xor_sync(0xFFFFFFFFu, k2, o);
    }
    int w = d >> 5;
    if ((d & 31) == 0) { red[w] = q2; red[4 + w] = k2; }
    __syncthreads();
    float qss = red[0] + red[1] + red[2] + red[3];
    float kss = red[4] + red[5] + red[6] + red[7];
    float qn = qv * rsqrtf(qss * (1.0f / HD) + EPSF) * qs[d];
    float kn = kv * rsqrtf(kss * (1.0f / HD) + EPSF) * ks[d];
    sq[d] = qn; sk[d] = kn;
    __syncthreads();
    int i = d >> 1, j = d & 1;
    const float* pp = pe + (((size_t)pos * 64 + i) * 4 + j * 2);
    float p0 = pp[0], p1 = pp[1];
    float rq = p0 * sq[2 * i] + p1 * sq[2 * i + 1];
    float rk = p0 * sk[2 * i] + p1 * sk[2 * i + 1];
    size_t o = ((size_t)h * LL + pos) * HD + d;
    qh[o] = __float2half_rn(rq);
    kh[o] = __float2half_rn(rk);
    size_t ov = ((size_t)h * HD + d) * LL + pos;
    vth[ov] = __float2half_rn(vv);
}

// ================= fused flash attention =================
// Per CTA: one head, 128 Q rows. KV chunks of 64, double-buffered cp.async.
// Single-product: S = q̂·k̂, O += p̂·v̂ (all fp16-rounded operands, fp32 accum).
#define FCHUNK 64
#define NCHUNK (LL / FCHUNK)       // 36
#define F_QROW 272                 // 128 cols fp16 + 16B pad
#define F_QSZ  (128 * F_QROW)      // 34816
#define F_KROW 272
#define F_KSZ  (64 * F_KROW)       // 17408
#define F_VROW 144                 // 64 cols fp16 + 16B pad
#define F_VSZ  (128 * F_VROW)      // 18432
#define F_STG0 F_QSZ               // 34816
#define F_STGSZ (F_KSZ + F_VSZ)    // 35840
#define FLASH_SMEM (F_STG0 + 2 * F_STGSZ) // 106496

__global__ __launch_bounds__(256, 1) void flash_k(
    const __half* __restrict__ qhg, const __half* __restrict__ khg,
    const __half* __restrict__ vthg,
    __half* __restrict__ aoh) {
    extern __shared__ char smem[];
    uint32_t sb = smem_to_u32(smem);
    int tid = threadIdx.x, wid = tid >> 5, lane = tid & 31;
    int h = blockIdx.y, qt = blockIdx.x;
    const float iscale = 0.08838834764831845f; // 1/sqrt(128)

    // ---- load Q tile (once) ----
#pragma unroll
    for (int i = 0; i < 8; i++) {
        int u = tid + i * 256;          // 0..2047
        int row = u >> 4, cu = u & 15;
        size_t go = ((size_t)h * LL + qt * 128 + row) * HD + cu * 8;
        cpa16(sb + row * F_QROW + cu * 16, qhg + go);
    }
    CP_COMMIT();

    // ---- prefetch chunk 0 ----
    {
        uint32_t st = sb + F_STG0;
#pragma unroll
        for (int i = 0; i < 4; i++) {
            int u = tid + i * 256;      // 0..1023
            int row = u >> 4, cu = u & 15;
            size_t go = ((size_t)h * LL + row) * HD + cu * 8;
            cpa16(st + row * F_KROW + cu * 16, khg + go);
            int vr = u >> 3, vc = u & 7;
            size_t gv = ((size_t)h * HD + vr) * LL + vc * 8;
            cpa16(st + F_KSZ + vr * F_VROW + vc * 16, vthg + gv);
        }
        CP_COMMIT();
    }

    float o[16][4];
#pragma unroll
    for (int i = 0; i < 16; i++)
#pragma unroll
        for (int f = 0; f < 4; f++) o[i][f] = 0.0f;
    float m0 = -1e30f, m1 = -1e30f, l0 = 0.0f, l1 = 0.0f;

    uint32_t qa_base = sb + (wid * 16 + (lane & 15)) * F_QROW + ((lane >> 4) * 16);

    for (int j = 0; j < NCHUNK; j++) {
        CP_WAIT(0);
        __syncthreads();
        if (j + 1 < NCHUNK) {
            int ln = (j + 1) * FCHUNK;
            uint32_t st = sb + F_STG0 + ((j + 1) & 1) * F_STGSZ;
#pragma unroll
            for (int i = 0; i < 4; i++) {
                int u = tid + i * 256;
                int row = u >> 4, cu = u & 15;
                size_t go = ((size_t)h * LL + ln + row) * HD + cu * 8;
                cpa16(st + row * F_KROW + cu * 16, khg + go);
                int vr = u >> 3, vc = u & 7;
                size_t gv = ((size_t)h * HD + vr) * LL + ln + vc * 8;
                cpa16(st + F_KSZ + vr * F_VROW + vc * 16, vthg + gv);
            }
            CP_COMMIT();
        }

        uint32_t st = sb + F_STG0 + (j & 1) * F_STGSZ;

        // ---- S = Q @ K^T (single product) ----
        float S[8][4];
#pragma unroll
        for (int i = 0; i < 8; i++)
#pragma unroll
            for (int f = 0; f < 4; f++) S[i][f] = 0.0f;
#pragma unroll
        for (int kk = 0; kk < 8; kk++) {
            uint32_t aH[4], bArr[8][2];
            ldsm_x4(qa_base + kk * 32, aH);
#pragma unroll
            for (int ni = 0; ni < 8; ni++) {
                uint32_t ka = st + (ni * 8 + (lane & 7)) * F_KROW + ((lane >> 3) & 1) * 16 + kk * 32;
                ldsm_x2(ka, bArr[ni]);
            }
#pragma unroll
            for (int ni = 0; ni < 8; ni++) mma_fp16(S[ni], aH, bArr[ni]);
        }

        // ---- online softmax ----
        float rm0 = -1e30f, rm1 = -1e30f;
#pragma unroll
        for (int ni = 0; ni < 8; ni++) {
            rm0 = fmaxf(rm0, fmaxf(S[ni][0], S[ni][1]));
            rm1 = fmaxf(rm1, fmaxf(S[ni][2], S[ni][3]));
        }
        rm0 = fmaxf(rm0, __shfl_xor_sync(0xFFFFFFFFu, rm0, 1));
        rm0 = fmaxf(rm0, __shfl_xor_sync(0xFFFFFFFFu, rm0, 2));
        rm1 = fmaxf(rm1, __shfl_xor_sync(0xFFFFFFFFu, rm1, 1));
        rm1 = fmaxf(rm1, __shfl_xor_sync(0xFFFFFFFFu, rm1, 2));
        float mn0 = fmaxf(m0, rm0), mn1 = fmaxf(m1, rm1);
        float f0 = __expf((m0 - mn0) * iscale);
        float f1 = __expf((m1 - mn1) * iscale);
        m0 = mn0; m1 = mn1;
        float rs0 = 0.0f, rs1 = 0.0f;
#pragma unroll
        for (int ni = 0; ni < 8; ni++) {
            S[ni][0] = __expf((S[ni][0] - mn0) * iscale);
            S[ni][1] = __expf((S[ni][1] - mn0) * iscale);
            S[ni][2] = __expf((S[ni][2] - mn1) * iscale);
            S[ni][3] = __expf((S[ni][3] - mn1) * iscale);
            rs0 += S[ni][0] + S[ni][1];
            rs1 += S[ni][2] + S[ni][3];
        }
        rs0 += __shfl_xor_sync(0xFFFFFFFFu, rs0, 1);
        rs0 += __shfl_xor_sync(0xFFFFFFFFu, rs0, 2);
        rs1 += __shfl_xor_sync(0xFFFFFFFFu, rs1, 1);
        rs1 += __shfl_xor_sync(0xFFFFFFFFu, rs1, 2);
        l0 = l0 * f0 + rs0;
        l1 = l1 * f1 + rs1;
#pragma unroll
        for (int ni = 0; ni < 16; ni++) {
            o[ni][0] *= f0; o[ni][1] *= f0;
            o[ni][2] *= f1; o[ni][3] *= f1;
        }

        // ---- O += P @ V (single product) ----
#pragma unroll
        for (int kf = 0; kf < 4; kf++) {
            uint32_t pH[4];
            {
                float* c0 = S[2 * kf];
                float* c1 = S[2 * kf + 1];
                __half2 t;
                t = __floats2half2_rn(c0[0], c0[1]); pH[0] = *(uint32_t*)&t;
                t = __floats2half2_rn(c0[2], c0[3]); pH[1] = *(uint32_t*)&t;
                t = __floats2half2_rn(c1[0], c1[1]); pH[2] = *(uint32_t*)&t;
                t = __floats2half2_rn(c1[2], c1[3]); pH[3] = *(uint32_t*)&t;
            }
#pragma unroll
            for (int ni = 0; ni < 16; ni++) {
                uint32_t bH[2];
                uint32_t va = st + F_KSZ + (ni * 8 + (lane & 7)) * F_VROW +
                              ((lane >> 3) & 1) * 16 + kf * 32;
                ldsm_x2(va, bH);
                mma_fp16(o[ni], pH, bH);
            }
        }
        __syncthreads();
    }

    // ---- normalize + write out (fp16 rounded) ----
    float inv0 = 1.0f / l0, inv1 = 1.0f / l1;
    int row0 = qt * 128 + wid * 16 + (lane >> 2);
    int row1 = row0 + 8;
#pragma unroll
    for (int ni = 0; ni < 16; ni++) {
        int col = h * HD + ni * 8 + (lane & 3) * 2;
        __half2 h0 = __floats2half2_rn(o[ni][0] * inv0, o[ni][1] * inv0);
        __half2 h1 = __floats2half2_rn(o[ni][2] * inv1, o[ni][3] * inv1);
        *(__half2*)&aoh[(size_t)row0 * DD + col] = h0;
        *(__half2*)&aoh[(size_t)row1 * DD + col] = h1;
    }
}

// ================= paired HMMA GEMM (img rows + txt rows in ONE launch) =================
// blockIdx.y < yi -> set a (img); else set b (txt).
// C[M,N] = epi( A[M,K] @ B[N,K]^T ), fp16 operands, fp32 accum.
// CTA tile 128x128, BK=32. 8 warps (2x4), warp tile 64x32.
#define SROW 80
#define ARRB (128 * SROW)
#define STAGEB (2 * ARRB)
#define TGEMM_SMEM (2 * STAGEB)    // 40960

template <int EPI>
__global__ __launch_bounds__(256, 1) void tgemm2(
    const __half* __restrict__ Aa, const __half* __restrict__ Ba,
    float* __restrict__ Ca, __half* __restrict__ Cha,
    const float* __restrict__ ba, const float* __restrict__ ga, const float* __restrict__ ra,
    const __half* __restrict__ Ab, const __half* __restrict__ Bb,
    float* __restrict__ Cb, __half* __restrict__ Chb,
    const float* __restrict__ bb, const float* __restrict__ gb, const float* __restrict__ rb,
    int K, int lda, int ldb, int ldc, int ldres, float alpha, int yi) {
    extern __shared__ char smem[];
    uint32_t sb = smem_to_u32(smem);
    int tid = threadIdx.x, wid = tid >> 5, lane = tid & 31;
    int warpM = wid >> 2, warpN = wid & 3;
    int by = blockIdx.y;
    const __half* A; const __half* B; float* C; __half* Chi;
    const float* bias; const float* gate; const float* res;
    int m0;
    if (by < yi) { A = Aa; B = Ba; C = Ca; Chi = Cha; bias = ba; gate = ga; res = ra; m0 = by * 128; }
    else         { A = Ab; B = Bb; C = Cb; Chi = Chb; bias = bb; gate = gb; res = rb; m0 = (by - yi) * 128; }
    int n0 = blockIdx.x * 128;

    const __half* g0 = A + (size_t)m0 * lda;
    const __half* g2 = B + (size_t)n0 * ldb;

    int r0 = tid >> 2, q0 = tid & 3;
    int r1 = (tid + 256) >> 2, q1 = q0;
    uint32_t d00 = sb + r0 * SROW + q0 * 16;
    uint32_t d01 = sb + r1 * SROW + q1 * 16;

    float acc[4][4][4];
#pragma unroll
    for (int i = 0; i < 4; i++)
#pragma unroll
        for (int j = 0; j < 4; j++)
#pragma unroll
            for (int f = 0; f < 4; f++) acc[i][j][f] = 0.0f;

    int nit = K / 32;

    {
        cpa16(d00 + 0 * ARRB, g0 + (size_t)r0 * lda + q0 * 8);
        cpa16(d01 + 0 * ARRB, g0 + (size_t)r1 * lda + q1 * 8);
        cpa16(d00 + 1 * ARRB, g2 + (size_t)r0 * ldb + q0 * 8);
        cpa16(d01 + 1 * ARRB, g2 + (size_t)r1 * ldb + q1 * 8);
        CP_COMMIT();
    }

    uint32_t a_base = sb + (warpM * 64 + (lane & 15)) * SROW + ((lane >> 4) * 16);
    uint32_t b_base = sb + 1 * ARRB + (warpN * 32 + (lane & 7)) * SROW + (((lane >> 3) & 1) * 16);

    for (int it = 0; it < nit; it++) {
        bool pf = (it + 1) < nit;
        if (pf) {
            int k0 = (it + 1) * 32;
            uint32_t st = ((it + 1) & 1) * STAGEB;
            cpa16(d00 + st + 0 * ARRB, g0 + (size_t)r0 * lda + k0 + q0 * 8);
            cpa16(d01 + st + 0 * ARRB, g0 + (size_t)r1 * lda + k0 + q1 * 8);
            cpa16(d00 + st + 1 * ARRB, g2 + (size_t)r0 * ldb + k0 + q0 * 8);
            cpa16(d01 + st + 1 * ARRB, g2 + (size_t)r1 * ldb + k0 + q1 * 8);
            CP_COMMIT();
            CP_WAIT(1);
        } else {
            CP_WAIT(0);
        }
        __syncthreads();

        uint32_t st = (it & 1) * STAGEB;
        uint32_t ab = a_base + st;
        uint32_t bb2 = b_base + st;
#pragma unroll
        for (int kk = 0; kk < 2; kk++) {
            int kb = kk * 32;
            uint32_t ah[4][4], bh[4][2];
#pragma unroll
            for (int mi = 0; mi < 4; mi++)
                ldsm_x4(ab + mi * (16 * SROW) + kb, ah[mi]);
#pragma unroll
            for (int ni = 0; ni < 4; ni++)
                ldsm_x2(bb2 + ni * (8 * SROW) + kb, bh[ni]);
#pragma unroll
            for (int ni = 0; ni < 4; ni++)
#pragma unroll
                for (int mi = 0; mi < 4; mi++)
                    mma_fp16(acc[mi][ni], ah[mi], bh[ni]);
        }
        __syncthreads();
    }

    int rbase = m0 + warpM * 64 + (lane >> 2);
    int cbase = n0 + warpN * 32 + (lane & 3) * 2;
#pragma unroll
    for (int mi = 0; mi < 4; mi++) {
#pragma unroll
        for (int ni = 0; ni < 4; ni++) {
            int col = cbase + ni * 8;
#pragma unroll
            for (int hf = 0; hf < 2; hf++) {
                int row = rbase + mi * 16 + hf * 8;
                float v0 = acc[mi][ni][hf * 2 + 0];
                float v1 = acc[mi][ni][hf * 2 + 1];
                if (EPI == 0) {
                    float2 oo; oo.x = alpha * v0; oo.y = alpha * v1;
                    *(float2*)&C[(size_t)row * ldc + col] = oo;
                } else if (EPI == 2) {
                    float2 oo;
                    oo.x = res[(size_t)row * ldres + col + 0] + gate[col + 0] * (v0 + bias[col + 0]);
                    oo.y = res[(size_t)row * ldres + col + 1] + gate[col + 1] * (v1 + bias[col + 1]);
                    *(float2*)&C[(size_t)row * ldc + col] = oo;
                } else { // EPI 3: gelu -> fp16
                    float gg0 = gelu_tanh(v0 + bias[col]);
                    float gg1 = gelu_tanh(v1 + bias[col + 1]);
                    __half2 hp = __floats2half2_rn(gg0, gg1);
                    *(__half2*)&Chi[(size_t)row * ldc + col] = hp;
                }
            }
        }
    }
}

// ================= host side =================
#define SYMF(p, s) do { void* _t = nullptr; cudaGetSymbolAddress(&_t, s); (p) = (float*)_t; } while (0)
#define SYMH(p, s) do { void* _t = nullptr; cudaGetSymbolAddress(&_t, s); (p) = (__half*)_t; } while (0)

extern "C" void kernel_launch(void* const* d_in, const int* in_sizes, int n_in,
                              void* d_out, int out_size) {
    const float* img     = (const float*)d_in[0];
    const float* txt     = (const float*)d_in[1];
    const float* vec     = (const float*)d_in[2];
    const float* pe      = (const float*)d_in[3];
    const float* i_mod_w = (const float*)d_in[4];
    const float* i_mod_b = (const float*)d_in[5];
    const float* i_qkv_w = (const float*)d_in[6];
    const float* i_q_s   = (const float*)d_in[7];
    const float* i_k_s   = (const float*)d_in[8];
    const float* i_pw    = (const float*)d_in[9];
    const float* i_pb    = (const float*)d_in[10];
    const float* i_w1    = (const float*)d_in[11];
    const float* i_b1    = (const float*)d_in[12];
    const float* i_w2    = (const float*)d_in[13];
    const float* i_b2    = (const float*)d_in[14];
    const float* t_mod_w = (const float*)d_in[15];
    const float* t_mod_b = (const float*)d_in[16];
    const float* t_qkv_w = (const float*)d_in[17];
    const float* t_q_s   = (const float*)d_in[18];
    const float* t_k_s   = (const float*)d_in[19];
    const float* t_pw    = (const float*)d_in[20];
    const float* t_pb    = (const float*)d_in[21];
    const float* t_w1    = (const float*)d_in[22];
    const float* t_b1    = (const float*)d_in[23];
    const float* t_w2    = (const float*)d_in[24];
    const float* t_b2    = (const float*)d_in[25];

    float* out_img = (float*)d_out;
    float* out_txt = out_img + (size_t)Li * DD;

    float *sv, *mod_i, *mod_t, *qkv_i, *qkv_t, *res_i, *res_t;
    __half *mxi_h, *mxt_h, *wta, *wtb;
    __half *qh, *kh, *vth, *aoh, *hh, *ht, *mh, *mt;
    SYMF(sv, g_sv); SYMF(mod_i, g_mod_img); SYMF(mod_t, g_mod_txt);
    SYMF(qkv_i, g_qkv_img); SYMF(qkv_t, g_qkv_txt);
    SYMF(res_i, g_res_i); SYMF(res_t, g_res_t);
    SYMH(mxi_h, g_mxi_h); SYMH(mxt_h, g_mxt_h);
    SYMH(wta, g_wta); SYMH(wtb, g_wtb);
    SYMH(qh, g_qh); SYMH(kh, g_kh); SYMH(vth, g_vth);
    SYMH(aoh, g_aoh);
    SYMH(hh, g_hh); SYMH(ht, g_ht); SYMH(mh, g_mh); SYMH(mt, g_mt);

    cudaFuncSetAttribute(tgemm2<0>, cudaFuncAttributeMaxDynamicSharedMemorySize, TGEMM_SMEM);
    cudaFuncSetAttribute(tgemm2<2>, cudaFuncAttributeMaxDynamicSharedMemorySize, TGEMM_SMEM);
    cudaFuncSetAttribute(tgemm2<3>, cudaFuncAttributeMaxDynamicSharedMemorySize, TGEMM_SMEM);
    cudaFuncSetAttribute(flash_k, cudaFuncAttributeMaxDynamicSharedMemorySize, FLASH_SMEM);

    dim3 wcb(32, 8);
    const int YI = Li / 128;   // 16
    const int YT = Lt / 128;   // 2

    // 1. modulation
    silu_k<<<(DD + 255) / 256, 256>>>(vec, sv);
    modmul_k<<<6 * DD / 128, 128>>>(sv, i_mod_w, i_mod_b, mod_i);
    modmul_k<<<6 * DD / 128, 128>>>(sv, t_mod_w, t_mod_b, mod_t);

    // 2. LN1 + modulate -> fp16
    ln_mod_h_k<<<Li, 256>>>(img, mxi_h, mod_i + 0 * DD, mod_i + 1 * DD);
    ln_mod_h_k<<<Lt, 256>>>(txt, mxt_h, mod_t + 0 * DD, mod_t + 1 * DD);

    // 3. QKV GEMM (img+txt merged)
    wconv_k<<<dim3(3 * DD / 32, DD / 32), wcb>>>(i_qkv_w, wta, DD, 3 * DD);
    wconv_k<<<dim3(3 * DD / 32, DD / 32), wcb>>>(t_qkv_w, wtb, DD, 3 * DD);
    tgemm2<0><<<dim3(3 * DD / 128, YI + YT), 256, TGEMM_SMEM>>>(
        mxi_h, wta, qkv_i, nullptr, nullptr, nullptr, nullptr,
        mxt_h, wtb, qkv_t, nullptr, nullptr, nullptr, nullptr,
        DD, DD, DD, 3 * DD, 0, 1.0f, YI);

    // 4. split + rmsnorm + rope
    qkv_prep_k<<<dim3(HH, LL), HD>>>(qkv_t, qkv_i, t_q_s, t_k_s, i_q_s, i_k_s, pe,
                                     qh, kh, vth);

    // 5. fused flash attention -> aoh
    flash_k<<<dim3(LL / 128, HH), 256, FLASH_SMEM>>>(qh, kh, vth, aoh);

    // 6. proj + gated residual (merged)
    wconv_k<<<dim3(DD / 32, DD / 32), wcb>>>(i_pw, wta, DD, DD);
    wconv_k<<<dim3(DD / 32, DD / 32), wcb>>>(t_pw, wtb, DD, DD);
    tgemm2<2><<<dim3(DD / 128, YI + YT), 256, TGEMM_SMEM>>>(
        aoh + (size_t)Lt * DD, wta, res_i, nullptr, i_pb, mod_i + 2 * DD, img,
        aoh, wtb, res_t, nullptr, t_pb, mod_t + 2 * DD, txt,
        DD, DD, DD, DD, DD, 1.0f, YI);

    // 7. LN2 (both)
    ln_mod_h_k<<<Li, 256>>>(res_i, hh, mod_i + 3 * DD, mod_i + 4 * DD);
    ln_mod_h_k<<<Lt, 256>>>(res_t, ht, mod_t + 3 * DD, mod_t + 4 * DD);

    // 8. MLP1 (merged, gelu -> fp16)
    wconv_k<<<dim3(MLPD / 32, DD / 32), wcb>>>(i_w1, wta, DD, MLPD);
    wconv_k<<<dim3(MLPD / 32, DD / 32), wcb>>>(t_w1, wtb, DD, MLPD);
    tgemm2<3><<<dim3(MLPD / 128, YI + YT), 256, TGEMM_SMEM>>>(
        hh, wta, nullptr, mh, i_b1, nullptr, nullptr,
        ht, wtb, nullptr, mt, t_b1, nullptr, nullptr,
        DD, DD, DD, MLPD, 0, 1.0f, YI);

    // 9. MLP2 (merged, gated residual -> d_out)
    wconv_k<<<dim3(DD / 32, MLPD / 32), wcb>>>(i_w2, wta, MLPD, DD);
    wconv_k<<<dim3(DD / 32, MLPD / 32), wcb>>>(t_w2, wtb, MLPD, DD);
    tgemm2<2><<<dim3(DD / 128, YI + YT), 256, TGEMM_SMEM>>>(
        mh, wta, out_img, nullptr, i_b2, mod_i + 5 * DD, res_i,
        mt, wtb, out_txt, nullptr, t_b2, mod_t + 5 * DD, res_t,
        MLPD, MLPD, MLPD, DD, DD, 1.0f, YI);

    (void)in_sizes; (void)n_in; (void)out_size;
}

// round 14
// speedup vs baseline: 1.8940x; 1.1369x over previous
#include <cuda_runtime.h>
#include <cuda_fp16.h>
#include <math.h>
#include <stdint.h>

#define Lt 256
#define Li 2048
#define LL 2304          // Lt + Li
#define DD 2048
#define HH 16
#define HD 128
#define MLPD 8192
#define EPSF 1e-6f

// ================= helpers =================
__device__ __forceinline__ uint32_t smem_to_u32(const void* p) {
    uint32_t a;
    asm("{ .reg .u64 t; cvta.to.shared.u64 t, %1; cvt.u32.u64 %0, t; }" : "=r"(a) : "l"(p));
    return a;
}
__device__ __forceinline__ void cpa16(uint32_t dst, const void* src) {
    asm volatile("cp.async.cg.shared.global [%0], [%1], 16;" :: "r"(dst), "l"(src));
}
#define CP_COMMIT() asm volatile("cp.async.commit_group;" ::: "memory")
#define CP_WAIT(N)  asm volatile("cp.async.wait_group %0;" :: "n"(N) : "memory")

__device__ __forceinline__ void ldsm_x4(uint32_t addr, uint32_t* r) {
    asm volatile("ldmatrix.sync.aligned.m8n8.x4.shared.b16 {%0,%1,%2,%3}, [%4];"
                 : "=r"(r[0]), "=r"(r[1]), "=r"(r[2]), "=r"(r[3]) : "r"(addr));
}
__device__ __forceinline__ void ldsm_x2(uint32_t addr, uint32_t* r) {
    asm volatile("ldmatrix.sync.aligned.m8n8.x2.shared.b16 {%0,%1}, [%2];"
                 : "=r"(r[0]), "=r"(r[1]) : "r"(addr));
}
__device__ __forceinline__ void mma_fp16(float* d, const uint32_t* a, const uint32_t* b) {
    asm volatile(
        "mma.sync.aligned.m16n8k16.row.col.f32.f16.f16.f32 "
        "{%0,%1,%2,%3}, {%4,%5,%6,%7}, {%8,%9}, {%0,%1,%2,%3};"
        : "+f"(d[0]), "+f"(d[1]), "+f"(d[2]), "+f"(d[3])
        : "r"(a[0]), "r"(a[1]), "r"(a[2]), "r"(a[3]), "r"(b[0]), "r"(b[1]));
}

__device__ __forceinline__ float gelu_tanh(float x) {
    float x3 = x * x * x;
    return 0.5f * x * (1.0f + tanhf(0.7978845608028654f * (x + 0.044715f * x3)));
}

// ================= scratch (static device globals) =================
__device__ __align__(16) float g_sv[DD];
__device__ __align__(16) float g_mod_img[6 * DD];
__device__ __align__(16) float g_mod_txt[6 * DD];
__device__ __align__(16) __half g_mxi_h[Li * DD];
__device__ __align__(16) __half g_mxt_h[Lt * DD];
__device__ __align__(16) __half g_wta[MLPD * DD];    // img weight (transposed fp16)
__device__ __align__(16) __half g_wtb[MLPD * DD];    // txt weight (transposed fp16)
__device__ __align__(16) float g_qkv_img[Li * 3 * DD];
__device__ __align__(16) float g_qkv_txt[Lt * 3 * DD];
__device__ __align__(16) __half g_qh[HH * LL * HD];
__device__ __align__(16) __half g_kh[HH * LL * HD];
__device__ __align__(16) __half g_vth[HH * HD * LL]; // V transposed per head [H, HD, LL]
__device__ __align__(16) __half g_aoh[LL * DD];
__device__ __align__(16) float g_res_i[Li * DD];
__device__ __align__(16) float g_res_t[Lt * DD];
__device__ __align__(16) __half g_hh[Li * DD];
__device__ __align__(16) __half g_ht[Lt * DD];
__device__ __align__(16) __half g_mh[(size_t)Li * MLPD];
__device__ __align__(16) __half g_mt[(size_t)Lt * MLPD];

// ================= small kernels =================
__global__ void silu_k(const float* __restrict__ vec, float* __restrict__ sv) {
    int i = blockIdx.x * blockDim.x + threadIdx.x;
    if (i < DD) { float x = vec[i]; sv[i] = x / (1.0f + __expf(-x)); }
}

__global__ void modmul_k(const float* __restrict__ sv, const float* __restrict__ W,
                         const float* __restrict__ b, float* __restrict__ out) {
    __shared__ float s[DD];
    for (int i = threadIdx.x; i < DD; i += 128) s[i] = sv[i];
    __syncthreads();
    int j = blockIdx.x * 128 + threadIdx.x;
    float acc = 0.0f;
    const float* wp = W + j;
    for (int d = 0; d < DD; d++) acc += s[d] * wp[(size_t)d * (6 * DD)];
    out[j] = acc + b[j];
}

// merged dual-stream: rows [0, na) -> stream a; rows [na, na+nb) -> stream b
// y = round_fp16((1+sc)*LN(x) + sh)
__global__ void ln_mod2_k(const float* __restrict__ xa, __half* __restrict__ ya,
                          const float* __restrict__ sha, const float* __restrict__ sca,
                          const float* __restrict__ xb, __half* __restrict__ yb,
                          const float* __restrict__ shb, const float* __restrict__ scb,
                          int na) {
    int row = blockIdx.x;
    const float* x; __half* y; const float* sh; const float* sc;
    if (row < na) { x = xa; y = ya; sh = sha; sc = sca; }
    else          { x = xb; y = yb; sh = shb; sc = scb; row -= na; }
    const float* px = x + (size_t)row * DD;
    __shared__ float red[256];
    int tid = threadIdx.x;
    float v[8];
    float s = 0.0f;
#pragma unroll
    for (int i = 0; i < 8; i++) { v[i] = px[tid + i * 256]; s += v[i]; }
    red[tid] = s; __syncthreads();
    for (int o = 128; o > 0; o >>= 1) { if (tid < o) red[tid] += red[tid + o]; __syncthreads(); }
    float mu = red[0] * (1.0f / DD);
    __syncthreads();
    float ss = 0.0f;
#pragma unroll
    for (int i = 0; i < 8; i++) { float d = v[i] - mu; ss += d * d; }
    red[tid] = ss; __syncthreads();
    for (int o = 128; o > 0; o >>= 1) { if (tid < o) red[tid] += red[tid + o]; __syncthreads(); }
    float r = rsqrtf(red[0] * (1.0f / DD) + EPSF);
#pragma unroll
    for (int i = 0; i < 8; i++) {
        int c = tid + i * 256;
        float y2 = (1.0f + sc[c]) * ((v[i] - mu) * r) + sh[c];
        y[(size_t)row * DD + c] = __float2half_rn(y2);
    }
}

// dual transpose + round: blockIdx.z selects (Wa->Wha) or (Wb->Whb); W[K,N] fp32 -> Wt [N,K] fp16
__global__ void wconv2_k(const float* __restrict__ Wa, __half* __restrict__ Wha,
                         const float* __restrict__ Wb, __half* __restrict__ Whb,
                         int Kd, int Nd) {
    const float* W = blockIdx.z ? Wb : Wa;
    __half* Wh = blockIdx.z ? Whb : Wha;
    __shared__ float t[32][33];
    int n = blockIdx.x * 32 + threadIdx.x;
#pragma unroll
    for (int i = 0; i < 4; i++) {
        int k = blockIdx.y * 32 + threadIdx.y + i * 8;
        t[threadIdx.y + i * 8][threadIdx.x] = W[(size_t)k * Nd + n];
    }
    __syncthreads();
    int k2 = blockIdx.y * 32 + threadIdx.x;
#pragma unroll
    for (int i = 0; i < 4; i++) {
        int n2 = blockIdx.x * 32 + threadIdx.y + i * 8;
        Wh[(size_t)n2 * Kd + k2] = __float2half_rn(t[threadIdx.x][threadIdx.y + i * 8]);
    }
}

// split qkv, rmsnorm(q,k)*scale, rope(q,k); q,k rounded fp16, v rounded (transposed)
__global__ void qkv_prep_k(const float* __restrict__ qkv_txt, const float* __restrict__ qkv_img,
                           const float* __restrict__ tq_s, const float* __restrict__ tk_s,
                           const float* __restrict__ iq_s, const float* __restrict__ ik_s,
                           const float* __restrict__ pe,
                           __half* __restrict__ qh, __half* __restrict__ kh,
                           __half* __restrict__ vth) {
    int h = blockIdx.x;
    int pos = blockIdx.y;
    int d = threadIdx.x;
    const float* src; int l; const float* qs; const float* ks;
    if (pos < Lt) { src = qkv_txt; l = pos;      qs = tq_s; ks = tk_s; }
    else          { src = qkv_img; l = pos - Lt; qs = iq_s; ks = ik_s; }
    const float* base = src + (size_t)l * (3 * DD) + h * HD;
    float qv = base[d];
    float kv = base[DD + d];
    float vv = base[2 * DD + d];

    __shared__ float sq[HD], sk[HD], red[8];
    float q2 = qv * qv, k2 = kv * kv;
#pragma unroll
    for (int o = 16; o > 0; o >>= 1) {
        q2 += __shfl_xor_sync(0xFFFFFFFFu, q2, o);
        k2 += __shfl_xor_sync(0xFFFFFFFFu, k2, o);
    }
    int w = d >> 5;
    if ((d & 31) == 0) { red[w] = q2; red[4 + w] = k2; }
    __syncthreads();
    float qss = red[0] + red[1] + red[2] + red[3];
    float kss = red[4] + red[5] + red[6] + red[7];
    float qn = qv * rsqrtf(qss * (1.0f / HD) + EPSF) * qs[d];
    float kn = kv * rsqrtf(kss * (1.0f / HD) + EPSF) * ks[d];
    sq[d] = qn; sk[d] = kn;
    __syncthreads();
    int i = d >> 1, j = d & 1;
    const float* pp = pe + (((size_t)pos * 64 + i) * 4 + j * 2);
    float p0 = pp[0], p1 = pp[1];
    float rq = p0 * sq[2 * i] + p1 * sq[2 * i + 1];
    float rk = p0 * sk[2 * i] + p1 * sk[2 * i + 1];
    size_t o = ((size_t)h * LL + pos) * HD + d;
    qh[o] = __float2half_rn(rq);
    kh[o] = __float2half_rn(rk);
    size_t ov = ((size_t)h * HD + d) * LL + pos;
    vth[ov] = __float2half_rn(vv);
}

// ================= fused flash attention =================
// Per CTA: one head, 128 Q rows. KV chunks of 64, double-buffered cp.async.
// Single-product: S = q̂·k̂, O += p̂·v̂ (all fp16-rounded operands, fp32 accum).
#define FCHUNK 64
#define NCHUNK (LL / FCHUNK)       // 36
#define F_QROW 272                 // 128 cols fp16 + 16B pad
#define F_QSZ  (128 * F_QROW)      // 34816
#define F_KROW 272
#define F_KSZ  (64 * F_KROW)       // 17408
#define F_VROW 144                 // 64 cols fp16 + 16B pad
#define F_VSZ  (128 * F_VROW)      // 18432
#define F_STG0 F_QSZ               // 34816
#define F_STGSZ (F_KSZ + F_VSZ)    // 35840
#define FLASH_SMEM (F_STG0 + 2 * F_STGSZ) // 106496

__global__ __launch_bounds__(256, 1) void flash_k(
    const __half* __restrict__ qhg, const __half* __restrict__ khg,
    const __half* __restrict__ vthg,
    __half* __restrict__ aoh) {
    extern __shared__ char smem[];
    uint32_t sb = smem_to_u32(smem);
    int tid = threadIdx.x, wid = tid >> 5, lane = tid & 31;
    int h = blockIdx.y, qt = blockIdx.x;
    const float iscale = 0.08838834764831845f; // 1/sqrt(128)

    // ---- load Q tile (once) ----
#pragma unroll
    for (int i = 0; i < 8; i++) {
        int u = tid + i * 256;          // 0..2047
        int row = u >> 4, cu = u & 15;
        size_t go = ((size_t)h * LL + qt * 128 + row) * HD + cu * 8;
        cpa16(sb + row * F_QROW + cu * 16, qhg + go);
    }
    CP_COMMIT();

    // ---- prefetch chunk 0 ----
    {
        uint32_t st = sb + F_STG0;
#pragma unroll
        for (int i = 0; i < 4; i++) {
            int u = tid + i * 256;      // 0..1023
            int row = u >> 4, cu = u & 15;
            size_t go = ((size_t)h * LL + row) * HD + cu * 8;
            cpa16(st + row * F_KROW + cu * 16, khg + go);
            int vr = u >> 3, vc = u & 7;
            size_t gv = ((size_t)h * HD + vr) * LL + vc * 8;
            cpa16(st + F_KSZ + vr * F_VROW + vc * 16, vthg + gv);
        }
        CP_COMMIT();
    }

    float o[16][4];
#pragma unroll
    for (int i = 0; i < 16; i++)
#pragma unroll
        for (int f = 0; f < 4; f++) o[i][f] = 0.0f;
    float m0 = -1e30f, m1 = -1e30f, l0 = 0.0f, l1 = 0.0f;

    uint32_t qa_base = sb + (wid * 16 + (lane & 15)) * F_QROW + ((lane >> 4) * 16);

    for (int j = 0; j < NCHUNK; j++) {
        CP_WAIT(0);
        __syncthreads();
        if (j + 1 < NCHUNK) {
            int ln = (j + 1) * FCHUNK;
            uint32_t st = sb + F_STG0 + ((j + 1) & 1) * F_STGSZ;
#pragma unroll
            for (int i = 0; i < 4; i++) {
                int u = tid + i * 256;
                int row = u >> 4, cu = u & 15;
                size_t go = ((size_t)h * LL + ln + row) * HD + cu * 8;
                cpa16(st + row * F_KROW + cu * 16, khg + go);
                int vr = u >> 3, vc = u & 7;
                size_t gv = ((size_t)h * HD + vr) * LL + ln + vc * 8;
                cpa16(st + F_KSZ + vr * F_VROW + vc * 16, vthg + gv);
            }
            CP_COMMIT();
        }

        uint32_t st = sb + F_STG0 + (j & 1) * F_STGSZ;

        // ---- S = Q @ K^T (single product) ----
        float S[8][4];
#pragma unroll
        for (int i = 0; i < 8; i++)
#pragma unroll
            for (int f = 0; f < 4; f++) S[i][f] = 0.0f;
#pragma unroll
        for (int kk = 0; kk < 8; kk++) {
            uint32_t aH[4], bArr[8][2];
            ldsm_x4(qa_base + kk * 32, aH);
#pragma unroll
            for (int ni = 0; ni < 8; ni++) {
                uint32_t ka = st + (ni * 8 + (lane & 7)) * F_KROW + ((lane >> 3) & 1) * 16 + kk * 32;
                ldsm_x2(ka, bArr[ni]);
            }
#pragma unroll
            for (int ni = 0; ni < 8; ni++) mma_fp16(S[ni], aH, bArr[ni]);
        }

        // ---- online softmax ----
        float rm0 = -1e30f, rm1 = -1e30f;
#pragma unroll
        for (int ni = 0; ni < 8; ni++) {
            rm0 = fmaxf(rm0, fmaxf(S[ni][0], S[ni][1]));
            rm1 = fmaxf(rm1, fmaxf(S[ni][2], S[ni][3]));
        }
        rm0 = fmaxf(rm0, __shfl_xor_sync(0xFFFFFFFFu, rm0, 1));
        rm0 = fmaxf(rm0, __shfl_xor_sync(0xFFFFFFFFu, rm0, 2));
        rm1 = fmaxf(rm1, __shfl_xor_sync(0xFFFFFFFFu, rm1, 1));
        rm1 = fmaxf(rm1, __shfl_xor_sync(0xFFFFFFFFu, rm1, 2));
        float mn0 = fmaxf(m0, rm0), mn1 = fmaxf(m1, rm1);
        float f0 = __expf((m0 - mn0) * iscale);
        float f1 = __expf((m1 - mn1) * iscale);
        m0 = mn0; m1 = mn1;
        float rs0 = 0.0f, rs1 = 0.0f;
#pragma unroll
        for (int ni = 0; ni < 8; ni++) {
            S[ni][0] = __expf((S[ni][0] - mn0) * iscale);
            S[ni][1] = __expf((S[ni][1] - mn0) * iscale);
            S[ni][2] = __expf((S[ni][2] - mn1) * iscale);
            S[ni][3] = __expf((S[ni][3] - mn1) * iscale);
            rs0 += S[ni][0] + S[ni][1];
            rs1 += S[ni][2] + S[ni][3];
        }
        rs0 += __shfl_xor_sync(0xFFFFFFFFu, rs0, 1);
        rs0 += __shfl_xor_sync(0xFFFFFFFFu, rs0, 2);
        rs1 += __shfl_xor_sync(0xFFFFFFFFu, rs1, 1);
        rs1 += __shfl_xor_sync(0xFFFFFFFFu, rs1, 2);
        l0 = l0 * f0 + rs0;
        l1 = l1 * f1 + rs1;
#pragma unroll
        for (int ni = 0; ni < 16; ni++) {
            o[ni][0] *= f0; o[ni][1] *= f0;
            o[ni][2] *= f1; o[ni][3] *= f1;
        }

        // ---- O += P @ V (single product) ----
#pragma unroll
        for (int kf = 0; kf < 4; kf++) {
            uint32_t pH[4];
            {
                float* c0 = S[2 * kf];
                float* c1 = S[2 * kf + 1];
                __half2 t;
                t = __floats2half2_rn(c0[0], c0[1]); pH[0] = *(uint32_t*)&t;
                t = __floats2half2_rn(c0[2], c0[3]); pH[1] = *(uint32_t*)&t;
                t = __floats2half2_rn(c1[0], c1[1]); pH[2] = *(uint32_t*)&t;
                t = __floats2half2_rn(c1[2], c1[3]); pH[3] = *(uint32_t*)&t;
            }
#pragma unroll
            for (int ni = 0; ni < 16; ni++) {
                uint32_t bH[2];
                uint32_t va = st + F_KSZ + (ni * 8 + (lane & 7)) * F_VROW +
                              ((lane >> 3) & 1) * 16 + kf * 32;
                ldsm_x2(va, bH);
                mma_fp16(o[ni], pH, bH);
            }
        }
        __syncthreads();
    }

    // ---- normalize + write out (fp16 rounded) ----
    float inv0 = 1.0f / l0, inv1 = 1.0f / l1;
    int row0 = qt * 128 + wid * 16 + (lane >> 2);
    int row1 = row0 + 8;
#pragma unroll
    for (int ni = 0; ni < 16; ni++) {
        int col = h * HD + ni * 8 + (lane & 3) * 2;
        __half2 h0 = __floats2half2_rn(o[ni][0] * inv0, o[ni][1] * inv0);
        __half2 h1 = __floats2half2_rn(o[ni][2] * inv1, o[ni][3] * inv1);
        *(__half2*)&aoh[(size_t)row0 * DD + col] = h0;
        *(__half2*)&aoh[(size_t)row1 * DD + col] = h1;
    }
}

// ================= paired HMMA GEMM (img rows + txt rows in ONE launch) =================
// blockIdx.y < yi -> set a (img); else set b (txt). Occupancy 2 for latency hiding.
// C[M,N] = epi( A[M,K] @ B[N,K]^T ), fp16 operands, fp32 accum.
// CTA tile 128x128, BK=32. 8 warps (2x4), warp tile 64x32.
#define SROW 80
#define ARRB (128 * SROW)
#define STAGEB (2 * ARRB)
#define TGEMM_SMEM (2 * STAGEB)    // 40960

template <int EPI>
__global__ __launch_bounds__(256, 2) void tgemm2(
    const __half* __restrict__ Aa, const __half* __restrict__ Ba,
    float* __restrict__ Ca, __half* __restrict__ Cha,
    const float* __restrict__ ba, const float* __restrict__ ga, const float* __restrict__ ra,
    const __half* __restrict__ Ab, const __half* __restrict__ Bb,
    float* __restrict__ Cb, __half* __restrict__ Chb,
    const float* __restrict__ bb, const float* __restrict__ gb, const float* __restrict__ rb,
    int K, int lda, int ldb, int ldc, int ldres, float alpha, int yi) {
    extern __shared__ char smem[];
    uint32_t sb = smem_to_u32(smem);
    int tid = threadIdx.x, wid = tid >> 5, lane = tid & 31;
    int warpM = wid >> 2, warpN = wid & 3;
    int by = blockIdx.y;
    const __half* A; const __half* B; float* C; __half* Chi;
    const float* bias; const float* gate; const float* res;
    int m0;
    if (by < yi) { A = Aa; B = Ba; C = Ca; Chi = Cha; bias = ba; gate = ga; res = ra; m0 = by * 128; }
    else         { A = Ab; B = Bb; C = Cb; Chi = Chb; bias = bb; gate = gb; res = rb; m0 = (by - yi) * 128; }
    int n0 = blockIdx.x * 128;

    const __half* g0 = A + (size_t)m0 * lda;
    const __half* g2 = B + (size_t)n0 * ldb;

    int r0 = tid >> 2, q0 = tid & 3;
    int r1 = (tid + 256) >> 2, q1 = q0;
    uint32_t d00 = sb + r0 * SROW + q0 * 16;
    uint32_t d01 = sb + r1 * SROW + q1 * 16;

    float acc[4][4][4];
#pragma unroll
    for (int i = 0; i < 4; i++)
#pragma unroll
        for (int j = 0; j < 4; j++)
#pragma unroll
            for (int f = 0; f < 4; f++) acc[i][j][f] = 0.0f;

    int nit = K / 32;

    {
        cpa16(d00 + 0 * ARRB, g0 + (size_t)r0 * lda + q0 * 8);
        cpa16(d01 + 0 * ARRB, g0 + (size_t)r1 * lda + q1 * 8);
        cpa16(d00 + 1 * ARRB, g2 + (size_t)r0 * ldb + q0 * 8);
        cpa16(d01 + 1 * ARRB, g2 + (size_t)r1 * ldb + q1 * 8);
        CP_COMMIT();
    }

    uint32_t a_base = sb + (warpM * 64 + (lane & 15)) * SROW + ((lane >> 4) * 16);
    uint32_t b_base = sb + 1 * ARRB + (warpN * 32 + (lane & 7)) * SROW + (((lane >> 3) & 1) * 16);

    for (int it = 0; it < nit; it++) {
        bool pf = (it + 1) < nit;
        if (pf) {
            int k0 = (it + 1) * 32;
            uint32_t st = ((it + 1) & 1) * STAGEB;
            cpa16(d00 + st + 0 * ARRB, g0 + (size_t)r0 * lda + k0 + q0 * 8);
            cpa16(d01 + st + 0 * ARRB, g0 + (size_t)r1 * lda + k0 + q1 * 8);
            cpa16(d00 + st + 1 * ARRB, g2 + (size_t)r0 * ldb + k0 + q0 * 8);
            cpa16(d01 + st + 1 * ARRB, g2 + (size_t)r1 * ldb + k0 + q1 * 8);
            CP_COMMIT();
            CP_WAIT(1);
        } else {
            CP_WAIT(0);
        }
        __syncthreads();

        uint32_t st = (it & 1) * STAGEB;
        uint32_t ab = a_base + st;
        uint32_t bb2 = b_base + st;
#pragma unroll
        for (int kk = 0; kk < 2; kk++) {
            int kb = kk * 32;
            uint32_t ah[4][4], bh[4][2];
#pragma unroll
            for (int mi = 0; mi < 4; mi++)
                ldsm_x4(ab + mi * (16 * SROW) + kb, ah[mi]);
#pragma unroll
            for (int ni = 0; ni < 4; ni++)
                ldsm_x2(bb2 + ni * (8 * SROW) + kb, bh[ni]);
#pragma unroll
            for (int ni = 0; ni < 4; ni++)
#pragma unroll
                for (int mi = 0; mi < 4; mi++)
                    mma_fp16(acc[mi][ni], ah[mi], bh[ni]);
        }
        __syncthreads();
    }

    int rbase = m0 + warpM * 64 + (lane >> 2);
    int cbase = n0 + warpN * 32 + (lane & 3) * 2;
#pragma unroll
    for (int mi = 0; mi < 4; mi++) {
#pragma unroll
        for (int ni = 0; ni < 4; ni++) {
            int col = cbase + ni * 8;
#pragma unroll
            for (int hf = 0; hf < 2; hf++) {
                int row = rbase + mi * 16 + hf * 8;
                float v0 = acc[mi][ni][hf * 2 + 0];
                float v1 = acc[mi][ni][hf * 2 + 1];
                if (EPI == 0) {
                    float2 oo; oo.x = alpha * v0; oo.y = alpha * v1;
                    *(float2*)&C[(size_t)row * ldc + col] = oo;
                } else if (EPI == 2) {
                    float2 oo;
                    oo.x = res[(size_t)row * ldres + col + 0] + gate[col + 0] * (v0 + bias[col + 0]);
                    oo.y = res[(size_t)row * ldres + col + 1] + gate[col + 1] * (v1 + bias[col + 1]);
                    *(float2*)&C[(size_t)row * ldc + col] = oo;
                } else { // EPI 3: gelu -> fp16
                    float gg0 = gelu_tanh(v0 + bias[col]);
                    float gg1 = gelu_tanh(v1 + bias[col + 1]);
                    __half2 hp = __floats2half2_rn(gg0, gg1);
                    *(__half2*)&Chi[(size_t)row * ldc + col] = hp;
                }
            }
        }
    }
}

// ================= host side =================
#define SYMF(p, s) do { void* _t = nullptr; cudaGetSymbolAddress(&_t, s); (p) = (float*)_t; } while (0)
#define SYMH(p, s) do { void* _t = nullptr; cudaGetSymbolAddress(&_t, s); (p) = (__half*)_t; } while (0)

extern "C" void kernel_launch(void* const* d_in, const int* in_sizes, int n_in,
                              void* d_out, int out_size) {
    const float* img     = (const float*)d_in[0];
    const float* txt     = (const float*)d_in[1];
    const float* vec     = (const float*)d_in[2];
    const float* pe      = (const float*)d_in[3];
    const float* i_mod_w = (const float*)d_in[4];
    const float* i_mod_b = (const float*)d_in[5];
    const float* i_qkv_w = (const float*)d_in[6];
    const float* i_q_s   = (const float*)d_in[7];
    const float* i_k_s   = (const float*)d_in[8];
    const float* i_pw    = (const float*)d_in[9];
    const float* i_pb    = (const float*)d_in[10];
    const float* i_w1    = (const float*)d_in[11];
    const float* i_b1    = (const float*)d_in[12];
    const float* i_w2    = (const float*)d_in[13];
    const float* i_b2    = (const float*)d_in[14];
    const float* t_mod_w = (const float*)d_in[15];
    const float* t_mod_b = (const float*)d_in[16];
    const float* t_qkv_w = (const float*)d_in[17];
    const float* t_q_s   = (const float*)d_in[18];
    const float* t_k_s   = (const float*)d_in[19];
    const float* t_pw    = (const float*)d_in[20];
    const float* t_pb    = (const float*)d_in[21];
    const float* t_w1    = (const float*)d_in[22];
    const float* t_b1    = (const float*)d_in[23];
    const float* t_w2    = (const float*)d_in[24];
    const float* t_b2    = (const float*)d_in[25];

    float* out_img = (float*)d_out;
    float* out_txt = out_img + (size_t)Li * DD;

    float *sv, *mod_i, *mod_t, *qkv_i, *qkv_t, *res_i, *res_t;
    __half *mxi_h, *mxt_h, *wta, *wtb;
    __half *qh, *kh, *vth, *aoh, *hh, *ht, *mh, *mt;
    SYMF(sv, g_sv); SYMF(mod_i, g_mod_img); SYMF(mod_t, g_mod_txt);
    SYMF(qkv_i, g_qkv_img); SYMF(qkv_t, g_qkv_txt);
    SYMF(res_i, g_res_i); SYMF(res_t, g_res_t);
    SYMH(mxi_h, g_mxi_h); SYMH(mxt_h, g_mxt_h);
    SYMH(wta, g_wta); SYMH(wtb, g_wtb);
    SYMH(qh, g_qh); SYMH(kh, g_kh); SYMH(vth, g_vth);
    SYMH(aoh, g_aoh);
    SYMH(hh, g_hh); SYMH(ht, g_ht); SYMH(mh, g_mh); SYMH(mt, g_mt);

    cudaFuncSetAttribute(tgemm2<0>, cudaFuncAttributeMaxDynamicSharedMemorySize, TGEMM_SMEM);
    cudaFuncSetAttribute(tgemm2<2>, cudaFuncAttributeMaxDynamicSharedMemorySize, TGEMM_SMEM);
    cudaFuncSetAttribute(tgemm2<3>, cudaFuncAttributeMaxDynamicSharedMemorySize, TGEMM_SMEM);
    cudaFuncSetAttribute(flash_k, cudaFuncAttributeMaxDynamicSharedMemorySize, FLASH_SMEM);

    dim3 wcb(32, 8);
    const int YI = Li / 128;   // 16
    const int YT = Lt / 128;   // 2

    // 1. modulation
    silu_k<<<(DD + 255) / 256, 256>>>(vec, sv);
    modmul_k<<<6 * DD / 128, 128>>>(sv, i_mod_w, i_mod_b, mod_i);
    modmul_k<<<6 * DD / 128, 128>>>(sv, t_mod_w, t_mod_b, mod_t);

    // 2. LN1 + modulate -> fp16 (merged img+txt)
    ln_mod2_k<<<Li + Lt, 256>>>(img, mxi_h, mod_i + 0 * DD, mod_i + 1 * DD,
                                txt, mxt_h, mod_t + 0 * DD, mod_t + 1 * DD, Li);

    // 3. QKV GEMM (img+txt merged)
    wconv2_k<<<dim3(3 * DD / 32, DD / 32, 2), wcb>>>(i_qkv_w, wta, t_qkv_w, wtb, DD, 3 * DD);
    tgemm2<0><<<dim3(3 * DD / 128, YI + YT), 256, TGEMM_SMEM>>>(
        mxi_h, wta, qkv_i, nullptr, nullptr, nullptr, nullptr,
        mxt_h, wtb, qkv_t, nullptr, nullptr, nullptr, nullptr,
        DD, DD, DD, 3 * DD, 0, 1.0f, YI);

    // 4. split + rmsnorm + rope
    qkv_prep_k<<<dim3(HH, LL), HD>>>(qkv_t, qkv_i, t_q_s, t_k_s, i_q_s, i_k_s, pe,
                                     qh, kh, vth);

    // 5. fused flash attention -> aoh
    flash_k<<<dim3(LL / 128, HH), 256, FLASH_SMEM>>>(qh, kh, vth, aoh);

    // 6. proj + gated residual (merged)
    wconv2_k<<<dim3(DD / 32, DD / 32, 2), wcb>>>(i_pw, wta, t_pw, wtb, DD, DD);
    tgemm2<2><<<dim3(DD / 128, YI + YT), 256, TGEMM_SMEM>>>(
        aoh + (size_t)Lt * DD, wta, res_i, nullptr, i_pb, mod_i + 2 * DD, img,
        aoh, wtb, res_t, nullptr, t_pb, mod_t + 2 * DD, txt,
        DD, DD, DD, DD, DD, 1.0f, YI);

    // 7. LN2 (merged)
    ln_mod2_k<<<Li + Lt, 256>>>(res_i, hh, mod_i + 3 * DD, mod_i + 4 * DD,
                                res_t, ht, mod_t + 3 * DD, mod_t + 4 * DD, Li);

    // 8. MLP1 (merged, gelu -> fp16)
    wconv2_k<<<dim3(MLPD / 32, DD / 32, 2), wcb>>>(i_w1, wta, t_w1, wtb, DD, MLPD);
    tgemm2<3><<<dim3(MLPD / 128, YI + YT), 256, TGEMM_SMEM>>>(
        hh, wta, nullptr, mh, i_b1, nullptr, nullptr,
        ht, wtb, nullptr, mt, t_b1, nullptr, nullptr,
        DD, DD, DD, MLPD, 0, 1.0f, YI);

    // 9. MLP2 (merged, gated residual -> d_out)
    wconv2_k<<<dim3(DD / 32, MLPD / 32, 2), wcb>>>(i_w2, wta, t_w2, wtb, MLPD, DD);
    tgemm2<2><<<dim3(DD / 128, YI + YT), 256, TGEMM_SMEM>>>(
        mh, wta, out_img, nullptr, i_b2, mod_i + 5 * DD, res_i,
        mt, wtb, out_txt, nullptr, t_b2, mod_t + 5 * DD, res_t,
        MLPD, MLPD, MLPD, DD, DD, 1.0f, YI);

    (void)in_sizes; (void)n_in; (void)out_size;
}

// round 15
// speedup vs baseline: 2.0445x; 1.0795x over previous
#include <cuda_runtime.h>
#include <cuda_fp16.h>
#include <math.h>
#include <stdint.h>

#define Lt 256
#define Li 2048
#define LL 2304          // Lt + Li
#define DD 2048
#define HH 16
#define HD 128
#define MLPD 8192
#define EPSF 1e-6f

// ================= helpers =================
__device__ __forceinline__ uint32_t smem_to_u32(const void* p) {
    uint32_t a;
    asm("{ .reg .u64 t; cvta.to.shared.u64 t, %1; cvt.u32.u64 %0, t; }" : "=r"(a) : "l"(p));
    return a;
}
__device__ __forceinline__ void cpa16(uint32_t dst, const void* src) {
    asm volatile("cp.async.cg.shared.global [%0], [%1], 16;" :: "r"(dst), "l"(src));
}
#define CP_COMMIT() asm volatile("cp.async.commit_group;" ::: "memory")
#define CP_WAIT(N)  asm volatile("cp.async.wait_group %0;" :: "n"(N) : "memory")

__device__ __forceinline__ void ldsm_x4(uint32_t addr, uint32_t* r) {
    asm volatile("ldmatrix.sync.aligned.m8n8.x4.shared.b16 {%0,%1,%2,%3}, [%4];"
                 : "=r"(r[0]), "=r"(r[1]), "=r"(r[2]), "=r"(r[3]) : "r"(addr));
}
__device__ __forceinline__ void ldsm_x2(uint32_t addr, uint32_t* r) {
    asm volatile("ldmatrix.sync.aligned.m8n8.x2.shared.b16 {%0,%1}, [%2];"
                 : "=r"(r[0]), "=r"(r[1]) : "r"(addr));
}
__device__ __forceinline__ void mma_fp16(float* d, const uint32_t* a, const uint32_t* b) {
    asm volatile(
        "mma.sync.aligned.m16n8k16.row.col.f32.f16.f16.f32 "
        "{%0,%1,%2,%3}, {%4,%5,%6,%7}, {%8,%9}, {%0,%1,%2,%3};"
        : "+f"(d[0]), "+f"(d[1]), "+f"(d[2]), "+f"(d[3])
        : "r"(a[0]), "r"(a[1]), "r"(a[2]), "r"(a[3]), "r"(b[0]), "r"(b[1]));
}

__device__ __forceinline__ float gelu_tanh(float x) {
    float x3 = x * x * x;
    return 0.5f * x * (1.0f + tanhf(0.7978845608028654f * (x + 0.044715f * x3)));
}

// ================= scratch (static device globals) =================
__device__ __align__(16) float g_mod_img[6 * DD];
__device__ __align__(16) float g_mod_txt[6 * DD];
__device__ __align__(16) __half g_mxi_h[Li * DD];
__device__ __align__(16) __half g_mxt_h[Lt * DD];
// dedicated transposed fp16 weight buffers (converted once per call in one launch)
__device__ __align__(16) __half g_w_qkv_i[(size_t)3 * DD * DD];
__device__ __align__(16) __half g_w_qkv_t[(size_t)3 * DD * DD];
__device__ __align__(16) __half g_w_p_i[(size_t)DD * DD];
__device__ __align__(16) __half g_w_p_t[(size_t)DD * DD];
__device__ __align__(16) __half g_w_1_i[(size_t)MLPD * DD];
__device__ __align__(16) __half g_w_1_t[(size_t)MLPD * DD];
__device__ __align__(16) __half g_w_2_i[(size_t)DD * MLPD];
__device__ __align__(16) __half g_w_2_t[(size_t)DD * MLPD];
__device__ __align__(16) float g_qkv_img[Li * 3 * DD];
__device__ __align__(16) float g_qkv_txt[Lt * 3 * DD];
__device__ __align__(16) __half g_qh[HH * LL * HD];
__device__ __align__(16) __half g_kh[HH * LL * HD];
__device__ __align__(16) __half g_vth[HH * HD * LL]; // V transposed per head [H, HD, LL]
__device__ __align__(16) __half g_aoh[LL * DD];
__device__ __align__(16) float g_res_i[Li * DD];
__device__ __align__(16) float g_res_t[Lt * DD];
__device__ __align__(16) __half g_hh[Li * DD];
__device__ __align__(16) __half g_ht[Lt * DD];
__device__ __align__(16) __half g_mh[(size_t)Li * MLPD];
__device__ __align__(16) __half g_mt[(size_t)Lt * MLPD];

// ================= small kernels =================
// merged silu + both modulation GEMVs: blocks [0,96) img, [96,192) txt
__global__ void modmul2_k(const float* __restrict__ vec,
                          const float* __restrict__ Wi, const float* __restrict__ bi,
                          float* __restrict__ outi,
                          const float* __restrict__ Wt, const float* __restrict__ bt,
                          float* __restrict__ outt) {
    __shared__ float s[DD];
    int tid = threadIdx.x;
    for (int i = tid; i < DD; i += 128) { float x = vec[i]; s[i] = x / (1.0f + __expf(-x)); }
    __syncthreads();
    const float* W; const float* bb; float* out; int j;
    if (blockIdx.x < 96) { W = Wi; bb = bi; out = outi; j = blockIdx.x * 128 + tid; }
    else                 { W = Wt; bb = bt; out = outt; j = (blockIdx.x - 96) * 128 + tid; }
    float acc = 0.0f;
    const float* wp = W + j;
    for (int d = 0; d < DD; d++) acc += s[d] * wp[(size_t)d * (6 * DD)];
    out[j] = acc + bb[j];
}

// merged dual-stream LN: rows [0, na) -> stream a; rows [na, ..) -> stream b
__global__ void ln_mod2_k(const float* __restrict__ xa, __half* __restrict__ ya,
                          const float* __restrict__ sha, const float* __restrict__ sca,
                          const float* __restrict__ xb, __half* __restrict__ yb,
                          const float* __restrict__ shb, const float* __restrict__ scb,
                          int na) {
    int row = blockIdx.x;
    const float* x; __half* y; const float* sh; const float* sc;
    if (row < na) { x = xa; y = ya; sh = sha; sc = sca; }
    else          { x = xb; y = yb; sh = shb; sc = scb; row -= na; }
    const float* px = x + (size_t)row * DD;
    __shared__ float red[256];
    int tid = threadIdx.x;
    float v[8];
    float s = 0.0f;
#pragma unroll
    for (int i = 0; i < 8; i++) { v[i] = px[tid + i * 256]; s += v[i]; }
    red[tid] = s; __syncthreads();
    for (int o = 128; o > 0; o >>= 1) { if (tid < o) red[tid] += red[tid + o]; __syncthreads(); }
    float mu = red[0] * (1.0f / DD);
    __syncthreads();
    float ss = 0.0f;
#pragma unroll
    for (int i = 0; i < 8; i++) { float d = v[i] - mu; ss += d * d; }
    red[tid] = ss; __syncthreads();
    for (int o = 128; o > 0; o >>= 1) { if (tid < o) red[tid] += red[tid + o]; __syncthreads(); }
    float r = rsqrtf(red[0] * (1.0f / DD) + EPSF);
#pragma unroll
    for (int i = 0; i < 8; i++) {
        int c = tid + i * 256;
        float y2 = (1.0f + sc[c]) * ((v[i] - mu) * r) + sh[c];
        y[(size_t)row * DD + c] = __float2half_rn(y2);
    }
}

// ======= ALL weight conversions in ONE launch =======
// Transpose + round 8 matrices; 1-D grid over 32x32 tiles, segment decode by range.
#define T_QKV 12288     // (6144/32)*(2048/32)
#define T_P   4096      // 64*64
#define T_W1  16384     // (8192/32)*(2048/32)
#define T_W2  16384     // (2048/32)*(8192/32)
#define T_TOTAL (2 * T_QKV + 2 * T_P + 2 * T_W1 + 2 * T_W2)   // 98304

__global__ void wconv_all_k(
    const float* __restrict__ iqkv, const float* __restrict__ tqkv,
    const float* __restrict__ ipw,  const float* __restrict__ tpw,
    const float* __restrict__ iw1,  const float* __restrict__ tw1,
    const float* __restrict__ iw2,  const float* __restrict__ tw2,
    __half* __restrict__ d_iqkv, __half* __restrict__ d_tqkv,
    __half* __restrict__ d_ipw,  __half* __restrict__ d_tpw,
    __half* __restrict__ d_iw1,  __half* __restrict__ d_tw1,
    __half* __restrict__ d_iw2,  __half* __restrict__ d_tw2) {
    int b = blockIdx.x;
    const float* W; __half* Wh; int Kd, Nd, lx;
    if (b < 2 * T_QKV) {
        Kd = DD; Nd = 3 * DD;
        if (b < T_QKV) { W = iqkv; Wh = d_iqkv; lx = b; }
        else           { W = tqkv; Wh = d_tqkv; lx = b - T_QKV; }
    } else if (b < 2 * T_QKV + 2 * T_P) {
        int c = b - 2 * T_QKV; Kd = DD; Nd = DD;
        if (c < T_P) { W = ipw; Wh = d_ipw; lx = c; }
        else         { W = tpw; Wh = d_tpw; lx = c - T_P; }
    } else if (b < 2 * T_QKV + 2 * T_P + 2 * T_W1) {
        int c = b - 2 * T_QKV - 2 * T_P; Kd = DD; Nd = MLPD;
        if (c < T_W1) { W = iw1; Wh = d_iw1; lx = c; }
        else          { W = tw1; Wh = d_tw1; lx = c - T_W1; }
    } else {
        int c = b - 2 * T_QKV - 2 * T_P - 2 * T_W1; Kd = MLPD; Nd = DD;
        if (c < T_W2) { W = iw2; Wh = d_iw2; lx = c; }
        else          { W = tw2; Wh = d_tw2; lx = c - T_W2; }
    }
    int xw = Nd / 32;
    int bx = lx % xw, by = lx / xw;

    __shared__ float t[32][33];
    int n = bx * 32 + threadIdx.x;
#pragma unroll
    for (int i = 0; i < 4; i++) {
        int k = by * 32 + threadIdx.y + i * 8;
        t[threadIdx.y + i * 8][threadIdx.x] = W[(size_t)k * Nd + n];
    }
    __syncthreads();
    int k2 = by * 32 + threadIdx.x;
#pragma unroll
    for (int i = 0; i < 4; i++) {
        int n2 = bx * 32 + threadIdx.y + i * 8;
        Wh[(size_t)n2 * Kd + k2] = __float2half_rn(t[threadIdx.x][threadIdx.y + i * 8]);
    }
}

// split qkv, rmsnorm(q,k)*scale, rope(q,k); q,k,v rounded fp16 (v transposed)
__global__ void qkv_prep_k(const float* __restrict__ qkv_txt, const float* __restrict__ qkv_img,
                           const float* __restrict__ tq_s, const float* __restrict__ tk_s,
                           const float* __restrict__ iq_s, const float* __restrict__ ik_s,
                           const float* __restrict__ pe,
                           __half* __restrict__ qh, __half* __restrict__ kh,
                           __half* __restrict__ vth) {
    int h = blockIdx.x;
    int pos = blockIdx.y;
    int d = threadIdx.x;
    const float* src; int l; const float* qs; const float* ks;
    if (pos < Lt) { src = qkv_txt; l = pos;      qs = tq_s; ks = tk_s; }
    else          { src = qkv_img; l = pos - Lt; qs = iq_s; ks = ik_s; }
    const float* base = src + (size_t)l * (3 * DD) + h * HD;
    float qv = base[d];
    float kv = base[DD + d];
    float vv = base[2 * DD + d];

    __shared__ float sq[HD], sk[HD], red[8];
    float q2 = qv * qv, k2 = kv * kv;
#pragma unroll
    for (int o = 16; o > 0; o >>= 1) {
        q2 += __shfl_xor_sync(0xFFFFFFFFu, q2, o);
        k2 += __shfl_xor_sync(0xFFFFFFFFu, k2, o);
    }
    int w = d >> 5;
    if ((d & 31) == 0) { red[w] = q2; red[4 + w] = k2; }
    __syncthreads();
    float qss = red[0] + red[1] + red[2] + red[3];
    float kss = red[4] + red[5] + red[6] + red[7];
    float qn = qv * rsqrtf(qss * (1.0f / HD) + EPSF) * qs[d];
    float kn = kv * rsqrtf(kss * (1.0f / HD) + EPSF) * ks[d];
    sq[d] = qn; sk[d] = kn;
    __syncthreads();
    int i = d >> 1, j = d & 1;
    const float* pp = pe + (((size_t)pos * 64 + i) * 4 + j * 2);
    float p0 = pp[0], p1 = pp[1];
    float rq = p0 * sq[2 * i] + p1 * sq[2 * i + 1];
    float rk = p0 * sk[2 * i] + p1 * sk[2 * i + 1];
    size_t o = ((size_t)h * LL + pos) * HD + d;
    qh[o] = __float2half_rn(rq);
    kh[o] = __float2half_rn(rk);
    size_t ov = ((size_t)h * HD + d) * LL + pos;
    vth[ov] = __float2half_rn(vv);
}

// ================= fused flash attention =================
#define FCHUNK 64
#define NCHUNK (LL / FCHUNK)       // 36
#define F_QROW 272
#define F_QSZ  (128 * F_QROW)      // 34816
#define F_KROW 272
#define F_KSZ  (64 * F_KROW)       // 17408
#define F_VROW 144
#define F_VSZ  (128 * F_VROW)      // 18432
#define F_STG0 F_QSZ
#define F_STGSZ (F_KSZ + F_VSZ)    // 35840
#define FLASH_SMEM (F_STG0 + 2 * F_STGSZ) // 106496

__global__ __launch_bounds__(256, 1) void flash_k(
    const __half* __restrict__ qhg, const __half* __restrict__ khg,
    const __half* __restrict__ vthg,
    __half* __restrict__ aoh) {
    extern __shared__ char smem[];
    uint32_t sb = smem_to_u32(smem);
    int tid = threadIdx.x, wid = tid >> 5, lane = tid & 31;
    int h = blockIdx.y, qt = blockIdx.x;
    const float iscale = 0.08838834764831845f; // 1/sqrt(128)

#pragma unroll
    for (int i = 0; i < 8; i++) {
        int u = tid + i * 256;
        int row = u >> 4, cu = u & 15;
        size_t go = ((size_t)h * LL + qt * 128 + row) * HD + cu * 8;
        cpa16(sb + row * F_QROW + cu * 16, qhg + go);
    }
    CP_COMMIT();

    {
        uint32_t st = sb + F_STG0;
#pragma unroll
        for (int i = 0; i < 4; i++) {
            int u = tid + i * 256;
            int row = u >> 4, cu = u & 15;
            size_t go = ((size_t)h * LL + row) * HD + cu * 8;
            cpa16(st + row * F_KROW + cu * 16, khg + go);
            int vr = u >> 3, vc = u & 7;
            size_t gv = ((size_t)h * HD + vr) * LL + vc * 8;
            cpa16(st + F_KSZ + vr * F_VROW + vc * 16, vthg + gv);
        }
        CP_COMMIT();
    }

    float o[16][4];
#pragma unroll
    for (int i = 0; i < 16; i++)
#pragma unroll
        for (int f = 0; f < 4; f++) o[i][f] = 0.0f;
    float m0 = -1e30f, m1 = -1e30f, l0 = 0.0f, l1 = 0.0f;

    uint32_t qa_base = sb + (wid * 16 + (lane & 15)) * F_QROW + ((lane >> 4) * 16);

    for (int j = 0; j < NCHUNK; j++) {
        CP_WAIT(0);
        __syncthreads();
        if (j + 1 < NCHUNK) {
            int ln = (j + 1) * FCHUNK;
            uint32_t st = sb + F_STG0 + ((j + 1) & 1) * F_STGSZ;
#pragma unroll
            for (int i = 0; i < 4; i++) {
                int u = tid + i * 256;
                int row = u >> 4, cu = u & 15;
                size_t go = ((size_t)h * LL + ln + row) * HD + cu * 8;
                cpa16(st + row * F_KROW + cu * 16, khg + go);
                int vr = u >> 3, vc = u & 7;
                size_t gv = ((size_t)h * HD + vr) * LL + ln + vc * 8;
                cpa16(st + F_KSZ + vr * F_VROW + vc * 16, vthg + gv);
            }
            CP_COMMIT();
        }

        uint32_t st = sb + F_STG0 + (j & 1) * F_STGSZ;

        float S[8][4];
#pragma unroll
        for (int i = 0; i < 8; i++)
#pragma unroll
            for (int f = 0; f < 4; f++) S[i][f] = 0.0f;
#pragma unroll
        for (int kk = 0; kk < 8; kk++) {
            uint32_t aH[4], bArr[8][2];
            ldsm_x4(qa_base + kk * 32, aH);
#pragma unroll
            for (int ni = 0; ni < 8; ni++) {
                uint32_t ka = st + (ni * 8 + (lane & 7)) * F_KROW + ((lane >> 3) & 1) * 16 + kk * 32;
                ldsm_x2(ka, bArr[ni]);
            }
#pragma unroll
            for (int ni = 0; ni < 8; ni++) mma_fp16(S[ni], aH, bArr[ni]);
        }

        float rm0 = -1e30f, rm1 = -1e30f;
#pragma unroll
        for (int ni = 0; ni < 8; ni++) {
            rm0 = fmaxf(rm0, fmaxf(S[ni][0], S[ni][1]));
            rm1 = fmaxf(rm1, fmaxf(S[ni][2], S[ni][3]));
        }
        rm0 = fmaxf(rm0, __shfl_xor_sync(0xFFFFFFFFu, rm0, 1));
        rm0 = fmaxf(rm0, __shfl_xor_sync(0xFFFFFFFFu, rm0, 2));
        rm1 = fmaxf(rm1, __shfl_xor_sync(0xFFFFFFFFu, rm1, 1));
        rm1 = fmaxf(rm1, __shfl_xor_sync(0xFFFFFFFFu, rm1, 2));
        float mn0 = fmaxf(m0, rm0), mn1 = fmaxf(m1, rm1);
        float f0 = __expf((m0 - mn0) * iscale);
        float f1 = __expf((m1 - mn1) * iscale);
        m0 = mn0; m1 = mn1;
        float rs0 = 0.0f, rs1 = 0.0f;
#pragma unroll
        for (int ni = 0; ni < 8; ni++) {
            S[ni][0] = __expf((S[ni][0] - mn0) * iscale);
            S[ni][1] = __expf((S[ni][1] - mn0) * iscale);
            S[ni][2] = __expf((S[ni][2] - mn1) * iscale);
            S[ni][3] = __expf((S[ni][3] - mn1) * iscale);
            rs0 += S[ni][0] + S[ni][1];
            rs1 += S[ni][2] + S[ni][3];
        }
        rs0 += __shfl_xor_sync(0xFFFFFFFFu, rs0, 1);
        rs0 += __shfl_xor_sync(0xFFFFFFFFu, rs0, 2);
        rs1 += __shfl_xor_sync(0xFFFFFFFFu, rs1, 1);
        rs1 += __shfl_xor_sync(0xFFFFFFFFu, rs1, 2);
        l0 = l0 * f0 + rs0;
        l1 = l1 * f1 + rs1;
#pragma unroll
        for (int ni = 0; ni < 16; ni++) {
            o[ni][0] *= f0; o[ni][1] *= f0;
            o[ni][2] *= f1; o[ni][3] *= f1;
        }

#pragma unroll
        for (int kf = 0; kf < 4; kf++) {
            uint32_t pH[4];
            {
                float* c0 = S[2 * kf];
                float* c1 = S[2 * kf + 1];
                __half2 t;
                t = __floats2half2_rn(c0[0], c0[1]); pH[0] = *(uint32_t*)&t;
                t = __floats2half2_rn(c0[2], c0[3]); pH[1] = *(uint32_t*)&t;
                t = __floats2half2_rn(c1[0], c1[1]); pH[2] = *(uint32_t*)&t;
                t = __floats2half2_rn(c1[2], c1[3]); pH[3] = *(uint32_t*)&t;
            }
#pragma unroll
            for (int ni = 0; ni < 16; ni++) {
                uint32_t bH[2];
                uint32_t va = st + F_KSZ + (ni * 8 + (lane & 7)) * F_VROW +
                              ((lane >> 3) & 1) * 16 + kf * 32;
                ldsm_x2(va, bH);
                mma_fp16(o[ni], pH, bH);
            }
        }
        __syncthreads();
    }

    float inv0 = 1.0f / l0, inv1 = 1.0f / l1;
    int row0 = qt * 128 + wid * 16 + (lane >> 2);
    int row1 = row0 + 8;
#pragma unroll
    for (int ni = 0; ni < 16; ni++) {
        int col = h * HD + ni * 8 + (lane & 3) * 2;
        __half2 h0 = __floats2half2_rn(o[ni][0] * inv0, o[ni][1] * inv0);
        __half2 h1 = __floats2half2_rn(o[ni][2] * inv1, o[ni][3] * inv1);
        *(__half2*)&aoh[(size_t)row0 * DD + col] = h0;
        *(__half2*)&aoh[(size_t)row1 * DD + col] = h1;
    }
}

// ================= paired HMMA GEMM (img+txt one launch), 3-stage pipeline, occ 2 =================
#define SROW 80
#define ARRB (128 * SROW)
#define STAGEB (2 * ARRB)          // 20480
#define TGEMM_SMEM (3 * STAGEB)    // 61440

template <int EPI>
__global__ __launch_bounds__(256, 2) void tgemm2(
    const __half* __restrict__ Aa, const __half* __restrict__ Ba,
    float* __restrict__ Ca, __half* __restrict__ Cha,
    const float* __restrict__ ba, const float* __restrict__ ga, const float* __restrict__ ra,
    const __half* __restrict__ Ab, const __half* __restrict__ Bb,
    float* __restrict__ Cb, __half* __restrict__ Chb,
    const float* __restrict__ bb, const float* __restrict__ gb, const float* __restrict__ rb,
    int K, int lda, int ldb, int ldc, int ldres, float alpha, int yi) {
    extern __shared__ char smem[];
    uint32_t sb = smem_to_u32(smem);
    int tid = threadIdx.x, wid = tid >> 5, lane = tid & 31;
    int warpM = wid >> 2, warpN = wid & 3;
    int by = blockIdx.y;
    const __half* A; const __half* B; float* C; __half* Chi;
    const float* bias; const float* gate; const float* res;
    int m0;
    if (by < yi) { A = Aa; B = Ba; C = Ca; Chi = Cha; bias = ba; gate = ga; res = ra; m0 = by * 128; }
    else         { A = Ab; B = Bb; C = Cb; Chi = Chb; bias = bb; gate = gb; res = rb; m0 = (by - yi) * 128; }
    int n0 = blockIdx.x * 128;

    const __half* g0 = A + (size_t)m0 * lda;
    const __half* g2 = B + (size_t)n0 * ldb;

    int r0 = tid >> 2, q0 = tid & 3;
    int r1 = (tid + 256) >> 2, q1 = q0;
    uint32_t d00 = sb + r0 * SROW + q0 * 16;
    uint32_t d01 = sb + r1 * SROW + q1 * 16;

    float acc[4][4][4];
#pragma unroll
    for (int i = 0; i < 4; i++)
#pragma unroll
        for (int j = 0; j < 4; j++)
#pragma unroll
            for (int f = 0; f < 4; f++) acc[i][j][f] = 0.0f;

    int nit = K / 32;

    // prologue: stages 0 and 1
#pragma unroll
    for (int p = 0; p < 2; p++) {
        int k0 = p * 32;
        uint32_t st = p * STAGEB;
        cpa16(d00 + st + 0 * ARRB, g0 + (size_t)r0 * lda + k0 + q0 * 8);
        cpa16(d01 + st + 0 * ARRB, g0 + (size_t)r1 * lda + k0 + q1 * 8);
        cpa16(d00 + st + 1 * ARRB, g2 + (size_t)r0 * ldb + k0 + q0 * 8);
        cpa16(d01 + st + 1 * ARRB, g2 + (size_t)r1 * ldb + k0 + q1 * 8);
        CP_COMMIT();
    }

    uint32_t a_base = sb + (warpM * 64 + (lane & 15)) * SROW + ((lane >> 4) * 16);
    uint32_t b_base = sb + 1 * ARRB + (warpN * 32 + (lane & 7)) * SROW + (((lane >> 3) & 1) * 16);

    int sidx = 0;   // stage of current iteration
    for (int it = 0; it < nit; it++) {
        if (it + 2 < nit) {
            int k0 = (it + 2) * 32;
            int ps = sidx - 1; if (ps < 0) ps += 3;   // (it+2)%3
            uint32_t st = (uint32_t)ps * STAGEB;
            cpa16(d00 + st + 0 * ARRB, g0 + (size_t)r0 * lda + k0 + q0 * 8);
            cpa16(d01 + st + 0 * ARRB, g0 + (size_t)r1 * lda + k0 + q1 * 8);
            cpa16(d00 + st + 1 * ARRB, g2 + (size_t)r0 * ldb + k0 + q0 * 8);
            cpa16(d01 + st + 1 * ARRB, g2 + (size_t)r1 * ldb + k0 + q1 * 8);
            CP_COMMIT();
            CP_WAIT(2);
        } else {
            CP_WAIT(0);
        }
        __syncthreads();

        uint32_t st = (uint32_t)sidx * STAGEB;
        uint32_t ab = a_base + st;
        uint32_t bb2 = b_base + st;
#pragma unroll
        for (int kk = 0; kk < 2; kk++) {
            int kb = kk * 32;
            uint32_t ah[4][4], bh[4][2];
#pragma unroll
            for (int mi = 0; mi < 4; mi++)
                ldsm_x4(ab + mi * (16 * SROW) + kb, ah[mi]);
#pragma unroll
            for (int ni = 0; ni < 4; ni++)
                ldsm_x2(bb2 + ni * (8 * SROW) + kb, bh[ni]);
#pragma unroll
            for (int ni = 0; ni < 4; ni++)
#pragma unroll
                for (int mi = 0; mi < 4; mi++)
                    mma_fp16(acc[mi][ni], ah[mi], bh[ni]);
        }
        __syncthreads();
        sidx++; if (sidx == 3) sidx = 0;
    }

    int rbase = m0 + warpM * 64 + (lane >> 2);
    int cbase = n0 + warpN * 32 + (lane & 3) * 2;
#pragma unroll
    for (int mi = 0; mi < 4; mi++) {
#pragma unroll
        for (int ni = 0; ni < 4; ni++) {
            int col = cbase + ni * 8;
#pragma unroll
            for (int hf = 0; hf < 2; hf++) {
                int row = rbase + mi * 16 + hf * 8;
                float v0 = acc[mi][ni][hf * 2 + 0];
                float v1 = acc[mi][ni][hf * 2 + 1];
                if (EPI == 0) {
                    float2 oo; oo.x = alpha * v0; oo.y = alpha * v1;
                    *(float2*)&C[(size_t)row * ldc + col] = oo;
                } else if (EPI == 2) {
                    float2 oo;
                    oo.x = res[(size_t)row * ldres + col + 0] + gate[col + 0] * (v0 + bias[col + 0]);
                    oo.y = res[(size_t)row * ldres + col + 1] + gate[col + 1] * (v1 + bias[col + 1]);
                    *(float2*)&C[(size_t)row * ldc + col] = oo;
                } else { // EPI 3: gelu -> fp16
                    float gg0 = gelu_tanh(v0 + bias[col]);
                    float gg1 = gelu_tanh(v1 + bias[col + 1]);
                    __half2 hp = __floats2half2_rn(gg0, gg1);
                    *(__half2*)&Chi[(size_t)row * ldc + col] = hp;
                }
            }
        }
    }
}

// ================= host side =================
#define SYMF(p, s) do { void* _t = nullptr; cudaGetSymbolAddress(&_t, s); (p) = (float*)_t; } while (0)
#define SYMH(p, s) do { void* _t = nullptr; cudaGetSymbolAddress(&_t, s); (p) = (__half*)_t; } while (0)

extern "C" void kernel_launch(void* const* d_in, const int* in_sizes, int n_in,
                              void* d_out, int out_size) {
    const float* img     = (const float*)d_in[0];
    const float* txt     = (const float*)d_in[1];
    const float* vec     = (const float*)d_in[2];
    const float* pe      = (const float*)d_in[3];
    const float* i_mod_w = (const float*)d_in[4];
    const float* i_mod_b = (const float*)d_in[5];
    const float* i_qkv_w = (const float*)d_in[6];
    const float* i_q_s   = (const float*)d_in[7];
    const float* i_k_s   = (const float*)d_in[8];
    const float* i_pw    = (const float*)d_in[9];
    const float* i_pb    = (const float*)d_in[10];
    const float* i_w1    = (const float*)d_in[11];
    const float* i_b1    = (const float*)d_in[12];
    const float* i_w2    = (const float*)d_in[13];
    const float* i_b2    = (const float*)d_in[14];
    const float* t_mod_w = (const float*)d_in[15];
    const float* t_mod_b = (const float*)d_in[16];
    const float* t_qkv_w = (const float*)d_in[17];
    const float* t_q_s   = (const float*)d_in[18];
    const float* t_k_s   = (const float*)d_in[19];
    const float* t_pw    = (const float*)d_in[20];
    const float* t_pb    = (const float*)d_in[21];
    const float* t_w1    = (const float*)d_in[22];
    const float* t_b1    = (const float*)d_in[23];
    const float* t_w2    = (const float*)d_in[24];
    const float* t_b2    = (const float*)d_in[25];

    float* out_img = (float*)d_out;
    float* out_txt = out_img + (size_t)Li * DD;

    float *mod_i, *mod_t, *qkv_i, *qkv_t, *res_i, *res_t;
    __half *mxi_h, *mxt_h;
    __half *wqi, *wqt, *wpi, *wpt, *w1i, *w1t, *w2i, *w2t;
    __half *qh, *kh, *vth, *aoh, *hh, *ht, *mh, *mt;
    SYMF(mod_i, g_mod_img); SYMF(mod_t, g_mod_txt);
    SYMF(qkv_i, g_qkv_img); SYMF(qkv_t, g_qkv_txt);
    SYMF(res_i, g_res_i); SYMF(res_t, g_res_t);
    SYMH(mxi_h, g_mxi_h); SYMH(mxt_h, g_mxt_h);
    SYMH(wqi, g_w_qkv_i); SYMH(wqt, g_w_qkv_t);
    SYMH(wpi, g_w_p_i); SYMH(wpt, g_w_p_t);
    SYMH(w1i, g_w_1_i); SYMH(w1t, g_w_1_t);
    SYMH(w2i, g_w_2_i); SYMH(w2t, g_w_2_t);
    SYMH(qh, g_qh); SYMH(kh, g_kh); SYMH(vth, g_vth);
    SYMH(aoh, g_aoh);
    SYMH(hh, g_hh); SYMH(ht, g_ht); SYMH(mh, g_mh); SYMH(mt, g_mt);

    cudaFuncSetAttribute(tgemm2<0>, cudaFuncAttributeMaxDynamicSharedMemorySize, TGEMM_SMEM);
    cudaFuncSetAttribute(tgemm2<2>, cudaFuncAttributeMaxDynamicSharedMemorySize, TGEMM_SMEM);
    cudaFuncSetAttribute(tgemm2<3>, cudaFuncAttributeMaxDynamicSharedMemorySize, TGEMM_SMEM);
    cudaFuncSetAttribute(flash_k, cudaFuncAttributeMaxDynamicSharedMemorySize, FLASH_SMEM);

    dim3 wcb(32, 8);
    const int YI = Li / 128;   // 16
    const int YT = Lt / 128;   // 2

    // 1. ALL weight conversions in one launch (no deps; runs first at full fill)
    wconv_all_k<<<T_TOTAL, wcb>>>(i_qkv_w, t_qkv_w, i_pw, t_pw, i_w1, t_w1, i_w2, t_w2,
                                  wqi, wqt, wpi, wpt, w1i, w1t, w2i, w2t);

    // 2. modulation (silu fused, both streams)
    modmul2_k<<<192, 128>>>(vec, i_mod_w, i_mod_b, mod_i, t_mod_w, t_mod_b, mod_t);

    // 3. LN1 + modulate -> fp16 (merged)
    ln_mod2_k<<<Li + Lt, 256>>>(img, mxi_h, mod_i + 0 * DD, mod_i + 1 * DD,
                                txt, mxt_h, mod_t + 0 * DD, mod_t + 1 * DD, Li);

    // 4. QKV GEMM (merged)
    tgemm2<0><<<dim3(3 * DD / 128, YI + YT), 256, TGEMM_SMEM>>>(
        mxi_h, wqi, qkv_i, nullptr, nullptr, nullptr, nullptr,
        mxt_h, wqt, qkv_t, nullptr, nullptr, nullptr, nullptr,
        DD, DD, DD, 3 * DD, 0, 1.0f, YI);

    // 5. split + rmsnorm + rope
    qkv_prep_k<<<dim3(HH, LL), HD>>>(qkv_t, qkv_i, t_q_s, t_k_s, i_q_s, i_k_s, pe,
                                     qh, kh, vth);

    // 6. fused flash attention -> aoh
    flash_k<<<dim3(LL / 128, HH), 256, FLASH_SMEM>>>(qh, kh, vth, aoh);

    // 7. proj + gated residual (merged)
    tgemm2<2><<<dim3(DD / 128, YI + YT), 256, TGEMM_SMEM>>>(
        aoh + (size_t)Lt * DD, wpi, res_i, nullptr, i_pb, mod_i + 2 * DD, img,
        aoh, wpt, res_t, nullptr, t_pb, mod_t + 2 * DD, txt,
        DD, DD, DD, DD, DD, 1.0f, YI);

    // 8. LN2 (merged)
    ln_mod2_k<<<Li + Lt, 256>>>(res_i, hh, mod_i + 3 * DD, mod_i + 4 * DD,
                                res_t, ht, mod_t + 3 * DD, mod_t + 4 * DD, Li);

    // 9. MLP1 (merged, gelu -> fp16)
    tgemm2<3><<<dim3(MLPD / 128, YI + YT), 256, TGEMM_SMEM>>>(
        hh, w1i, nullptr, mh, i_b1, nullptr, nullptr,
        ht, w1t, nullptr, mt, t_b1, nullptr, nullptr,
        DD, DD, DD, MLPD, 0, 1.0f, YI);

    // 10. MLP2 (merged, gated residual -> d_out)
    tgemm2<2><<<dim3(DD / 128, YI + YT), 256, TGEMM_SMEM>>>(
        mh, w2i, out_img, nullptr, i_b2, mod_i + 5 * DD, res_i,
        mt, w2t, out_txt, nullptr, t_b2, mod_t + 5 * DD, res_t,
        MLPD, MLPD, MLPD, DD, DD, 1.0f, YI);

    (void)in_sizes; (void)n_in; (void)out_size;
}

// round 17
// speedup vs baseline: 2.4044x; 1.1760x over previous
#include <cuda_runtime.h>
#include <cuda_fp16.h>
#include <math.h>
#include <stdint.h>

#define Lt 256
#define Li 2048
#define LL 2304          // Lt + Li
#define DD 2048
#define HH 16
#define HD 128
#define MLPD 8192
#define EPSF 1e-6f

// ================= helpers =================
__device__ __forceinline__ uint32_t smem_to_u32(const void* p) {
    uint32_t a;
    asm("{ .reg .u64 t; cvta.to.shared.u64 t, %1; cvt.u32.u64 %0, t; }" : "=r"(a) : "l"(p));
    return a;
}
__device__ __forceinline__ void cpa16(uint32_t dst, const void* src) {
    asm volatile("cp.async.cg.shared.global [%0], [%1], 16;" :: "r"(dst), "l"(src));
}
#define CP_COMMIT() asm volatile("cp.async.commit_group;" ::: "memory")
#define CP_WAIT(N)  asm volatile("cp.async.wait_group %0;" :: "n"(N) : "memory")

__device__ __forceinline__ void ldsm_x4(uint32_t addr, uint32_t* r) {
    asm volatile("ldmatrix.sync.aligned.m8n8.x4.shared.b16 {%0,%1,%2,%3}, [%4];"
                 : "=r"(r[0]), "=r"(r[1]), "=r"(r[2]), "=r"(r[3]) : "r"(addr));
}
__device__ __forceinline__ void ldsm_x2(uint32_t addr, uint32_t* r) {
    asm volatile("ldmatrix.sync.aligned.m8n8.x2.shared.b16 {%0,%1}, [%2];"
                 : "=r"(r[0]), "=r"(r[1]) : "r"(addr));
}
__device__ __forceinline__ void mma_fp16(float* d, const uint32_t* a, const uint32_t* b) {
    asm volatile(
        "mma.sync.aligned.m16n8k16.row.col.f32.f16.f16.f32 "
        "{%0,%1,%2,%3}, {%4,%5,%6,%7}, {%8,%9}, {%0,%1,%2,%3};"
        : "+f"(d[0]), "+f"(d[1]), "+f"(d[2]), "+f"(d[3])
        : "r"(a[0]), "r"(a[1]), "r"(a[2]), "r"(a[3]), "r"(b[0]), "r"(b[1]));
}

__device__ __forceinline__ float gelu_tanh(float x) {
    float x3 = x * x * x;
    return 0.5f * x * (1.0f + tanhf(0.7978845608028654f * (x + 0.044715f * x3)));
}

// ================= scratch (static device globals) =================
__device__ __align__(16) float g_mod_img[6 * DD];
__device__ __align__(16) float g_mod_txt[6 * DD];
__device__ __align__(16) __half g_mxi_h[Li * DD];
__device__ __align__(16) __half g_mxt_h[Lt * DD];
__device__ __align__(16) __half g_w_qkv_i[(size_t)3 * DD * DD];
__device__ __align__(16) __half g_w_qkv_t[(size_t)3 * DD * DD];
__device__ __align__(16) __half g_w_p_i[(size_t)DD * DD];
__device__ __align__(16) __half g_w_p_t[(size_t)DD * DD];
__device__ __align__(16) __half g_w_1_i[(size_t)MLPD * DD];
__device__ __align__(16) __half g_w_1_t[(size_t)MLPD * DD];
__device__ __align__(16) __half g_w_2_i[(size_t)DD * MLPD];
__device__ __align__(16) __half g_w_2_t[(size_t)DD * MLPD];
__device__ __align__(16) float g_qkv_img[Li * 3 * DD];
__device__ __align__(16) float g_qkv_txt[Lt * 3 * DD];
__device__ __align__(16) __half g_qh[HH * LL * HD];
__device__ __align__(16) __half g_kh[HH * LL * HD];
__device__ __align__(16) __half g_vth[HH * HD * LL]; // V transposed per head [H, HD, LL]
__device__ __align__(16) __half g_aoh[LL * DD];
__device__ __align__(16) float g_res_i[Li * DD];
__device__ __align__(16) float g_res_t[Lt * DD];
__device__ __align__(16) __half g_hh[Li * DD];
__device__ __align__(16) __half g_ht[Lt * DD];
__device__ __align__(16) __half g_mh[(size_t)Li * MLPD];
__device__ __align__(16) __half g_mt[(size_t)Lt * MLPD];

// ================= small kernels =================
__global__ void modmul2_k(const float* __restrict__ vec,
                          const float* __restrict__ Wi, const float* __restrict__ bi,
                          float* __restrict__ outi,
                          const float* __restrict__ Wt, const float* __restrict__ bt,
                          float* __restrict__ outt) {
    __shared__ float s[DD];
    int tid = threadIdx.x;
    for (int i = tid; i < DD; i += 128) { float x = vec[i]; s[i] = x / (1.0f + __expf(-x)); }
    __syncthreads();
    const float* W; const float* bb; float* out; int j;
    if (blockIdx.x < 96) { W = Wi; bb = bi; out = outi; j = blockIdx.x * 128 + tid; }
    else                 { W = Wt; bb = bt; out = outt; j = (blockIdx.x - 96) * 128 + tid; }
    float acc = 0.0f;
    const float* wp = W + j;
    for (int d = 0; d < DD; d++) acc += s[d] * wp[(size_t)d * (6 * DD)];
    out[j] = acc + bb[j];
}

__global__ void ln_mod2_k(const float* __restrict__ xa, __half* __restrict__ ya,
                          const float* __restrict__ sha, const float* __restrict__ sca,
                          const float* __restrict__ xb, __half* __restrict__ yb,
                          const float* __restrict__ shb, const float* __restrict__ scb,
                          int na) {
    int row = blockIdx.x;
    const float* x; __half* y; const float* sh; const float* sc;
    if (row < na) { x = xa; y = ya; sh = sha; sc = sca; }
    else          { x = xb; y = yb; sh = shb; sc = scb; row -= na; }
    const float* px = x + (size_t)row * DD;
    __shared__ float red[256];
    int tid = threadIdx.x;
    float v[8];
    float s = 0.0f;
#pragma unroll
    for (int i = 0; i < 8; i++) { v[i] = px[tid + i * 256]; s += v[i]; }
    red[tid] = s; __syncthreads();
    for (int o = 128; o > 0; o >>= 1) { if (tid < o) red[tid] += red[tid + o]; __syncthreads(); }
    float mu = red[0] * (1.0f / DD);
    __syncthreads();
    float ss = 0.0f;
#pragma unroll
    for (int i = 0; i < 8; i++) { float d = v[i] - mu; ss += d * d; }
    red[tid] = ss; __syncthreads();
    for (int o = 128; o > 0; o >>= 1) { if (tid < o) red[tid] += red[tid + o]; __syncthreads(); }
    float r = rsqrtf(red[0] * (1.0f / DD) + EPSF);
#pragma unroll
    for (int i = 0; i < 8; i++) {
        int c = tid + i * 256;
        float y2 = (1.0f + sc[c]) * ((v[i] - mu) * r) + sh[c];
        y[(size_t)row * DD + c] = __float2half_rn(y2);
    }
}

// ======= ALL weight conversions in ONE launch =======
#define T_QKV 12288
#define T_P   4096
#define T_W1  16384
#define T_W2  16384
#define T_TOTAL (2 * T_QKV + 2 * T_P + 2 * T_W1 + 2 * T_W2)   // 98304

__global__ void wconv_all_k(
    const float* __restrict__ iqkv, const float* __restrict__ tqkv,
    const float* __restrict__ ipw,  const float* __restrict__ tpw,
    const float* __restrict__ iw1,  const float* __restrict__ tw1,
    const float* __restrict__ iw2,  const float* __restrict__ tw2,
    __half* __restrict__ d_iqkv, __half* __restrict__ d_tqkv,
    __half* __restrict__ d_ipw,  __half* __restrict__ d_tpw,
    __half* __restrict__ d_iw1,  __half* __restrict__ d_tw1,
    __half* __restrict__ d_iw2,  __half* __restrict__ d_tw2) {
    int b = blockIdx.x;
    const float* W; __half* Wh; int Kd, Nd, lx;
    if (b < 2 * T_QKV) {
        Kd = DD; Nd = 3 * DD;
        if (b < T_QKV) { W = iqkv; Wh = d_iqkv; lx = b; }
        else           { W = tqkv; Wh = d_tqkv; lx = b - T_QKV; }
    } else if (b < 2 * T_QKV + 2 * T_P) {
        int c = b - 2 * T_QKV; Kd = DD; Nd = DD;
        if (c < T_P) { W = ipw; Wh = d_ipw; lx = c; }
        else         { W = tpw; Wh = d_tpw; lx = c - T_P; }
    } else if (b < 2 * T_QKV + 2 * T_P + 2 * T_W1) {
        int c = b - 2 * T_QKV - 2 * T_P; Kd = DD; Nd = MLPD;
        if (c < T_W1) { W = iw1; Wh = d_iw1; lx = c; }
        else          { W = tw1; Wh = d_tw1; lx = c - T_W1; }
    } else {
        int c = b - 2 * T_QKV - 2 * T_P - 2 * T_W1; Kd = MLPD; Nd = DD;
        if (c < T_W2) { W = iw2; Wh = d_iw2; lx = c; }
        else          { W = tw2; Wh = d_tw2; lx = c - T_W2; }
    }
    int xw = Nd / 32;
    int bx = lx % xw, by = lx / xw;

    __shared__ float t[32][33];
    int n = bx * 32 + threadIdx.x;
#pragma unroll
    for (int i = 0; i < 4; i++) {
        int k = by * 32 + threadIdx.y + i * 8;
        t[threadIdx.y + i * 8][threadIdx.x] = W[(size_t)k * Nd + n];
    }
    __syncthreads();
    int k2 = by * 32 + threadIdx.x;
#pragma unroll
    for (int i = 0; i < 4; i++) {
        int n2 = bx * 32 + threadIdx.y + i * 8;
        Wh[(size_t)n2 * Kd + k2] = __float2half_rn(t[threadIdx.x][threadIdx.y + i * 8]);
    }
}

// split qkv, rmsnorm(q,k)*scale, rope(q,k); q,k,v rounded fp16 (v transposed)
__global__ void qkv_prep_k(const float* __restrict__ qkv_txt, const float* __restrict__ qkv_img,
                           const float* __restrict__ tq_s, const float* __restrict__ tk_s,
                           const float* __restrict__ iq_s, const float* __restrict__ ik_s,
                           const float* __restrict__ pe,
                           __half* __restrict__ qh, __half* __restrict__ kh,
                           __half* __restrict__ vth) {
    int h = blockIdx.x;
    int pos = blockIdx.y;
    int d = threadIdx.x;
    const float* src; int l; const float* qs; const float* ks;
    if (pos < Lt) { src = qkv_txt; l = pos;      qs = tq_s; ks = tk_s; }
    else          { src = qkv_img; l = pos - Lt; qs = iq_s; ks = ik_s; }
    const float* base = src + (size_t)l * (3 * DD) + h * HD;
    float qv = base[d];
    float kv = base[DD + d];
    float vv = base[2 * DD + d];

    __shared__ float sq[HD], sk[HD], red[8];
    float q2 = qv * qv, k2 = kv * kv;
#pragma unroll
    for (int o = 16; o > 0; o >>= 1) {
        q2 += __shfl_xor_sync(0xFFFFFFFFu, q2, o);
        k2 += __shfl_xor_sync(0xFFFFFFFFu, k2, o);
    }
    int w = d >> 5;
    if ((d & 31) == 0) { red[w] = q2; red[4 + w] = k2; }
    __syncthreads();
    float qss = red[0] + red[1] + red[2] + red[3];
    float kss = red[4] + red[5] + red[6] + red[7];
    float qn = qv * rsqrtf(qss * (1.0f / HD) + EPSF) * qs[d];
    float kn = kv * rsqrtf(kss * (1.0f / HD) + EPSF) * ks[d];
    sq[d] = qn; sk[d] = kn;
    __syncthreads();
    int i = d >> 1, j = d & 1;
    const float* pp = pe + (((size_t)pos * 64 + i) * 4 + j * 2);
    float p0 = pp[0], p1 = pp[1];
    float rq = p0 * sq[2 * i] + p1 * sq[2 * i + 1];
    float rk = p0 * sk[2 * i] + p1 * sk[2 * i + 1];
    size_t o = ((size_t)h * LL + pos) * HD + d;
    qh[o] = __float2half_rn(rq);
    kh[o] = __float2half_rn(rk);
    size_t ov = ((size_t)h * HD + d) * LL + pos;
    vth[ov] = __float2half_rn(vv);
}

// ================= fused flash attention =================
// Single barrier per chunk; occupancy 2 (one wave of 288 CTAs).
#define FCHUNK 64
#define NCHUNK (LL / FCHUNK)       // 36
#define F_QROW 272
#define F_QSZ  (128 * F_QROW)      // 34816
#define F_KROW 272
#define F_KSZ  (64 * F_KROW)       // 17408
#define F_VROW 144
#define F_VSZ  (128 * F_VROW)      // 18432
#define F_STG0 F_QSZ
#define F_STGSZ (F_KSZ + F_VSZ)    // 35840
#define FLASH_SMEM (F_STG0 + 2 * F_STGSZ) // 106496

__global__ __launch_bounds__(256, 2) void flash_k(
    const __half* __restrict__ qhg, const __half* __restrict__ khg,
    const __half* __restrict__ vthg,
    __half* __restrict__ aoh) {
    extern __shared__ char smem[];
    uint32_t sb = smem_to_u32(smem);
    int tid = threadIdx.x, wid = tid >> 5, lane = tid & 31;
    int h = blockIdx.y, qt = blockIdx.x;
    const float iscale = 0.08838834764831845f; // 1/sqrt(128)

#pragma unroll
    for (int i = 0; i < 8; i++) {
        int u = tid + i * 256;
        int row = u >> 4, cu = u & 15;
        size_t go = ((size_t)h * LL + qt * 128 + row) * HD + cu * 8;
        cpa16(sb + row * F_QROW + cu * 16, qhg + go);
    }
    CP_COMMIT();

    {
        uint32_t st = sb + F_STG0;
#pragma unroll
        for (int i = 0; i < 4; i++) {
            int u = tid + i * 256;
            int row = u >> 4, cu = u & 15;
            size_t go = ((size_t)h * LL + row) * HD + cu * 8;
            cpa16(st + row * F_KROW + cu * 16, khg + go);
            int vr = u >> 3, vc = u & 7;
            size_t gv = ((size_t)h * HD + vr) * LL + vc * 8;
            cpa16(st + F_KSZ + vr * F_VROW + vc * 16, vthg + gv);
        }
        CP_COMMIT();
    }

    float o[16][4];
#pragma unroll
    for (int i = 0; i < 16; i++)
#pragma unroll
        for (int f = 0; f < 4; f++) o[i][f] = 0.0f;
    float m0 = -1e30f, m1 = -1e30f, l0 = 0.0f, l1 = 0.0f;

    uint32_t qa_base = sb + (wid * 16 + (lane & 15)) * F_QROW + ((lane >> 4) * 16);

    for (int j = 0; j < NCHUNK; j++) {
        CP_WAIT(0);
        __syncthreads();     // stage j ready; all warps done with compute(j-1)
        if (j + 1 < NCHUNK) {
            int ln = (j + 1) * FCHUNK;
            uint32_t st = sb + F_STG0 + ((j + 1) & 1) * F_STGSZ;
#pragma unroll
            for (int i = 0; i < 4; i++) {
                int u = tid + i * 256;
                int row = u >> 4, cu = u & 15;
                size_t go = ((size_t)h * LL + ln + row) * HD + cu * 8;
                cpa16(st + row * F_KROW + cu * 16, khg + go);
                int vr = u >> 3, vc = u & 7;
                size_t gv = ((size_t)h * HD + vr) * LL + ln + vc * 8;
                cpa16(st + F_KSZ + vr * F_VROW + vc * 16, vthg + gv);
            }
            CP_COMMIT();
        }

        uint32_t st = sb + F_STG0 + (j & 1) * F_STGSZ;

        float S[8][4];
#pragma unroll
        for (int i = 0; i < 8; i++)
#pragma unroll
            for (int f = 0; f < 4; f++) S[i][f] = 0.0f;
#pragma unroll
        for (int kk = 0; kk < 8; kk++) {
            uint32_t aH[4], bArr[8][2];
            ldsm_x4(qa_base + kk * 32, aH);
#pragma unroll
            for (int ni = 0; ni < 8; ni++) {
                uint32_t ka = st + (ni * 8 + (lane & 7)) * F_KROW + ((lane >> 3) & 1) * 16 + kk * 32;
                ldsm_x2(ka, bArr[ni]);
            }
#pragma unroll
            for (int ni = 0; ni < 8; ni++) mma_fp16(S[ni], aH, bArr[ni]);
        }

        float rm0 = -1e30f, rm1 = -1e30f;
#pragma unroll
        for (int ni = 0; ni < 8; ni++) {
            rm0 = fmaxf(rm0, fmaxf(S[ni][0], S[ni][1]));
            rm1 = fmaxf(rm1, fmaxf(S[ni][2], S[ni][3]));
        }
        rm0 = fmaxf(rm0, __shfl_xor_sync(0xFFFFFFFFu, rm0, 1));
        rm0 = fmaxf(rm0, __shfl_xor_sync(0xFFFFFFFFu, rm0, 2));
        rm1 = fmaxf(rm1, __shfl_xor_sync(0xFFFFFFFFu, rm1, 1));
        rm1 = fmaxf(rm1, __shfl_xor_sync(0xFFFFFFFFu, rm1, 2));
        float mn0 = fmaxf(m0, rm0), mn1 = fmaxf(m1, rm1);
        float f0 = __expf((m0 - mn0) * iscale);
        float f1 = __expf((m1 - mn1) * iscale);
        m0 = mn0; m1 = mn1;
        float rs0 = 0.0f, rs1 = 0.0f;
#pragma unroll
        for (int ni = 0; ni < 8; ni++) {
            S[ni][0] = __expf((S[ni][0] - mn0) * iscale);
            S[ni][1] = __expf((S[ni][1] - mn0) * iscale);
            S[ni][2] = __expf((S[ni][2] - mn1) * iscale);
            S[ni][3] = __expf((S[ni][3] - mn1) * iscale);
            rs0 += S[ni][0] + S[ni][1];
            rs1 += S[ni][2] + S[ni][3];
        }
        rs0 += __shfl_xor_sync(0xFFFFFFFFu, rs0, 1);
        rs0 += __shfl_xor_sync(0xFFFFFFFFu, rs0, 2);
        rs1 += __shfl_xor_sync(0xFFFFFFFFu, rs1, 1);
        rs1 += __shfl_xor_sync(0xFFFFFFFFu, rs1, 2);
        l0 = l0 * f0 + rs0;
        l1 = l1 * f1 + rs1;
#pragma unroll
        for (int ni = 0; ni < 16; ni++) {
            o[ni][0] *= f0; o[ni][1] *= f0;
            o[ni][2] *= f1; o[ni][3] *= f1;
        }

#pragma unroll
        for (int kf = 0; kf < 4; kf++) {
            uint32_t pH[4];
            {
                float* c0 = S[2 * kf];
                float* c1 = S[2 * kf + 1];
                __half2 t;
                t = __floats2half2_rn(c0[0], c0[1]); pH[0] = *(uint32_t*)&t;
                t = __floats2half2_rn(c0[2], c0[3]); pH[1] = *(uint32_t*)&t;
                t = __floats2half2_rn(c1[0], c1[1]); pH[2] = *(uint32_t*)&t;
                t = __floats2half2_rn(c1[2], c1[3]); pH[3] = *(uint32_t*)&t;
            }
#pragma unroll
            for (int ni = 0; ni < 16; ni++) {
                uint32_t bH[2];
                uint32_t va = st + F_KSZ + (ni * 8 + (lane & 7)) * F_VROW +
                              ((lane >> 3) & 1) * 16 + kf * 32;
                ldsm_x2(va, bH);
                mma_fp16(o[ni], pH, bH);
            }
        }
        // no trailing barrier: next iteration's top barrier orders stage reuse
    }

    float inv0 = 1.0f / l0, inv1 = 1.0f / l1;
    int row0 = qt * 128 + wid * 16 + (lane >> 2);
    int row1 = row0 + 8;
#pragma unroll
    for (int ni = 0; ni < 16; ni++) {
        int col = h * HD + ni * 8 + (lane & 3) * 2;
        __half2 h0 = __floats2half2_rn(o[ni][0] * inv0, o[ni][1] * inv0);
        __half2 h1 = __floats2half2_rn(o[ni][2] * inv1, o[ni][3] * inv1);
        *(__half2*)&aoh[(size_t)row0 * DD + col] = h0;
        *(__half2*)&aoh[(size_t)row1 * DD + col] = h1;
    }
}

// ================= paired HMMA GEMM: 4-stage pipeline, ONE barrier/iter, occ 2 =================
#define SROW 80
#define ARRB (128 * SROW)
#define STAGEB (2 * ARRB)          // 20480
#define NSTG 4
#define TGEMM_SMEM (NSTG * STAGEB) // 81920

template <int EPI>
__global__ __launch_bounds__(256, 2) void tgemm2(
    const __half* __restrict__ Aa, const __half* __restrict__ Ba,
    float* __restrict__ Ca, __half* __restrict__ Cha,
    const float* __restrict__ ba, const float* __restrict__ ga, const float* __restrict__ ra,
    const __half* __restrict__ Ab, const __half* __restrict__ Bb,
    float* __restrict__ Cb, __half* __restrict__ Chb,
    const float* __restrict__ bb, const float* __restrict__ gb, const float* __restrict__ rb,
    int K, int lda, int ldb, int ldc, int ldres, float alpha, int yi) {
    extern __shared__ char smem[];
    uint32_t sb = smem_to_u32(smem);
    int tid = threadIdx.x, wid = tid >> 5, lane = tid & 31;
    int warpM = wid >> 2, warpN = wid & 3;
    int by = blockIdx.y;
    const __half* A; const __half* B; float* C; __half* Chi;
    const float* bias; const float* gate; const float* res;
    int m0;
    if (by < yi) { A = Aa; B = Ba; C = Ca; Chi = Cha; bias = ba; gate = ga; res = ra; m0 = by * 128; }
    else         { A = Ab; B = Bb; C = Cb; Chi = Chb; bias = bb; gate = gb; res = rb; m0 = (by - yi) * 128; }
    int n0 = blockIdx.x * 128;

    const __half* g0 = A + (size_t)m0 * lda;
    const __half* g2 = B + (size_t)n0 * ldb;

    int r0 = tid >> 2, q0 = tid & 3;
    int r1 = (tid + 256) >> 2, q1 = q0;
    uint32_t d00 = sb + r0 * SROW + q0 * 16;
    uint32_t d01 = sb + r1 * SROW + q1 * 16;

    float acc[4][4][4];
#pragma unroll
    for (int i = 0; i < 4; i++)
#pragma unroll
        for (int j = 0; j < 4; j++)
#pragma unroll
            for (int f = 0; f < 4; f++) acc[i][j][f] = 0.0f;

    int nit = K / 32;

    // prologue: stages 0..NSTG-2
#pragma unroll
    for (int p = 0; p < NSTG - 1; p++) {
        int k0 = p * 32;
        uint32_t st = (uint32_t)p * STAGEB;
        cpa16(d00 + st + 0 * ARRB, g0 + (size_t)r0 * lda + k0 + q0 * 8);
        cpa16(d01 + st + 0 * ARRB, g0 + (size_t)r1 * lda + k0 + q1 * 8);
        cpa16(d00 + st + 1 * ARRB, g2 + (size_t)r0 * ldb + k0 + q0 * 8);
        cpa16(d01 + st + 1 * ARRB, g2 + (size_t)r1 * ldb + k0 + q1 * 8);
        CP_COMMIT();
    }

    uint32_t a_base = sb + (warpM * 64 + (lane & 15)) * SROW + ((lane >> 4) * 16);
    uint32_t b_base = sb + 1 * ARRB + (warpN * 32 + (lane & 7)) * SROW + (((lane >> 3) & 1) * 16);

    int sidx = 0;
    for (int it = 0; it < nit; it++) {
        CP_WAIT(NSTG - 2);      // stage sidx data landed (≤2 newest groups pending)
        __syncthreads();        // + all warps done with compute(it-1)

        uint32_t st = (uint32_t)sidx * STAGEB;
        uint32_t ab = a_base + st;
        uint32_t bb2 = b_base + st;
#pragma unroll
        for (int kk = 0; kk < 2; kk++) {
            int kb = kk * 32;
            uint32_t ah[4][4], bh[4][2];
#pragma unroll
            for (int mi = 0; mi < 4; mi++)
                ldsm_x4(ab + mi * (16 * SROW) + kb, ah[mi]);
#pragma unroll
            for (int ni = 0; ni < 4; ni++)
                ldsm_x2(bb2 + ni * (8 * SROW) + kb, bh[ni]);
#pragma unroll
            for (int ni = 0; ni < 4; ni++)
#pragma unroll
                for (int mi = 0; mi < 4; mi++)
                    mma_fp16(acc[mi][ni], ah[mi], bh[ni]);
        }

        // prefetch stage it+NSTG-1 (safe: overwrites stage read at it-1; barrier above ordered it)
        if (it + NSTG - 1 < nit) {
            int k0 = (it + NSTG - 1) * 32;
            uint32_t ps = (uint32_t)((it + NSTG - 1) & (NSTG - 1)) * STAGEB;
            cpa16(d00 + ps + 0 * ARRB, g0 + (size_t)r0 * lda + k0 + q0 * 8);
            cpa16(d01 + ps + 0 * ARRB, g0 + (size_t)r1 * lda + k0 + q1 * 8);
            cpa16(d00 + ps + 1 * ARRB, g2 + (size_t)r0 * ldb + k0 + q0 * 8);
            cpa16(d01 + ps + 1 * ARRB, g2 + (size_t)r1 * ldb + k0 + q1 * 8);
        }
        CP_COMMIT();            // unconditional: empty tail groups keep wait arithmetic valid
        sidx = (sidx + 1) & (NSTG - 1);
    }

    int rbase = m0 + warpM * 64 + (lane >> 2);
    int cbase = n0 + warpN * 32 + (lane & 3) * 2;
#pragma unroll
    for (int mi = 0; mi < 4; mi++) {
#pragma unroll
        for (int ni = 0; ni < 4; ni++) {
            int col = cbase + ni * 8;
#pragma unroll
            for (int hf = 0; hf < 2; hf++) {
                int row = rbase + mi * 16 + hf * 8;
                float v0 = acc[mi][ni][hf * 2 + 0];
                float v1 = acc[mi][ni][hf * 2 + 1];
                if (EPI == 0) {
                    float2 oo; oo.x = alpha * v0; oo.y = alpha * v1;
                    *(float2*)&C[(size_t)row * ldc + col] = oo;
                } else if (EPI == 2) {
                    float2 oo;
                    oo.x = res[(size_t)row * ldres + col + 0] + gate[col + 0] * (v0 + bias[col + 0]);
                    oo.y = res[(size_t)row * ldres + col + 1] + gate[col + 1] * (v1 + bias[col + 1]);
                    *(float2*)&C[(size_t)row * ldc + col] = oo;
                } else { // EPI 3: gelu -> fp16
                    float gg0 = gelu_tanh(v0 + bias[col]);
                    float gg1 = gelu_tanh(v1 + bias[col + 1]);
                    __half2 hp = __floats2half2_rn(gg0, gg1);
                    *(__half2*)&Chi[(size_t)row * ldc + col] = hp;
                }
            }
        }
    }
}

// ================= host side =================
#define SYMF(p, s) do { void* _t = nullptr; cudaGetSymbolAddress(&_t, s); (p) = (float*)_t; } while (0)
#define SYMH(p, s) do { void* _t = nullptr; cudaGetSymbolAddress(&_t, s); (p) = (__half*)_t; } while (0)

extern "C" void kernel_launch(void* const* d_in, const int* in_sizes, int n_in,
                              void* d_out, int out_size) {
    const float* img     = (const float*)d_in[0];
    const float* txt     = (const float*)d_in[1];
    const float* vec     = (const float*)d_in[2];
    const float* pe      = (const float*)d_in[3];
    const float* i_mod_w = (const float*)d_in[4];
    const float* i_mod_b = (const float*)d_in[5];
    const float* i_qkv_w = (const float*)d_in[6];
    const float* i_q_s   = (const float*)d_in[7];
    const float* i_k_s   = (const float*)d_in[8];
    const float* i_pw    = (const float*)d_in[9];
    const float* i_pb    = (const float*)d_in[10];
    const float* i_w1    = (const float*)d_in[11];
    const float* i_b1    = (const float*)d_in[12];
    const float* i_w2    = (const float*)d_in[13];
    const float* i_b2    = (const float*)d_in[14];
    const float* t_mod_w = (const float*)d_in[15];
    const float* t_mod_b = (const float*)d_in[16];
    const float* t_qkv_w = (const float*)d_in[17];
    const float* t_q_s   = (const float*)d_in[18];
    const float* t_k_s   = (const float*)d_in[19];
    const float* t_pw    = (const float*)d_in[20];
    const float* t_pb    = (const float*)d_in[21];
    const float* t_w1    = (const float*)d_in[22];
    const float* t_b1    = (const float*)d_in[23];
    const float* t_w2    = (const float*)d_in[24];
    const float* t_b2    = (const float*)d_in[25];

    float* out_img = (float*)d_out;
    float* out_txt = out_img + (size_t)Li * DD;

    float *mod_i, *mod_t, *qkv_i, *qkv_t, *res_i, *res_t;
    __half *mxi_h, *mxt_h;
    __half *wqi, *wqt, *wpi, *wpt, *w1i, *w1t, *w2i, *w2t;
    __half *qh, *kh, *vth, *aoh, *hh, *ht, *mh, *mt;
    SYMF(mod_i, g_mod_img); SYMF(mod_t, g_mod_txt);
    SYMF(qkv_i, g_qkv_img); SYMF(qkv_t, g_qkv_txt);
    SYMF(res_i, g_res_i); SYMF(res_t, g_res_t);
    SYMH(mxi_h, g_mxi_h); SYMH(mxt_h, g_mxt_h);
    SYMH(wqi, g_w_qkv_i); SYMH(wqt, g_w_qkv_t);
    SYMH(wpi, g_w_p_i); SYMH(wpt, g_w_p_t);
    SYMH(w1i, g_w_1_i); SYMH(w1t, g_w_1_t);
    SYMH(w2i, g_w_2_i); SYMH(w2t, g_w_2_t);
    SYMH(qh, g_qh); SYMH(kh, g_kh); SYMH(vth, g_vth);
    SYMH(aoh, g_aoh);
    SYMH(hh, g_hh); SYMH(ht, g_ht); SYMH(mh, g_mh); SYMH(mt, g_mt);

    cudaFuncSetAttribute(tgemm2<0>, cudaFuncAttributeMaxDynamicSharedMemorySize, TGEMM_SMEM);
    cudaFuncSetAttribute(tgemm2<2>, cudaFuncAttributeMaxDynamicSharedMemorySize, TGEMM_SMEM);
    cudaFuncSetAttribute(tgemm2<3>, cudaFuncAttributeMaxDynamicSharedMemorySize, TGEMM_SMEM);
    cudaFuncSetAttribute(flash_k, cudaFuncAttributeMaxDynamicSharedMemorySize, FLASH_SMEM);

    dim3 wcb(32, 8);
    const int YI = Li / 128;   // 16
    const int YT = Lt / 128;   // 2

    // 1. ALL weight conversions in one launch
    wconv_all_k<<<T_TOTAL, wcb>>>(i_qkv_w, t_qkv_w, i_pw, t_pw, i_w1, t_w1, i_w2, t_w2,
                                  wqi, wqt, wpi, wpt, w1i, w1t, w2i, w2t);

    // 2. modulation (silu fused, both streams)
    modmul2_k<<<192, 128>>>(vec, i_mod_w, i_mod_b, mod_i, t_mod_w, t_mod_b, mod_t);

    // 3. LN1 + modulate -> fp16 (merged)
    ln_mod2_k<<<Li + Lt, 256>>>(img, mxi_h, mod_i + 0 * DD, mod_i + 1 * DD,
                                txt, mxt_h, mod_t + 0 * DD, mod_t + 1 * DD, Li);

    // 4. QKV GEMM (merged)
    tgemm2<0><<<dim3(3 * DD / 128, YI + YT), 256, TGEMM_SMEM>>>(
        mxi_h, wqi, qkv_i, nullptr, nullptr, nullptr, nullptr,
        mxt_h, wqt, qkv_t, nullptr, nullptr, nullptr, nullptr,
        DD, DD, DD, 3 * DD, 0, 1.0f, YI);

    // 5. split + rmsnorm + rope
    qkv_prep_k<<<dim3(HH, LL), HD>>>(qkv_t, qkv_i, t_q_s, t_k_s, i_q_s, i_k_s, pe,
                                     qh, kh, vth);

    // 6. fused flash attention -> aoh
    flash_k<<<dim3(LL / 128, HH), 256, FLASH_SMEM>>>(qh, kh, vth, aoh);

    // 7. proj + gated residual (merged)
    tgemm2<2><<<dim3(DD / 128, YI + YT), 256, TGEMM_SMEM>>>(
        aoh + (size_t)Lt * DD, wpi, res_i, nullptr, i_pb, mod_i + 2 * DD, img,
        aoh, wpt, res_t, nullptr, t_pb, mod_t + 2 * DD, txt,
        DD, DD, DD, DD, DD, 1.0f, YI);

    // 8. LN2 (merged)
    ln_mod2_k<<<Li + Lt, 256>>>(res_i, hh, mod_i + 3 * DD, mod_i + 4 * DD,
                                res_t, ht, mod_t + 3 * DD, mod_t + 4 * DD, Li);

    // 9. MLP1 (merged, gelu -> fp16)
    tgemm2<3><<<dim3(MLPD / 128, YI + YT), 256, TGEMM_SMEM>>>(
        hh, w1i, nullptr, mh, i_b1, nullptr, nullptr,
        ht, w1t, nullptr, mt, t_b1, nullptr, nullptr,
        DD, DD, DD, MLPD, 0, 1.0f, YI);

    // 10. MLP2 (merged, gated residual -> d_out)
    tgemm2<2><<<dim3(DD / 128, YI + YT), 256, TGEMM_SMEM>>>(
        mh, w2i, out_img, nullptr, i_b2, mod_i + 5 * DD, res_i,
        mt, w2t, out_txt, nullptr, t_b2, mod_t + 5 * DD, res_t,
        MLPD, MLPD, MLPD, DD, DD, 1.0f, YI);

    (void)in_sizes; (void)n_in; (void)out_size;
}